// round 1
// baseline (speedup 1.0000x reference)
#include <cuda_runtime.h>
#include <math.h>

#define NTOK 4096      // B*T
#define EMB  1024
#define FFD  4096
#define BATCH 2
#define SEQ  2048
#define NHEAD 16
#define HDIM 64
#define LN_EPS 1e-5f

// ---------------- scratch (device globals; no allocations allowed) ----------
__device__ float g_xln [NTOK * EMB];
__device__ float g_q   [NTOK * EMB];
__device__ float g_k   [NTOK * EMB];
__device__ float g_v   [NTOK * EMB];
__device__ float g_attn[NTOK * EMB];
__device__ float g_x1  [NTOK * EMB];
__device__ float g_xln2[NTOK * EMB];
__device__ float g_ff  [NTOK * FFD];

// ---------------- LayerNorm: one block per row of 1024 ----------------------
__global__ __launch_bounds__(256) void ln_kernel(
    const float* __restrict__ x, const float* __restrict__ g,
    const float* __restrict__ b, float* __restrict__ y)
{
    int row = blockIdx.x;
    int tid = threadIdx.x;               // 256 threads, 4 elems each
    const float* xr = x + row * EMB;
    float4 v = *(const float4*)&xr[tid * 4];
    float s  = v.x + v.y + v.z + v.w;
    float ss = v.x*v.x + v.y*v.y + v.z*v.z + v.w*v.w;

    // warp reduce
    #pragma unroll
    for (int off = 16; off > 0; off >>= 1) {
        s  += __shfl_down_sync(0xffffffffu, s,  off);
        ss += __shfl_down_sync(0xffffffffu, ss, off);
    }
    __shared__ float red_s[8], red_ss[8];
    int wid = tid >> 5, lid = tid & 31;
    if (lid == 0) { red_s[wid] = s; red_ss[wid] = ss; }
    __syncthreads();
    if (wid == 0) {
        float a  = (lid < 8) ? red_s[lid]  : 0.f;
        float a2 = (lid < 8) ? red_ss[lid] : 0.f;
        #pragma unroll
        for (int off = 4; off > 0; off >>= 1) {
            a  += __shfl_down_sync(0xffffffffu, a,  off);
            a2 += __shfl_down_sync(0xffffffffu, a2, off);
        }
        if (lid == 0) { red_s[0] = a; red_ss[0] = a2; }
    }
    __syncthreads();
    float mu  = red_s[0] * (1.0f / EMB);
    float var = red_ss[0] * (1.0f / EMB) - mu * mu;
    float rs  = rsqrtf(var + LN_EPS);

    float4 gv = *(const float4*)&g[tid * 4];
    float4 bv = *(const float4*)&b[tid * 4];
    float4 o;
    o.x = (v.x - mu) * rs * gv.x + bv.x;
    o.y = (v.y - mu) * rs * gv.y + bv.y;
    o.z = (v.z - mu) * rs * gv.z + bv.z;
    o.w = (v.w - mu) * rs * gv.w + bv.w;
    *(float4*)&y[row * EMB + tid * 4] = o;
}

// ---------------- SGEMM 128x128x16, 256 thr, 8x8 per thread -----------------
// C[M,N] = epilogue(A[M,K] @ W[K,N] + bias)
// MODE 0: + bias            MODE 1: gelu(+bias)      MODE 2: res + alpha*(+bias)
__device__ __forceinline__ float gelu_exact(float c) {
    return 0.5f * c * (1.0f + erff(c * 0.70710678118654752f));
}

template<int MODE>
__global__ __launch_bounds__(256, 2) void gemm_kernel(
    const float* __restrict__ A, const float* __restrict__ W,
    const float* __restrict__ bias, const float* __restrict__ res,
    const float* __restrict__ alpha_p, float* __restrict__ C,
    int M, int N, int K)
{
    const int BM = 128, BN = 128, BK = 16;
    __shared__ float As[BK][BM + 4];   // row = 132 floats (528B, 16B-aligned)
    __shared__ float Bs[BK][BN];

    int bm = blockIdx.y * BM, bn = blockIdx.x * BN;
    int tid = threadIdx.x;
    int tx = tid & 15, ty = tid >> 4;

    float acc[8][8];
    #pragma unroll
    for (int i = 0; i < 8; i++)
        #pragma unroll
        for (int j = 0; j < 8; j++) acc[i][j] = 0.f;

    int ar = tid >> 2;            // 0..63 (rows ar, ar+64)
    int ac = (tid & 3) * 4;       // 0,4,8,12
    int br = tid >> 4;            // 0..15
    int bc = (tid & 15) * 4;      // 0..60 (cols bc, bc+64)

    for (int k0 = 0; k0 < K; k0 += BK) {
        #pragma unroll
        for (int rr = 0; rr < 2; rr++) {
            float4 a4 = *(const float4*)&A[(bm + ar + rr * 64) * K + k0 + ac];
            As[ac + 0][ar + rr * 64] = a4.x;
            As[ac + 1][ar + rr * 64] = a4.y;
            As[ac + 2][ar + rr * 64] = a4.z;
            As[ac + 3][ar + rr * 64] = a4.w;
        }
        #pragma unroll
        for (int cc = 0; cc < 2; cc++) {
            float4 b4 = *(const float4*)&W[(k0 + br) * N + bn + bc + cc * 64];
            *(float4*)&Bs[br][bc + cc * 64] = b4;
        }
        __syncthreads();

        #pragma unroll
        for (int k = 0; k < BK; k++) {
            float a[8], b[8];
            *(float4*)&a[0] = *(const float4*)&As[k][ty * 8];
            *(float4*)&a[4] = *(const float4*)&As[k][ty * 8 + 4];
            *(float4*)&b[0] = *(const float4*)&Bs[k][tx * 8];
            *(float4*)&b[4] = *(const float4*)&Bs[k][tx * 8 + 4];
            #pragma unroll
            for (int i = 0; i < 8; i++)
                #pragma unroll
                for (int j = 0; j < 8; j++)
                    acc[i][j] = fmaf(a[i], b[j], acc[i][j]);
        }
        __syncthreads();
    }

    float alpha = (MODE == 2) ? *alpha_p : 1.0f;
    #pragma unroll
    for (int i = 0; i < 8; i++) {
        int m = bm + ty * 8 + i;
        #pragma unroll
        for (int j = 0; j < 8; j++) {
            int n = bn + tx * 8 + j;
            float c = acc[i][j] + bias[n];
            if (MODE == 1) c = gelu_exact(c);
            if (MODE == 2) c = res[m * N + n] + alpha * c;
            C[m * N + n] = c;
        }
    }
}

// ---------------- causal flash attention ------------------------------------
// grid: (T/128, B*NH), 256 threads. 2 threads per query, each owns half of D.
#define AT_QT 128
#define AT_KT 32
__global__ __launch_bounds__(256) void attn_kernel(
    const float* __restrict__ Q, const float* __restrict__ K,
    const float* __restrict__ V, float* __restrict__ O)
{
    __shared__ float ksh[AT_KT][HDIM];   // 8 KB
    __shared__ float vsh[AT_KT][HDIM];   // 8 KB

    int qt = blockIdx.x;
    int bh = blockIdx.y;
    int b  = bh / NHEAD, h = bh % NHEAD;
    int tid  = threadIdx.x;
    int me   = tid >> 1;          // query row in tile: 0..127
    int half = tid & 1;           // which half of D
    int qglob = qt * AT_QT + me;
    const float scale = 0.125f;   // 1/sqrt(64)

    // q fragment -> registers
    float qreg[32];
    {
        const float* qp = &Q[(b * SEQ + qglob) * EMB + h * HDIM + half * 32];
        #pragma unroll
        for (int i = 0; i < 8; i++) {
            float4 t = *(const float4*)&qp[i * 4];
            qreg[i*4+0] = t.x; qreg[i*4+1] = t.y; qreg[i*4+2] = t.z; qreg[i*4+3] = t.w;
        }
    }

    float acc[32];
    #pragma unroll
    for (int d = 0; d < 32; d++) acc[d] = 0.f;
    float m = -INFINITY, l = 0.f;

    int n_kt = qt * (AT_QT / AT_KT) + (AT_QT / AT_KT);   // tiles up to diagonal
    for (int kt = 0; kt < n_kt; kt++) {
        // load K,V tiles
        for (int i = tid; i < AT_KT * HDIM; i += 256) {
            int j = i >> 6, d = i & 63;
            int row = (b * SEQ + kt * AT_KT + j) * EMB + h * HDIM + d;
            ksh[j][d] = K[row];
            vsh[j][d] = V[row];
        }
        __syncthreads();

        // scores
        float s[AT_KT];
        float tmax = -INFINITY;
        #pragma unroll
        for (int j = 0; j < AT_KT; j++) {
            float sp = 0.f;
            #pragma unroll
            for (int d4 = 0; d4 < 8; d4++) {
                float4 kk = *(const float4*)&ksh[j][half * 32 + d4 * 4];
                sp = fmaf(qreg[d4*4+0], kk.x, sp);
                sp = fmaf(qreg[d4*4+1], kk.y, sp);
                sp = fmaf(qreg[d4*4+2], kk.z, sp);
                sp = fmaf(qreg[d4*4+3], kk.w, sp);
            }
            sp += __shfl_xor_sync(0xffffffffu, sp, 1);
            float sv = sp * scale;
            if (kt * AT_KT + j > qglob) sv = -INFINITY;
            s[j] = sv;
            tmax = fmaxf(tmax, sv);
        }

        // online softmax
        float m_new = fmaxf(m, tmax);
        float corr = __expf(m - m_new);
        float psum = 0.f;
        #pragma unroll
        for (int j = 0; j < AT_KT; j++) {
            s[j] = __expf(s[j] - m_new);   // masked -> exp(-inf)=0
            psum += s[j];
        }
        l = l * corr + psum;
        m = m_new;

        #pragma unroll
        for (int d = 0; d < 32; d++) acc[d] *= corr;
        #pragma unroll
        for (int j = 0; j < AT_KT; j++) {
            float pj = s[j];
            #pragma unroll
            for (int d4 = 0; d4 < 8; d4++) {
                float4 vv = *(const float4*)&vsh[j][half * 32 + d4 * 4];
                acc[d4*4+0] = fmaf(pj, vv.x, acc[d4*4+0]);
                acc[d4*4+1] = fmaf(pj, vv.y, acc[d4*4+1]);
                acc[d4*4+2] = fmaf(pj, vv.z, acc[d4*4+2]);
                acc[d4*4+3] = fmaf(pj, vv.w, acc[d4*4+3]);
            }
        }
        __syncthreads();
    }

    float inv_l = 1.0f / l;
    float* op = &O[(b * SEQ + qglob) * EMB + h * HDIM + half * 32];
    #pragma unroll
    for (int d4 = 0; d4 < 8; d4++) {
        float4 o;
        o.x = acc[d4*4+0] * inv_l; o.y = acc[d4*4+1] * inv_l;
        o.z = acc[d4*4+2] * inv_l; o.w = acc[d4*4+3] * inv_l;
        *(float4*)&op[d4 * 4] = o;
    }
}

// ---------------- launch ----------------------------------------------------
extern "C" void kernel_launch(void* const* d_in, const int* in_sizes, int n_in,
                              void* d_out, int out_size)
{
    (void)in_sizes; (void)n_in; (void)out_size;
    const float* x     = (const float*)d_in[0];
    const float* wq    = (const float*)d_in[1];
    const float* bq    = (const float*)d_in[2];
    const float* wk    = (const float*)d_in[3];
    const float* bk    = (const float*)d_in[4];
    const float* wv    = (const float*)d_in[5];
    const float* bv    = (const float*)d_in[6];
    const float* wo    = (const float*)d_in[7];
    const float* bo    = (const float*)d_in[8];
    const float* w1    = (const float*)d_in[9];
    const float* b1    = (const float*)d_in[10];
    const float* w2    = (const float*)d_in[11];
    const float* b2    = (const float*)d_in[12];
    const float* ln1g  = (const float*)d_in[13];
    const float* ln1b  = (const float*)d_in[14];
    const float* ln2g  = (const float*)d_in[15];
    const float* ln2b  = (const float*)d_in[16];
    const float* a_att = (const float*)d_in[17];
    const float* a_ff  = (const float*)d_in[18];
    float* out = (float*)d_out;

    float *xln, *q, *k, *v, *attn, *x1, *xln2, *ff;
    cudaGetSymbolAddress((void**)&xln,  g_xln);
    cudaGetSymbolAddress((void**)&q,    g_q);
    cudaGetSymbolAddress((void**)&k,    g_k);
    cudaGetSymbolAddress((void**)&v,    g_v);
    cudaGetSymbolAddress((void**)&attn, g_attn);
    cudaGetSymbolAddress((void**)&x1,   g_x1);
    cudaGetSymbolAddress((void**)&xln2, g_xln2);
    cudaGetSymbolAddress((void**)&ff,   g_ff);

    dim3 g_e(EMB / 128, NTOK / 128);   // N=1024 GEMMs
    dim3 g_f(FFD / 128, NTOK / 128);   // N=4096 GEMM

    // 1) LN1
    ln_kernel<<<NTOK, 256>>>(x, ln1g, ln1b, xln);
    // 2) QKV
    gemm_kernel<0><<<g_e, 256>>>(xln, wq, bq, nullptr, nullptr, q, NTOK, EMB, EMB);
    gemm_kernel<0><<<g_e, 256>>>(xln, wk, bk, nullptr, nullptr, k, NTOK, EMB, EMB);
    gemm_kernel<0><<<g_e, 256>>>(xln, wv, bv, nullptr, nullptr, v, NTOK, EMB, EMB);
    // 3) causal attention
    attn_kernel<<<dim3(SEQ / AT_QT, BATCH * NHEAD), 256>>>(q, k, v, attn);
    // 4) O proj + residual: x1 = x + alpha_attn*(attn@wo + bo)
    gemm_kernel<2><<<g_e, 256>>>(attn, wo, bo, x, a_att, x1, NTOK, EMB, EMB);
    // 5) LN2
    ln_kernel<<<NTOK, 256>>>(x1, ln2g, ln2b, xln2);
    // 6) FF1 + GELU
    gemm_kernel<1><<<g_f, 256>>>(xln2, w1, b1, nullptr, nullptr, ff, NTOK, FFD, EMB);
    // 7) FF2 + residual -> out
    gemm_kernel<2><<<g_e, 256>>>(ff, w2, b2, x1, a_ff, out, NTOK, EMB, FFD);
}

// round 3
// speedup vs baseline: 1.8179x; 1.8179x over previous
#include <cuda_runtime.h>
#include <math.h>
#include <stdint.h>

#define NTOK 4096      // B*T
#define EMB  1024
#define FFD  4096
#define BATCH 2
#define SEQ  2048
#define NHEAD 16
#define HDIM 64
#define LN_EPS 1e-5f
#define QKV_LD 3072

// ---------------- scratch (device globals; no allocations allowed) ----------
__device__ float g_xln [NTOK * EMB];
__device__ float g_qkv [NTOK * QKV_LD];
__device__ float g_attn[NTOK * EMB];
__device__ float g_x1  [NTOK * EMB];
__device__ float g_xln2[NTOK * EMB];
__device__ float g_ff  [NTOK * FFD];
// transposed weights [N, K]
__device__ float g_wqkvt[QKV_LD * EMB];
__device__ float g_wot  [EMB * EMB];
__device__ float g_w1t  [EMB * FFD];
__device__ float g_w2t  [FFD * EMB];
__device__ float g_bqkv [QKV_LD];

// ---------------- helpers ----------------------------------------------------
__device__ __forceinline__ uint32_t sm_u32(const void* p) {
    return (uint32_t)__cvta_generic_to_shared(p);
}
__device__ __forceinline__ void cp_async16(uint32_t smem, const void* gptr) {
    asm volatile("cp.async.cg.shared.global [%0], [%1], 16;"
                 :: "r"(smem), "l"(__cvta_generic_to_global(gptr)) : "memory");
}
__device__ __forceinline__ void cp_commit() {
    asm volatile("cp.async.commit_group;" ::: "memory");
}
template<int N>
__device__ __forceinline__ void cp_wait() {
    asm volatile("cp.async.wait_group %0;" :: "n"(N) : "memory");
}
__device__ __forceinline__ void mma_tf32(float* c, const uint32_t* a, const uint32_t* b) {
    asm volatile(
        "mma.sync.aligned.m16n8k8.row.col.f32.tf32.tf32.f32 "
        "{%0,%1,%2,%3}, {%4,%5,%6,%7}, {%8,%9}, {%0,%1,%2,%3};"
        : "+f"(c[0]), "+f"(c[1]), "+f"(c[2]), "+f"(c[3])
        : "r"(a[0]), "r"(a[1]), "r"(a[2]), "r"(a[3]), "r"(b[0]), "r"(b[1]));
}
__device__ __forceinline__ float gelu_exact(float c) {
    return 0.5f * c * (1.0f + erff(c * 0.70710678118654752f));
}

// ---------------- weight transpose: W[K,N] -> WT[N,K] -----------------------
__global__ __launch_bounds__(256) void transpose_kernel(
    const float* __restrict__ W, float* __restrict__ WT, int K, int N)
{
    __shared__ float t[32][33];
    int bx = blockIdx.x * 32, by = blockIdx.y * 32;
    int tx = threadIdx.x, ty = threadIdx.y;   // (32, 8)
    #pragma unroll
    for (int i = 0; i < 32; i += 8)
        t[ty + i][tx] = W[(size_t)(by + ty + i) * N + bx + tx];
    __syncthreads();
    #pragma unroll
    for (int i = 0; i < 32; i += 8)
        WT[(size_t)(bx + ty + i) * K + by + tx] = t[tx][ty + i];
}

__global__ __launch_bounds__(256) void concat_bias_kernel(
    const float* __restrict__ a, const float* __restrict__ b,
    const float* __restrict__ c, float* __restrict__ o)
{
    int i = blockIdx.x * 256 + threadIdx.x;
    if (i < EMB)           o[i] = a[i];
    else if (i < 2 * EMB)  o[i] = b[i - EMB];
    else if (i < 3 * EMB)  o[i] = c[i - 2 * EMB];
}

// ---------------- LayerNorm --------------------------------------------------
__global__ __launch_bounds__(256) void ln_kernel(
    const float* __restrict__ x, const float* __restrict__ g,
    const float* __restrict__ b, float* __restrict__ y)
{
    int row = blockIdx.x;
    int tid = threadIdx.x;
    const float* xr = x + row * EMB;
    float4 v = *(const float4*)&xr[tid * 4];
    float s  = v.x + v.y + v.z + v.w;
    float ss = v.x*v.x + v.y*v.y + v.z*v.z + v.w*v.w;

    #pragma unroll
    for (int off = 16; off > 0; off >>= 1) {
        s  += __shfl_down_sync(0xffffffffu, s,  off);
        ss += __shfl_down_sync(0xffffffffu, ss, off);
    }
    __shared__ float red_s[8], red_ss[8];
    int wid = tid >> 5, lid = tid & 31;
    if (lid == 0) { red_s[wid] = s; red_ss[wid] = ss; }
    __syncthreads();
    if (wid == 0) {
        float a  = (lid < 8) ? red_s[lid]  : 0.f;
        float a2 = (lid < 8) ? red_ss[lid] : 0.f;
        #pragma unroll
        for (int off = 4; off > 0; off >>= 1) {
            a  += __shfl_down_sync(0xffffffffu, a,  off);
            a2 += __shfl_down_sync(0xffffffffu, a2, off);
        }
        if (lid == 0) { red_s[0] = a; red_ss[0] = a2; }
    }
    __syncthreads();
    float mu  = red_s[0] * (1.0f / EMB);
    float var = red_ss[0] * (1.0f / EMB) - mu * mu;
    float rs  = rsqrtf(var + LN_EPS);

    float4 gv = *(const float4*)&g[tid * 4];
    float4 bv = *(const float4*)&b[tid * 4];
    float4 o;
    o.x = (v.x - mu) * rs * gv.x + bv.x;
    o.y = (v.y - mu) * rs * gv.y + bv.y;
    o.z = (v.z - mu) * rs * gv.z + bv.z;
    o.w = (v.w - mu) * rs * gv.w + bv.w;
    *(float4*)&y[row * EMB + tid * 4] = o;
}

// ---------------- tf32 mma.sync GEMM -----------------------------------------
// C[M,N] = epilogue(A[M,K] @ BT[N,K]^T + bias)
// MODE 0: +bias   MODE 1: gelu(+bias)   MODE 2: res + alpha*(+bias)
#define GBM 128
#define GBN 256
#define GBK 32
#define APITCH 36                           // floats per smem row (bank-safe)
#define ABYTES (GBM * APITCH * 4)           // 18432
#define BBYTES (GBN * APITCH * 4)           // 36864
#define STAGE_BYTES (ABYTES + BBYTES)       // 55296
#define GSTAGES 3
#define GSMEM_DYN (GSTAGES * STAGE_BYTES)   // 165888

template<int MODE>
__global__ __launch_bounds__(256, 1) void gemm_mma(
    const float* __restrict__ A, const float* __restrict__ BT,
    const float* __restrict__ bias, const float* __restrict__ res,
    const float* __restrict__ alpha_p, float* __restrict__ C,
    int M, int N, int K)
{
    extern __shared__ char dynsm[];
    int tid = threadIdx.x, wid = tid >> 5, lid = tid & 31;
    int gid = lid >> 2, tg = lid & 3;          // fragment group / thread-in-group
    int wm = (wid & 1) * 64, wn = (wid >> 1) * 64;
    int bm = blockIdx.y * GBM, bn = blockIdx.x * GBN;

    float acc[4][8][4];
    #pragma unroll
    for (int mf = 0; mf < 4; mf++)
        #pragma unroll
        for (int nf = 0; nf < 8; nf++)
            #pragma unroll
            for (int i = 0; i < 4; i++) acc[mf][nf][i] = 0.f;

    auto load_stage = [&](int s) {
        char* base = dynsm + (s % GSTAGES) * STAGE_BYTES;
        float* As = (float*)base;
        float* Bs = (float*)(base + ABYTES);
        const float* Ag = A  + (size_t)bm * K + s * GBK;
        const float* Bg = BT + (size_t)bn * K + s * GBK;
        #pragma unroll
        for (int i = 0; i < 4; i++) {           // A: 128 rows x 8 chunks
            int idx = tid + i * 256;
            int r = idx >> 3, c = idx & 7;
            cp_async16(sm_u32(As + r * APITCH + c * 4), Ag + (size_t)r * K + c * 4);
        }
        #pragma unroll
        for (int i = 0; i < 8; i++) {           // B: 256 rows x 8 chunks
            int idx = tid + i * 256;
            int r = idx >> 3, c = idx & 7;
            cp_async16(sm_u32(Bs + r * APITCH + c * 4), Bg + (size_t)r * K + c * 4);
        }
    };

    load_stage(0); cp_commit();
    load_stage(1); cp_commit();

    int nst = K / GBK;
    for (int s = 0; s < nst; s++) {
        cp_wait<1>();
        __syncthreads();
        if (s + 2 < nst) load_stage(s + 2);
        cp_commit();

        const char* base = dynsm + (s % GSTAGES) * STAGE_BYTES;
        const float* As = (const float*)base;
        const float* Bs = (const float*)(base + ABYTES);

        #pragma unroll
        for (int ks = 0; ks < 4; ks++) {
            int k0 = ks * 8;
            uint32_t af[4][4], bf[8][2];
            #pragma unroll
            for (int mf = 0; mf < 4; mf++) {
                const float* p = As + (wm + mf * 16 + gid) * APITCH + k0 + tg;
                af[mf][0] = *(const uint32_t*)(p);
                af[mf][1] = *(const uint32_t*)(p + 8 * APITCH);
                af[mf][2] = *(const uint32_t*)(p + 4);
                af[mf][3] = *(const uint32_t*)(p + 8 * APITCH + 4);
            }
            #pragma unroll
            for (int nf = 0; nf < 8; nf++) {
                const float* p = Bs + (wn + nf * 8 + gid) * APITCH + k0 + tg;
                bf[nf][0] = *(const uint32_t*)(p);
                bf[nf][1] = *(const uint32_t*)(p + 4);
            }
            #pragma unroll
            for (int mf = 0; mf < 4; mf++)
                #pragma unroll
                for (int nf = 0; nf < 8; nf++)
                    mma_tf32(acc[mf][nf], af[mf], bf[nf]);
        }
    }

    // epilogue
    float alpha = (MODE == 2) ? *alpha_p : 1.0f;
    #pragma unroll
    for (int mf = 0; mf < 4; mf++) {
        int r0 = bm + wm + mf * 16 + gid;
        #pragma unroll
        for (int nf = 0; nf < 8; nf++) {
            int col = bn + wn + nf * 8 + 2 * tg;
            float2 bv = *(const float2*)&bias[col];
            float v0 = acc[mf][nf][0] + bv.x;
            float v1 = acc[mf][nf][1] + bv.y;
            float v2 = acc[mf][nf][2] + bv.x;
            float v3 = acc[mf][nf][3] + bv.y;
            if (MODE == 1) {
                v0 = gelu_exact(v0); v1 = gelu_exact(v1);
                v2 = gelu_exact(v2); v3 = gelu_exact(v3);
            }
            if (MODE == 2) {
                float2 ra = *(const float2*)&res[(size_t)r0 * N + col];
                float2 rb = *(const float2*)&res[(size_t)(r0 + 8) * N + col];
                v0 = ra.x + alpha * v0; v1 = ra.y + alpha * v1;
                v2 = rb.x + alpha * v2; v3 = rb.y + alpha * v3;
            }
            *(float2*)&C[(size_t)r0 * N + col]       = make_float2(v0, v1);
            *(float2*)&C[(size_t)(r0 + 8) * N + col] = make_float2(v2, v3);
        }
    }
}

// ---------------- causal flash attention (reads packed QKV) ------------------
#define AT_QT 128
#define AT_KT 32
__global__ __launch_bounds__(256) void attn_kernel(
    const float* __restrict__ QKV, float* __restrict__ O)
{
    __shared__ float ksh[AT_KT][HDIM];
    __shared__ float vsh[AT_KT][HDIM];

    int qt = blockIdx.x;
    int bh = blockIdx.y;
    int b  = bh / NHEAD, h = bh % NHEAD;
    int tid  = threadIdx.x;
    int me   = tid >> 1;
    int half = tid & 1;
    int qglob = qt * AT_QT + me;
    const float scale = 0.125f;

    float qreg[32];
    {
        const float* qp = &QKV[(size_t)(b * SEQ + qglob) * QKV_LD + h * HDIM + half * 32];
        #pragma unroll
        for (int i = 0; i < 8; i++) {
            float4 t = *(const float4*)&qp[i * 4];
            qreg[i*4+0] = t.x; qreg[i*4+1] = t.y; qreg[i*4+2] = t.z; qreg[i*4+3] = t.w;
        }
    }

    float acc[32];
    #pragma unroll
    for (int d = 0; d < 32; d++) acc[d] = 0.f;
    float m = -INFINITY, l = 0.f;

    int n_kt = qt * (AT_QT / AT_KT) + (AT_QT / AT_KT);
    for (int kt = 0; kt < n_kt; kt++) {
        for (int i = tid; i < AT_KT * HDIM; i += 256) {
            int j = i >> 6, d = i & 63;
            size_t row = (size_t)(b * SEQ + kt * AT_KT + j) * QKV_LD + h * HDIM + d;
            ksh[j][d] = QKV[row + EMB];
            vsh[j][d] = QKV[row + 2 * EMB];
        }
        __syncthreads();

        float s[AT_KT];
        float tmax = -INFINITY;
        #pragma unroll
        for (int j = 0; j < AT_KT; j++) {
            float sp = 0.f;
            #pragma unroll
            for (int d4 = 0; d4 < 8; d4++) {
                float4 kk = *(const float4*)&ksh[j][half * 32 + d4 * 4];
                sp = fmaf(qreg[d4*4+0], kk.x, sp);
                sp = fmaf(qreg[d4*4+1], kk.y, sp);
                sp = fmaf(qreg[d4*4+2], kk.z, sp);
                sp = fmaf(qreg[d4*4+3], kk.w, sp);
            }
            sp += __shfl_xor_sync(0xffffffffu, sp, 1);
            float sv = sp * scale;
            if (kt * AT_KT + j > qglob) sv = -INFINITY;
            s[j] = sv;
            tmax = fmaxf(tmax, sv);
        }

        float m_new = fmaxf(m, tmax);
        float corr = __expf(m - m_new);
        float psum = 0.f;
        #pragma unroll
        for (int j = 0; j < AT_KT; j++) {
            s[j] = __expf(s[j] - m_new);
            psum += s[j];
        }
        l = l * corr + psum;
        m = m_new;

        #pragma unroll
        for (int d = 0; d < 32; d++) acc[d] *= corr;
        #pragma unroll
        for (int j = 0; j < AT_KT; j++) {
            float pj = s[j];
            #pragma unroll
            for (int d4 = 0; d4 < 8; d4++) {
                float4 vv = *(const float4*)&vsh[j][half * 32 + d4 * 4];
                acc[d4*4+0] = fmaf(pj, vv.x, acc[d4*4+0]);
                acc[d4*4+1] = fmaf(pj, vv.y, acc[d4*4+1]);
                acc[d4*4+2] = fmaf(pj, vv.z, acc[d4*4+2]);
                acc[d4*4+3] = fmaf(pj, vv.w, acc[d4*4+3]);
            }
        }
        __syncthreads();
    }

    float inv_l = 1.0f / l;
    float* op = &O[(size_t)(b * SEQ + qglob) * EMB + h * HDIM + half * 32];
    #pragma unroll
    for (int d4 = 0; d4 < 8; d4++) {
        float4 o;
        o.x = acc[d4*4+0] * inv_l; o.y = acc[d4*4+1] * inv_l;
        o.z = acc[d4*4+2] * inv_l; o.w = acc[d4*4+3] * inv_l;
        *(float4*)&op[d4 * 4] = o;
    }
}

// ---------------- launch ----------------------------------------------------
extern "C" void kernel_launch(void* const* d_in, const int* in_sizes, int n_in,
                              void* d_out, int out_size)
{
    (void)in_sizes; (void)n_in; (void)out_size;
    const float* x     = (const float*)d_in[0];
    const float* wq    = (const float*)d_in[1];
    const float* bq    = (const float*)d_in[2];
    const float* wk    = (const float*)d_in[3];
    const float* bk    = (const float*)d_in[4];
    const float* wv    = (const float*)d_in[5];
    const float* bv    = (const float*)d_in[6];
    const float* wo    = (const float*)d_in[7];
    const float* bo    = (const float*)d_in[8];
    const float* w1    = (const float*)d_in[9];
    const float* b1    = (const float*)d_in[10];
    const float* w2    = (const float*)d_in[11];
    const float* b2    = (const float*)d_in[12];
    const float* ln1g  = (const float*)d_in[13];
    const float* ln1b  = (const float*)d_in[14];
    const float* ln2g  = (const float*)d_in[15];
    const float* ln2b  = (const float*)d_in[16];
    const float* a_att = (const float*)d_in[17];
    const float* a_ff  = (const float*)d_in[18];
    float* out = (float*)d_out;

    float *xln, *qkv, *attn, *x1, *xln2, *ff;
    float *wqkvt, *wot, *w1t, *w2t, *bqkv;
    cudaGetSymbolAddress((void**)&xln,   g_xln);
    cudaGetSymbolAddress((void**)&qkv,   g_qkv);
    cudaGetSymbolAddress((void**)&attn,  g_attn);
    cudaGetSymbolAddress((void**)&x1,    g_x1);
    cudaGetSymbolAddress((void**)&xln2,  g_xln2);
    cudaGetSymbolAddress((void**)&ff,    g_ff);
    cudaGetSymbolAddress((void**)&wqkvt, g_wqkvt);
    cudaGetSymbolAddress((void**)&wot,   g_wot);
    cudaGetSymbolAddress((void**)&w1t,   g_w1t);
    cudaGetSymbolAddress((void**)&w2t,   g_w2t);
    cudaGetSymbolAddress((void**)&bqkv,  g_bqkv);

    cudaFuncSetAttribute(gemm_mma<0>, cudaFuncAttributeMaxDynamicSharedMemorySize, GSMEM_DYN);
    cudaFuncSetAttribute(gemm_mma<1>, cudaFuncAttributeMaxDynamicSharedMemorySize, GSMEM_DYN);
    cudaFuncSetAttribute(gemm_mma<2>, cudaFuncAttributeMaxDynamicSharedMemorySize, GSMEM_DYN);

    dim3 tb(32, 8);
    // weight transposes [K,N] -> [N,K]; QKV packed into one [3072,1024]
    transpose_kernel<<<dim3(EMB / 32, EMB / 32), tb>>>(wq, wqkvt,            EMB, EMB);
    transpose_kernel<<<dim3(EMB / 32, EMB / 32), tb>>>(wk, wqkvt + EMB*EMB,  EMB, EMB);
    transpose_kernel<<<dim3(EMB / 32, EMB / 32), tb>>>(wv, wqkvt + 2*EMB*EMB, EMB, EMB);
    transpose_kernel<<<dim3(EMB / 32, EMB / 32), tb>>>(wo, wot, EMB, EMB);
    transpose_kernel<<<dim3(FFD / 32, EMB / 32), tb>>>(w1, w1t, EMB, FFD);
    transpose_kernel<<<dim3(EMB / 32, FFD / 32), tb>>>(w2, w2t, FFD, EMB);
    concat_bias_kernel<<<QKV_LD / 256, 256>>>(bq, bk, bv, bqkv);

    // 1) LN1
    ln_kernel<<<NTOK, 256>>>(x, ln1g, ln1b, xln);
    // 2) fused QKV GEMM (tf32 mma.sync): [4096,1024] @ [1024,3072]
    gemm_mma<0><<<dim3(QKV_LD / GBN, NTOK / GBM), 256, GSMEM_DYN>>>(
        xln, wqkvt, bqkv, nullptr, nullptr, qkv, NTOK, QKV_LD, EMB);
    // 3) causal attention
    attn_kernel<<<dim3(SEQ / AT_QT, BATCH * NHEAD), 256>>>(qkv, attn);
    // 4) O proj + residual
    gemm_mma<2><<<dim3(EMB / GBN, NTOK / GBM), 256, GSMEM_DYN>>>(
        attn, wot, bo, x, a_att, x1, NTOK, EMB, EMB);
    // 5) LN2
    ln_kernel<<<NTOK, 256>>>(x1, ln2g, ln2b, xln2);
    // 6) FF1 + GELU
    gemm_mma<1><<<dim3(FFD / GBN, NTOK / GBM), 256, GSMEM_DYN>>>(
        xln2, w1t, b1, nullptr, nullptr, ff, NTOK, FFD, EMB);
    // 7) FF2 + residual -> out
    gemm_mma<2><<<dim3(EMB / GBN, NTOK / GBM), 256, GSMEM_DYN>>>(
        ff, w2t, b2, x1, a_ff, out, NTOK, EMB, FFD);
}

// round 4
// speedup vs baseline: 2.6513x; 1.4584x over previous
#include <cuda_runtime.h>
#include <math.h>
#include <stdint.h>

#define NTOK 4096      // B*T
#define EMB  1024
#define FFD  4096
#define BATCH 2
#define SEQ  2048
#define NHEAD 16
#define HDIM 64
#define LN_EPS 1e-5f
#define QKV_LD 3072

// ---------------- scratch (device globals; no allocations allowed) ----------
__device__ float g_xln [NTOK * EMB];
__device__ float g_qkv [NTOK * QKV_LD];
__device__ float g_attn[NTOK * EMB];
__device__ float g_x1  [NTOK * EMB];
__device__ float g_xln2[NTOK * EMB];
__device__ float g_ff  [NTOK * FFD];
// transposed weights [N, K]
__device__ float g_wqkvt[QKV_LD * EMB];
__device__ float g_wot  [EMB * EMB];
__device__ float g_w1t  [EMB * FFD];
__device__ float g_w2t  [FFD * EMB];
__device__ float g_bqkv [QKV_LD];

// ---------------- helpers ----------------------------------------------------
__device__ __forceinline__ uint32_t sm_u32(const void* p) {
    return (uint32_t)__cvta_generic_to_shared(p);
}
__device__ __forceinline__ void cp_async16(uint32_t smem, const void* gptr) {
    asm volatile("cp.async.cg.shared.global [%0], [%1], 16;"
                 :: "r"(smem), "l"(__cvta_generic_to_global(gptr)) : "memory");
}
__device__ __forceinline__ void cp_commit() {
    asm volatile("cp.async.commit_group;" ::: "memory");
}
template<int N>
__device__ __forceinline__ void cp_wait() {
    asm volatile("cp.async.wait_group %0;" :: "n"(N) : "memory");
}
__device__ __forceinline__ void mma_tf32(float* c, const uint32_t* a, const uint32_t* b) {
    asm volatile(
        "mma.sync.aligned.m16n8k8.row.col.f32.tf32.tf32.f32 "
        "{%0,%1,%2,%3}, {%4,%5,%6,%7}, {%8,%9}, {%0,%1,%2,%3};"
        : "+f"(c[0]), "+f"(c[1]), "+f"(c[2]), "+f"(c[3])
        : "r"(a[0]), "r"(a[1]), "r"(a[2]), "r"(a[3]), "r"(b[0]), "r"(b[1]));
}
__device__ __forceinline__ float gelu_exact(float c) {
    return 0.5f * c * (1.0f + erff(c * 0.70710678118654752f));
}

// ---------------- weight transpose: W[K,N] -> WT[N,K] -----------------------
__global__ __launch_bounds__(256) void transpose_kernel(
    const float* __restrict__ W, float* __restrict__ WT, int K, int N)
{
    __shared__ float t[32][33];
    int bx = blockIdx.x * 32, by = blockIdx.y * 32;
    int tx = threadIdx.x, ty = threadIdx.y;   // (32, 8)
    #pragma unroll
    for (int i = 0; i < 32; i += 8)
        t[ty + i][tx] = W[(size_t)(by + ty + i) * N + bx + tx];
    __syncthreads();
    #pragma unroll
    for (int i = 0; i < 32; i += 8)
        WT[(size_t)(bx + ty + i) * K + by + tx] = t[tx][ty + i];
}

__global__ __launch_bounds__(256) void concat_bias_kernel(
    const float* __restrict__ a, const float* __restrict__ b,
    const float* __restrict__ c, float* __restrict__ o)
{
    int i = blockIdx.x * 256 + threadIdx.x;
    if (i < EMB)           o[i] = a[i];
    else if (i < 2 * EMB)  o[i] = b[i - EMB];
    else if (i < 3 * EMB)  o[i] = c[i - 2 * EMB];
}

// ---------------- LayerNorm --------------------------------------------------
__global__ __launch_bounds__(256) void ln_kernel(
    const float* __restrict__ x, const float* __restrict__ g,
    const float* __restrict__ b, float* __restrict__ y)
{
    int row = blockIdx.x;
    int tid = threadIdx.x;
    const float* xr = x + row * EMB;
    float4 v = *(const float4*)&xr[tid * 4];
    float s  = v.x + v.y + v.z + v.w;
    float ss = v.x*v.x + v.y*v.y + v.z*v.z + v.w*v.w;

    #pragma unroll
    for (int off = 16; off > 0; off >>= 1) {
        s  += __shfl_down_sync(0xffffffffu, s,  off);
        ss += __shfl_down_sync(0xffffffffu, ss, off);
    }
    __shared__ float red_s[8], red_ss[8];
    int wid = tid >> 5, lid = tid & 31;
    if (lid == 0) { red_s[wid] = s; red_ss[wid] = ss; }
    __syncthreads();
    if (wid == 0) {
        float a  = (lid < 8) ? red_s[lid]  : 0.f;
        float a2 = (lid < 8) ? red_ss[lid] : 0.f;
        #pragma unroll
        for (int off = 4; off > 0; off >>= 1) {
            a  += __shfl_down_sync(0xffffffffu, a,  off);
            a2 += __shfl_down_sync(0xffffffffu, a2, off);
        }
        if (lid == 0) { red_s[0] = a; red_ss[0] = a2; }
    }
    __syncthreads();
    float mu  = red_s[0] * (1.0f / EMB);
    float var = red_ss[0] * (1.0f / EMB) - mu * mu;
    float rs  = rsqrtf(var + LN_EPS);

    float4 gv = *(const float4*)&g[tid * 4];
    float4 bv = *(const float4*)&b[tid * 4];
    float4 o;
    o.x = (v.x - mu) * rs * gv.x + bv.x;
    o.y = (v.y - mu) * rs * gv.y + bv.y;
    o.z = (v.z - mu) * rs * gv.z + bv.z;
    o.w = (v.w - mu) * rs * gv.w + bv.w;
    *(float4*)&y[row * EMB + tid * 4] = o;
}

// ---------------- tf32 mma.sync GEMM -----------------------------------------
#define GBM 128
#define GBN 256
#define GBK 32
#define APITCH 36
#define ABYTES (GBM * APITCH * 4)
#define BBYTES (GBN * APITCH * 4)
#define STAGE_BYTES (ABYTES + BBYTES)
#define GSTAGES 3
#define GSMEM_DYN (GSTAGES * STAGE_BYTES)

template<int MODE>
__global__ __launch_bounds__(256, 1) void gemm_mma(
    const float* __restrict__ A, const float* __restrict__ BT,
    const float* __restrict__ bias, const float* __restrict__ res,
    const float* __restrict__ alpha_p, float* __restrict__ C,
    int M, int N, int K)
{
    extern __shared__ char dynsm[];
    int tid = threadIdx.x, wid = tid >> 5, lid = tid & 31;
    int gid = lid >> 2, tg = lid & 3;
    int wm = (wid & 1) * 64, wn = (wid >> 1) * 64;
    int bm = blockIdx.y * GBM, bn = blockIdx.x * GBN;

    float acc[4][8][4];
    #pragma unroll
    for (int mf = 0; mf < 4; mf++)
        #pragma unroll
        for (int nf = 0; nf < 8; nf++)
            #pragma unroll
            for (int i = 0; i < 4; i++) acc[mf][nf][i] = 0.f;

    auto load_stage = [&](int s) {
        char* base = dynsm + (s % GSTAGES) * STAGE_BYTES;
        float* As = (float*)base;
        float* Bs = (float*)(base + ABYTES);
        const float* Ag = A  + (size_t)bm * K + s * GBK;
        const float* Bg = BT + (size_t)bn * K + s * GBK;
        #pragma unroll
        for (int i = 0; i < 4; i++) {
            int idx = tid + i * 256;
            int r = idx >> 3, c = idx & 7;
            cp_async16(sm_u32(As + r * APITCH + c * 4), Ag + (size_t)r * K + c * 4);
        }
        #pragma unroll
        for (int i = 0; i < 8; i++) {
            int idx = tid + i * 256;
            int r = idx >> 3, c = idx & 7;
            cp_async16(sm_u32(Bs + r * APITCH + c * 4), Bg + (size_t)r * K + c * 4);
        }
    };

    load_stage(0); cp_commit();
    load_stage(1); cp_commit();

    int nst = K / GBK;
    for (int s = 0; s < nst; s++) {
        cp_wait<1>();
        __syncthreads();
        if (s + 2 < nst) load_stage(s + 2);
        cp_commit();

        const char* base = dynsm + (s % GSTAGES) * STAGE_BYTES;
        const float* As = (const float*)base;
        const float* Bs = (const float*)(base + ABYTES);

        #pragma unroll
        for (int ks = 0; ks < 4; ks++) {
            int k0 = ks * 8;
            uint32_t af[4][4], bf[8][2];
            #pragma unroll
            for (int mf = 0; mf < 4; mf++) {
                const float* p = As + (wm + mf * 16 + gid) * APITCH + k0 + tg;
                af[mf][0] = *(const uint32_t*)(p);
                af[mf][1] = *(const uint32_t*)(p + 8 * APITCH);
                af[mf][2] = *(const uint32_t*)(p + 4);
                af[mf][3] = *(const uint32_t*)(p + 8 * APITCH + 4);
            }
            #pragma unroll
            for (int nf = 0; nf < 8; nf++) {
                const float* p = Bs + (wn + nf * 8 + gid) * APITCH + k0 + tg;
                bf[nf][0] = *(const uint32_t*)(p);
                bf[nf][1] = *(const uint32_t*)(p + 4);
            }
            #pragma unroll
            for (int mf = 0; mf < 4; mf++)
                #pragma unroll
                for (int nf = 0; nf < 8; nf++)
                    mma_tf32(acc[mf][nf], af[mf], bf[nf]);
        }
    }

    float alpha = (MODE == 2) ? *alpha_p : 1.0f;
    #pragma unroll
    for (int mf = 0; mf < 4; mf++) {
        int r0 = bm + wm + mf * 16 + gid;
        #pragma unroll
        for (int nf = 0; nf < 8; nf++) {
            int col = bn + wn + nf * 8 + 2 * tg;
            float2 bv = *(const float2*)&bias[col];
            float v0 = acc[mf][nf][0] + bv.x;
            float v1 = acc[mf][nf][1] + bv.y;
            float v2 = acc[mf][nf][2] + bv.x;
            float v3 = acc[mf][nf][3] + bv.y;
            if (MODE == 1) {
                v0 = gelu_exact(v0); v1 = gelu_exact(v1);
                v2 = gelu_exact(v2); v3 = gelu_exact(v3);
            }
            if (MODE == 2) {
                float2 ra = *(const float2*)&res[(size_t)r0 * N + col];
                float2 rb = *(const float2*)&res[(size_t)(r0 + 8) * N + col];
                v0 = ra.x + alpha * v0; v1 = ra.y + alpha * v1;
                v2 = rb.x + alpha * v2; v3 = rb.y + alpha * v3;
            }
            *(float2*)&C[(size_t)r0 * N + col]       = make_float2(v0, v1);
            *(float2*)&C[(size_t)(r0 + 8) * N + col] = make_float2(v2, v3);
        }
    }
}

// ---------------- tf32 mma flash attention -----------------------------------
// BQ=64 rows per block, 4 warps (warp = 16 rows). BK=64 keys per tile.
// smem (dynamic): ksh[64][68], vsh[64][68] (V transposed), psh[64][68]
#define ATP 68
#define AT_KSH 0
#define AT_VSH (64 * ATP)
#define AT_PSH (128 * ATP)
#define AT_SMEM (192 * ATP * 4)      // 52224 bytes

__global__ __launch_bounds__(128, 1) void attn_mma(
    const float* __restrict__ QKV, float* __restrict__ O)
{
    extern __shared__ float ash[];
    float* ksh = ash + AT_KSH;   // [key][d]
    float* vsh = ash + AT_VSH;   // [d][key]
    float* psh = ash + AT_PSH;   // [qrow][key]

    int qt = gridDim.x - 1 - blockIdx.x;     // long blocks first
    int bh = blockIdx.y;
    int b  = bh >> 4, h = bh & 15;
    int tid = threadIdx.x, wid = tid >> 5, lid = tid & 31;
    int gid = lid >> 2, tg = lid & 3;
    int wm = wid * 16;
    int qb = qt * 64;
    const float scale = 0.125f;

    // Q fragments for this warp's 16 rows (held for whole kernel)
    uint32_t qf[8][4];
    {
        const float* q0 = &QKV[(size_t)(b * SEQ + qb + wm + gid) * QKV_LD + h * HDIM];
        const float* q8 = q0 + 8 * QKV_LD;
        #pragma unroll
        for (int ks = 0; ks < 8; ks++) {
            qf[ks][0] = *(const uint32_t*)(q0 + ks * 8 + tg);
            qf[ks][1] = *(const uint32_t*)(q8 + ks * 8 + tg);
            qf[ks][2] = *(const uint32_t*)(q0 + ks * 8 + tg + 4);
            qf[ks][3] = *(const uint32_t*)(q8 + ks * 8 + tg + 4);
        }
    }

    float oacc[8][4];
    #pragma unroll
    for (int nf = 0; nf < 8; nf++)
        #pragma unroll
        for (int i = 0; i < 4; i++) oacc[nf][i] = 0.f;
    float om0 = -INFINITY, om1 = -INFINITY, ol0 = 0.f, ol1 = 0.f;

    int r0 = qb + wm + gid, r1 = r0 + 8;
    int nkt = qt + 1;

    for (int kt = 0; kt < nkt; kt++) {
        // ---- load K tile [64][d] and V tile transposed [d][64] ----
        #pragma unroll
        for (int i = 0; i < 8; i++) {
            int idx = tid + i * 128;
            int r = idx >> 4, c4 = (idx & 15) * 4;
            const float* src = &QKV[(size_t)(b * SEQ + kt * 64 + r) * QKV_LD + h * HDIM + c4];
            float4 kk = *(const float4*)(src + EMB);
            float4 vv = *(const float4*)(src + 2 * EMB);
            *(float4*)&ksh[r * ATP + c4] = kk;
            vsh[(c4 + 0) * ATP + r] = vv.x;
            vsh[(c4 + 1) * ATP + r] = vv.y;
            vsh[(c4 + 2) * ATP + r] = vv.z;
            vsh[(c4 + 3) * ATP + r] = vv.w;
        }
        __syncthreads();

        // ---- S = Q @ K^T ----
        float sacc[8][4];
        #pragma unroll
        for (int nf = 0; nf < 8; nf++)
            #pragma unroll
            for (int i = 0; i < 4; i++) sacc[nf][i] = 0.f;
        #pragma unroll
        for (int ks = 0; ks < 8; ks++) {
            uint32_t bf[8][2];
            #pragma unroll
            for (int nf = 0; nf < 8; nf++) {
                const float* p = &ksh[(nf * 8 + gid) * ATP + ks * 8 + tg];
                bf[nf][0] = *(const uint32_t*)(p);
                bf[nf][1] = *(const uint32_t*)(p + 4);
            }
            #pragma unroll
            for (int nf = 0; nf < 8; nf++)
                mma_tf32(sacc[nf], qf[ks], bf[nf]);
        }

        // ---- scale + causal mask + row max ----
        bool diag = (kt == qt);
        float tmax0 = -INFINITY, tmax1 = -INFINITY;
        #pragma unroll
        for (int nf = 0; nf < 8; nf++) {
            int c0 = kt * 64 + nf * 8 + 2 * tg;
            #pragma unroll
            for (int c = 0; c < 2; c++) {
                float s0 = sacc[nf][c] * scale;
                float s1 = sacc[nf][2 + c] * scale;
                if (diag && c0 + c > r0) s0 = -INFINITY;
                if (diag && c0 + c > r1) s1 = -INFINITY;
                sacc[nf][c] = s0; sacc[nf][2 + c] = s1;
                tmax0 = fmaxf(tmax0, s0);
                tmax1 = fmaxf(tmax1, s1);
            }
        }
        tmax0 = fmaxf(tmax0, __shfl_xor_sync(0xffffffffu, tmax0, 1));
        tmax0 = fmaxf(tmax0, __shfl_xor_sync(0xffffffffu, tmax0, 2));
        tmax1 = fmaxf(tmax1, __shfl_xor_sync(0xffffffffu, tmax1, 1));
        tmax1 = fmaxf(tmax1, __shfl_xor_sync(0xffffffffu, tmax1, 2));

        float mn0 = fmaxf(om0, tmax0), mn1 = fmaxf(om1, tmax1);
        float corr0 = __expf(om0 - mn0), corr1 = __expf(om1 - mn1);
        om0 = mn0; om1 = mn1;

        float ps0 = 0.f, ps1 = 0.f;
        #pragma unroll
        for (int nf = 0; nf < 8; nf++) {
            #pragma unroll
            for (int c = 0; c < 2; c++) {
                float e0 = __expf(sacc[nf][c] - mn0);
                float e1 = __expf(sacc[nf][2 + c] - mn1);
                sacc[nf][c] = e0; sacc[nf][2 + c] = e1;
                ps0 += e0; ps1 += e1;
            }
        }
        ps0 += __shfl_xor_sync(0xffffffffu, ps0, 1);
        ps0 += __shfl_xor_sync(0xffffffffu, ps0, 2);
        ps1 += __shfl_xor_sync(0xffffffffu, ps1, 1);
        ps1 += __shfl_xor_sync(0xffffffffu, ps1, 2);
        ol0 = ol0 * corr0 + ps0;
        ol1 = ol1 * corr1 + ps1;

        #pragma unroll
        for (int nf = 0; nf < 8; nf++) {
            oacc[nf][0] *= corr0; oacc[nf][1] *= corr0;
            oacc[nf][2] *= corr1; oacc[nf][3] *= corr1;
        }

        // ---- P -> smem (warp-private rows) ----
        #pragma unroll
        for (int nf = 0; nf < 8; nf++) {
            int col = nf * 8 + 2 * tg;
            *(float2*)&psh[(wm + gid) * ATP + col]     = make_float2(sacc[nf][0], sacc[nf][1]);
            *(float2*)&psh[(wm + gid + 8) * ATP + col] = make_float2(sacc[nf][2], sacc[nf][3]);
        }
        __syncwarp();

        // ---- O += P @ V ----
        #pragma unroll
        for (int ks = 0; ks < 8; ks++) {
            uint32_t af[4];
            const float* p0 = &psh[(wm + gid) * ATP + ks * 8 + tg];
            const float* p8 = p0 + 8 * ATP;
            af[0] = *(const uint32_t*)(p0);
            af[1] = *(const uint32_t*)(p8);
            af[2] = *(const uint32_t*)(p0 + 4);
            af[3] = *(const uint32_t*)(p8 + 4);
            uint32_t bf[8][2];
            #pragma unroll
            for (int nf = 0; nf < 8; nf++) {
                const float* p = &vsh[(nf * 8 + gid) * ATP + ks * 8 + tg];
                bf[nf][0] = *(const uint32_t*)(p);
                bf[nf][1] = *(const uint32_t*)(p + 4);
            }
            #pragma unroll
            for (int nf = 0; nf < 8; nf++)
                mma_tf32(oacc[nf], af, bf[nf]);
        }
        __syncthreads();
    }

    // ---- epilogue ----
    float inv0 = 1.0f / ol0, inv1 = 1.0f / ol1;
    float* o0 = &O[(size_t)(b * SEQ + r0) * EMB + h * HDIM];
    float* o8 = o0 + 8 * EMB;
    #pragma unroll
    for (int nf = 0; nf < 8; nf++) {
        int d = nf * 8 + 2 * tg;
        *(float2*)&o0[d] = make_float2(oacc[nf][0] * inv0, oacc[nf][1] * inv0);
        *(float2*)&o8[d] = make_float2(oacc[nf][2] * inv1, oacc[nf][3] * inv1);
    }
}

// ---------------- launch ----------------------------------------------------
extern "C" void kernel_launch(void* const* d_in, const int* in_sizes, int n_in,
                              void* d_out, int out_size)
{
    (void)in_sizes; (void)n_in; (void)out_size;
    const float* x     = (const float*)d_in[0];
    const float* wq    = (const float*)d_in[1];
    const float* bq    = (const float*)d_in[2];
    const float* wk    = (const float*)d_in[3];
    const float* bk    = (const float*)d_in[4];
    const float* wv    = (const float*)d_in[5];
    const float* bv    = (const float*)d_in[6];
    const float* wo    = (const float*)d_in[7];
    const float* bo    = (const float*)d_in[8];
    const float* w1    = (const float*)d_in[9];
    const float* b1    = (const float*)d_in[10];
    const float* w2    = (const float*)d_in[11];
    const float* b2    = (const float*)d_in[12];
    const float* ln1g  = (const float*)d_in[13];
    const float* ln1b  = (const float*)d_in[14];
    const float* ln2g  = (const float*)d_in[15];
    const float* ln2b  = (const float*)d_in[16];
    const float* a_att = (const float*)d_in[17];
    const float* a_ff  = (const float*)d_in[18];
    float* out = (float*)d_out;

    float *xln, *qkv, *attn, *x1, *xln2, *ff;
    float *wqkvt, *wot, *w1t, *w2t, *bqkv;
    cudaGetSymbolAddress((void**)&xln,   g_xln);
    cudaGetSymbolAddress((void**)&qkv,   g_qkv);
    cudaGetSymbolAddress((void**)&attn,  g_attn);
    cudaGetSymbolAddress((void**)&x1,    g_x1);
    cudaGetSymbolAddress((void**)&xln2,  g_xln2);
    cudaGetSymbolAddress((void**)&ff,    g_ff);
    cudaGetSymbolAddress((void**)&wqkvt, g_wqkvt);
    cudaGetSymbolAddress((void**)&wot,   g_wot);
    cudaGetSymbolAddress((void**)&w1t,   g_w1t);
    cudaGetSymbolAddress((void**)&w2t,   g_w2t);
    cudaGetSymbolAddress((void**)&bqkv,  g_bqkv);

    cudaFuncSetAttribute(gemm_mma<0>, cudaFuncAttributeMaxDynamicSharedMemorySize, GSMEM_DYN);
    cudaFuncSetAttribute(gemm_mma<1>, cudaFuncAttributeMaxDynamicSharedMemorySize, GSMEM_DYN);
    cudaFuncSetAttribute(gemm_mma<2>, cudaFuncAttributeMaxDynamicSharedMemorySize, GSMEM_DYN);
    cudaFuncSetAttribute(attn_mma,    cudaFuncAttributeMaxDynamicSharedMemorySize, AT_SMEM);

    dim3 tb(32, 8);
    transpose_kernel<<<dim3(EMB / 32, EMB / 32), tb>>>(wq, wqkvt,             EMB, EMB);
    transpose_kernel<<<dim3(EMB / 32, EMB / 32), tb>>>(wk, wqkvt + EMB*EMB,   EMB, EMB);
    transpose_kernel<<<dim3(EMB / 32, EMB / 32), tb>>>(wv, wqkvt + 2*EMB*EMB, EMB, EMB);
    transpose_kernel<<<dim3(EMB / 32, EMB / 32), tb>>>(wo, wot, EMB, EMB);
    transpose_kernel<<<dim3(FFD / 32, EMB / 32), tb>>>(w1, w1t, EMB, FFD);
    transpose_kernel<<<dim3(EMB / 32, FFD / 32), tb>>>(w2, w2t, FFD, EMB);
    concat_bias_kernel<<<QKV_LD / 256, 256>>>(bq, bk, bv, bqkv);

    // 1) LN1
    ln_kernel<<<NTOK, 256>>>(x, ln1g, ln1b, xln);
    // 2) fused QKV GEMM
    gemm_mma<0><<<dim3(QKV_LD / GBN, NTOK / GBM), 256, GSMEM_DYN>>>(
        xln, wqkvt, bqkv, nullptr, nullptr, qkv, NTOK, QKV_LD, EMB);
    // 3) causal attention (tf32 mma flash)
    attn_mma<<<dim3(SEQ / 64, BATCH * NHEAD), 128, AT_SMEM>>>(qkv, attn);
    // 4) O proj + residual
    gemm_mma<2><<<dim3(EMB / GBN, NTOK / GBM), 256, GSMEM_DYN>>>(
        attn, wot, bo, x, a_att, x1, NTOK, EMB, EMB);
    // 5) LN2
    ln_kernel<<<NTOK, 256>>>(x1, ln2g, ln2b, xln2);
    // 6) FF1 + GELU
    gemm_mma<1><<<dim3(FFD / GBN, NTOK / GBM), 256, GSMEM_DYN>>>(
        xln2, w1t, b1, nullptr, nullptr, ff, NTOK, FFD, EMB);
    // 7) FF2 + residual -> out
    gemm_mma<2><<<dim3(EMB / GBN, NTOK / GBM), 256, GSMEM_DYN>>>(
        ff, w2t, b2, x1, a_ff, out, NTOK, EMB, FFD);
}

// round 5
// speedup vs baseline: 4.2702x; 1.6106x over previous
#include <cuda_runtime.h>
#include <math.h>
#include <stdint.h>

#define NTOK 4096      // B*T
#define EMB  1024
#define FFD  4096
#define BATCH 2
#define SEQ  2048
#define NHEAD 16
#define HDIM 64
#define LN_EPS 1e-5f
#define QKV_LD 3072

// ---------------- scratch (device globals; no allocations allowed) ----------
__device__ float g_xln [NTOK * EMB];
__device__ float g_qkv [NTOK * QKV_LD];
__device__ float g_attn[NTOK * EMB];
__device__ float g_x1  [NTOK * EMB];
__device__ float g_xln2[NTOK * EMB];
__device__ float g_ff  [NTOK * FFD];
// transposed weights [N, K]
__device__ float g_wqkvt[QKV_LD * EMB];
__device__ float g_wot  [EMB * EMB];
__device__ float g_w1t  [EMB * FFD];
__device__ float g_w2t  [FFD * EMB];
__device__ float g_bqkv [QKV_LD];

// ---------------- helpers ----------------------------------------------------
__device__ __forceinline__ uint32_t sm_u32(const void* p) {
    return (uint32_t)__cvta_generic_to_shared(p);
}
__device__ __forceinline__ void cp_async16(uint32_t smem, const void* gptr) {
    asm volatile("cp.async.cg.shared.global [%0], [%1], 16;"
                 :: "r"(smem), "l"(__cvta_generic_to_global(gptr)) : "memory");
}
__device__ __forceinline__ void cp_commit() {
    asm volatile("cp.async.commit_group;" ::: "memory");
}
template<int N>
__device__ __forceinline__ void cp_wait() {
    asm volatile("cp.async.wait_group %0;" :: "n"(N) : "memory");
}
__device__ __forceinline__ void mma_tf32(float* c, const uint32_t* a, const uint32_t* b) {
    asm volatile(
        "mma.sync.aligned.m16n8k8.row.col.f32.tf32.tf32.f32 "
        "{%0,%1,%2,%3}, {%4,%5,%6,%7}, {%8,%9}, {%0,%1,%2,%3};"
        : "+f"(c[0]), "+f"(c[1]), "+f"(c[2]), "+f"(c[3])
        : "r"(a[0]), "r"(a[1]), "r"(a[2]), "r"(a[3]), "r"(b[0]), "r"(b[1]));
}
__device__ __forceinline__ float gelu_exact(float c) {
    return 0.5f * c * (1.0f + erff(c * 0.70710678118654752f));
}

// ---------------- weight transpose: W[K,N] -> WT[N,K] -----------------------
__global__ __launch_bounds__(256) void transpose_kernel(
    const float* __restrict__ W, float* __restrict__ WT, int K, int N)
{
    __shared__ float t[32][33];
    int bx = blockIdx.x * 32, by = blockIdx.y * 32;
    int tx = threadIdx.x, ty = threadIdx.y;   // (32, 8)
    #pragma unroll
    for (int i = 0; i < 32; i += 8)
        t[ty + i][tx] = W[(size_t)(by + ty + i) * N + bx + tx];
    __syncthreads();
    #pragma unroll
    for (int i = 0; i < 32; i += 8)
        WT[(size_t)(bx + ty + i) * K + by + tx] = t[tx][ty + i];
}

__global__ __launch_bounds__(256) void concat_bias_kernel(
    const float* __restrict__ a, const float* __restrict__ b,
    const float* __restrict__ c, float* __restrict__ o)
{
    int i = blockIdx.x * 256 + threadIdx.x;
    if (i < EMB)           o[i] = a[i];
    else if (i < 2 * EMB)  o[i] = b[i - EMB];
    else if (i < 3 * EMB)  o[i] = c[i - 2 * EMB];
}

// ---------------- LayerNorm --------------------------------------------------
__global__ __launch_bounds__(256) void ln_kernel(
    const float* __restrict__ x, const float* __restrict__ g,
    const float* __restrict__ b, float* __restrict__ y)
{
    int row = blockIdx.x;
    int tid = threadIdx.x;
    const float* xr = x + row * EMB;
    float4 v = *(const float4*)&xr[tid * 4];
    float s  = v.x + v.y + v.z + v.w;
    float ss = v.x*v.x + v.y*v.y + v.z*v.z + v.w*v.w;

    #pragma unroll
    for (int off = 16; off > 0; off >>= 1) {
        s  += __shfl_down_sync(0xffffffffu, s,  off);
        ss += __shfl_down_sync(0xffffffffu, ss, off);
    }
    __shared__ float red_s[8], red_ss[8];
    int wid = tid >> 5, lid = tid & 31;
    if (lid == 0) { red_s[wid] = s; red_ss[wid] = ss; }
    __syncthreads();
    if (wid == 0) {
        float a  = (lid < 8) ? red_s[lid]  : 0.f;
        float a2 = (lid < 8) ? red_ss[lid] : 0.f;
        #pragma unroll
        for (int off = 4; off > 0; off >>= 1) {
            a  += __shfl_down_sync(0xffffffffu, a,  off);
            a2 += __shfl_down_sync(0xffffffffu, a2, off);
        }
        if (lid == 0) { red_s[0] = a; red_ss[0] = a2; }
    }
    __syncthreads();
    float mu  = red_s[0] * (1.0f / EMB);
    float var = red_ss[0] * (1.0f / EMB) - mu * mu;
    float rs  = rsqrtf(var + LN_EPS);

    float4 gv = *(const float4*)&g[tid * 4];
    float4 bv = *(const float4*)&b[tid * 4];
    float4 o;
    o.x = (v.x - mu) * rs * gv.x + bv.x;
    o.y = (v.y - mu) * rs * gv.y + bv.y;
    o.z = (v.z - mu) * rs * gv.z + bv.z;
    o.w = (v.w - mu) * rs * gv.w + bv.w;
    *(float4*)&y[row * EMB + tid * 4] = o;
}

// ---------------- tf32 mma.sync GEMM (128x128, occ 2) ------------------------
#define GBM 128
#define GBN 128
#define GBK 32
#define APITCH 36
#define TBYTES (128 * APITCH * 4)           // 18432 per operand
#define STAGE_BYTES (2 * TBYTES)            // 36864
#define GSTAGES 3
#define GSMEM_DYN (GSTAGES * STAGE_BYTES)   // 110592

template<int MODE>
__global__ __launch_bounds__(256, 2) void gemm_mma(
    const float* __restrict__ A, const float* __restrict__ BT,
    const float* __restrict__ bias, const float* __restrict__ res,
    const float* __restrict__ alpha_p, float* __restrict__ C,
    int M, int N, int K)
{
    extern __shared__ char dynsm[];
    int tid = threadIdx.x, wid = tid >> 5, lid = tid & 31;
    int gid = lid >> 2, tg = lid & 3;
    int wm = (wid & 1) * 64, wn = (wid >> 1) * 32;   // warp tile 64x32
    int bm = blockIdx.y * GBM, bn = blockIdx.x * GBN;

    float acc[4][4][4];
    #pragma unroll
    for (int mf = 0; mf < 4; mf++)
        #pragma unroll
        for (int nf = 0; nf < 4; nf++)
            #pragma unroll
            for (int i = 0; i < 4; i++) acc[mf][nf][i] = 0.f;

    auto load_stage = [&](int s) {
        char* base = dynsm + (s % GSTAGES) * STAGE_BYTES;
        float* As = (float*)base;
        float* Bs = (float*)(base + TBYTES);
        const float* Ag = A  + (size_t)bm * K + s * GBK;
        const float* Bg = BT + (size_t)bn * K + s * GBK;
        #pragma unroll
        for (int i = 0; i < 4; i++) {
            int idx = tid + i * 256;
            int r = idx >> 3, c = idx & 7;
            cp_async16(sm_u32(As + r * APITCH + c * 4), Ag + (size_t)r * K + c * 4);
        }
        #pragma unroll
        for (int i = 0; i < 4; i++) {
            int idx = tid + i * 256;
            int r = idx >> 3, c = idx & 7;
            cp_async16(sm_u32(Bs + r * APITCH + c * 4), Bg + (size_t)r * K + c * 4);
        }
    };

    load_stage(0); cp_commit();
    load_stage(1); cp_commit();

    int nst = K / GBK;
    for (int s = 0; s < nst; s++) {
        cp_wait<1>();
        __syncthreads();
        if (s + 2 < nst) load_stage(s + 2);
        cp_commit();

        const char* base = dynsm + (s % GSTAGES) * STAGE_BYTES;
        const float* As = (const float*)base;
        const float* Bs = (const float*)(base + TBYTES);

        #pragma unroll
        for (int ks = 0; ks < 4; ks++) {
            int k0 = ks * 8;
            uint32_t af[4][4], bf[4][2];
            #pragma unroll
            for (int mf = 0; mf < 4; mf++) {
                const float* p = As + (wm + mf * 16 + gid) * APITCH + k0 + tg;
                af[mf][0] = *(const uint32_t*)(p);
                af[mf][1] = *(const uint32_t*)(p + 8 * APITCH);
                af[mf][2] = *(const uint32_t*)(p + 4);
                af[mf][3] = *(const uint32_t*)(p + 8 * APITCH + 4);
            }
            #pragma unroll
            for (int nf = 0; nf < 4; nf++) {
                const float* p = Bs + (wn + nf * 8 + gid) * APITCH + k0 + tg;
                bf[nf][0] = *(const uint32_t*)(p);
                bf[nf][1] = *(const uint32_t*)(p + 4);
            }
            #pragma unroll
            for (int mf = 0; mf < 4; mf++)
                #pragma unroll
                for (int nf = 0; nf < 4; nf++)
                    mma_tf32(acc[mf][nf], af[mf], bf[nf]);
        }
    }

    float alpha = (MODE == 2) ? *alpha_p : 1.0f;
    #pragma unroll
    for (int mf = 0; mf < 4; mf++) {
        int r0 = bm + wm + mf * 16 + gid;
        #pragma unroll
        for (int nf = 0; nf < 4; nf++) {
            int col = bn + wn + nf * 8 + 2 * tg;
            float2 bv = *(const float2*)&bias[col];
            float v0 = acc[mf][nf][0] + bv.x;
            float v1 = acc[mf][nf][1] + bv.y;
            float v2 = acc[mf][nf][2] + bv.x;
            float v3 = acc[mf][nf][3] + bv.y;
            if (MODE == 1) {
                v0 = gelu_exact(v0); v1 = gelu_exact(v1);
                v2 = gelu_exact(v2); v3 = gelu_exact(v3);
            }
            if (MODE == 2) {
                float2 ra = *(const float2*)&res[(size_t)r0 * N + col];
                float2 rb = *(const float2*)&res[(size_t)(r0 + 8) * N + col];
                v0 = ra.x + alpha * v0; v1 = ra.y + alpha * v1;
                v2 = rb.x + alpha * v2; v3 = rb.y + alpha * v3;
            }
            *(float2*)&C[(size_t)r0 * N + col]       = make_float2(v0, v1);
            *(float2*)&C[(size_t)(r0 + 8) * N + col] = make_float2(v2, v3);
        }
    }
}

// ---------------- tf32 mma flash attention (cp.async double-buffered) --------
// BQ=64 rows / block, 4 warps (16 rows each), BK=64 keys per tile.
// smem: kv[2 buf][K 64x68 + V 64x68] + psh[64][68]; V stays [key][d] (no transpose).
#define ATP 68
#define AT_TILE (64 * ATP)                  // floats per K or V tile
#define AT_PSH  (4 * AT_TILE)
#define AT_SMEM (5 * AT_TILE * 4)           // 87040 bytes

__global__ __launch_bounds__(128) void attn_mma(
    const float* __restrict__ QKV, float* __restrict__ O)
{
    extern __shared__ float ash[];
    float* psh = ash + AT_PSH;

    int qt = gridDim.x - 1 - blockIdx.x;     // long blocks first
    int bh = blockIdx.y;
    int b  = bh >> 4, h = bh & 15;
    int tid = threadIdx.x, wid = tid >> 5, lid = tid & 31;
    int gid = lid >> 2, tg = lid & 3;
    int wm = wid * 16;
    int qb = qt * 64;
    const float scale = 0.125f;

    auto load_tile = [&](int kt, int buf) {
        float* kb = ash + buf * 2 * AT_TILE;
        float* vb = kb + AT_TILE;
        #pragma unroll
        for (int i = 0; i < 8; i++) {
            int idx = tid + i * 128;
            int r = idx >> 4, c4 = (idx & 15) * 4;
            const float* src = &QKV[(size_t)(b * SEQ + kt * 64 + r) * QKV_LD + h * HDIM + c4];
            cp_async16(sm_u32(kb + r * ATP + c4), src + EMB);
            cp_async16(sm_u32(vb + r * ATP + c4), src + 2 * EMB);
        }
    };

    // Q fragments for this warp's 16 rows (held for whole kernel)
    uint32_t qf[8][4];
    {
        const float* q0 = &QKV[(size_t)(b * SEQ + qb + wm + gid) * QKV_LD + h * HDIM];
        const float* q8 = q0 + 8 * QKV_LD;
        #pragma unroll
        for (int ks = 0; ks < 8; ks++) {
            qf[ks][0] = *(const uint32_t*)(q0 + ks * 8 + tg);
            qf[ks][1] = *(const uint32_t*)(q8 + ks * 8 + tg);
            qf[ks][2] = *(const uint32_t*)(q0 + ks * 8 + tg + 4);
            qf[ks][3] = *(const uint32_t*)(q8 + ks * 8 + tg + 4);
        }
    }

    float oacc[8][4];
    #pragma unroll
    for (int nf = 0; nf < 8; nf++)
        #pragma unroll
        for (int i = 0; i < 4; i++) oacc[nf][i] = 0.f;
    float om0 = -INFINITY, om1 = -INFINITY, ol0 = 0.f, ol1 = 0.f;

    int r0 = qb + wm + gid, r1 = r0 + 8;
    int nkt = qt + 1;

    load_tile(0, 0); cp_commit();

    for (int kt = 0; kt < nkt; kt++) {
        if (kt + 1 < nkt) load_tile(kt + 1, (kt + 1) & 1);
        cp_commit();
        cp_wait<1>();
        __syncthreads();

        const float* ksh = ash + (kt & 1) * 2 * AT_TILE;
        const float* vsh = ksh + AT_TILE;

        // ---- S = Q @ K^T ----
        float sacc[8][4];
        #pragma unroll
        for (int nf = 0; nf < 8; nf++)
            #pragma unroll
            for (int i = 0; i < 4; i++) sacc[nf][i] = 0.f;
        #pragma unroll
        for (int ks = 0; ks < 8; ks++) {
            uint32_t bf[8][2];
            #pragma unroll
            for (int nf = 0; nf < 8; nf++) {
                const float* p = &ksh[(nf * 8 + gid) * ATP + ks * 8 + tg];
                bf[nf][0] = *(const uint32_t*)(p);
                bf[nf][1] = *(const uint32_t*)(p + 4);
            }
            #pragma unroll
            for (int nf = 0; nf < 8; nf++)
                mma_tf32(sacc[nf], qf[ks], bf[nf]);
        }

        // ---- scale + causal mask + row max ----
        bool diag = (kt == qt);
        float tmax0 = -INFINITY, tmax1 = -INFINITY;
        #pragma unroll
        for (int nf = 0; nf < 8; nf++) {
            int c0 = kt * 64 + nf * 8 + 2 * tg;
            #pragma unroll
            for (int c = 0; c < 2; c++) {
                float s0 = sacc[nf][c] * scale;
                float s1 = sacc[nf][2 + c] * scale;
                if (diag && c0 + c > r0) s0 = -INFINITY;
                if (diag && c0 + c > r1) s1 = -INFINITY;
                sacc[nf][c] = s0; sacc[nf][2 + c] = s1;
                tmax0 = fmaxf(tmax0, s0);
                tmax1 = fmaxf(tmax1, s1);
            }
        }
        tmax0 = fmaxf(tmax0, __shfl_xor_sync(0xffffffffu, tmax0, 1));
        tmax0 = fmaxf(tmax0, __shfl_xor_sync(0xffffffffu, tmax0, 2));
        tmax1 = fmaxf(tmax1, __shfl_xor_sync(0xffffffffu, tmax1, 1));
        tmax1 = fmaxf(tmax1, __shfl_xor_sync(0xffffffffu, tmax1, 2));

        float mn0 = fmaxf(om0, tmax0), mn1 = fmaxf(om1, tmax1);
        float corr0 = __expf(om0 - mn0), corr1 = __expf(om1 - mn1);
        om0 = mn0; om1 = mn1;

        float ps0 = 0.f, ps1 = 0.f;
        #pragma unroll
        for (int nf = 0; nf < 8; nf++) {
            #pragma unroll
            for (int c = 0; c < 2; c++) {
                float e0 = __expf(sacc[nf][c] - mn0);
                float e1 = __expf(sacc[nf][2 + c] - mn1);
                sacc[nf][c] = e0; sacc[nf][2 + c] = e1;
                ps0 += e0; ps1 += e1;
            }
        }
        ps0 += __shfl_xor_sync(0xffffffffu, ps0, 1);
        ps0 += __shfl_xor_sync(0xffffffffu, ps0, 2);
        ps1 += __shfl_xor_sync(0xffffffffu, ps1, 1);
        ps1 += __shfl_xor_sync(0xffffffffu, ps1, 2);
        ol0 = ol0 * corr0 + ps0;
        ol1 = ol1 * corr1 + ps1;

        #pragma unroll
        for (int nf = 0; nf < 8; nf++) {
            oacc[nf][0] *= corr0; oacc[nf][1] *= corr0;
            oacc[nf][2] *= corr1; oacc[nf][3] *= corr1;
        }

        // ---- P -> smem (warp-private rows) ----
        #pragma unroll
        for (int nf = 0; nf < 8; nf++) {
            int col = nf * 8 + 2 * tg;
            *(float2*)&psh[(wm + gid) * ATP + col]     = make_float2(sacc[nf][0], sacc[nf][1]);
            *(float2*)&psh[(wm + gid + 8) * ATP + col] = make_float2(sacc[nf][2], sacc[nf][3]);
        }
        __syncwarp();

        // ---- O += P @ V  (V read directly as [key][d], conflict-free) ----
        #pragma unroll
        for (int ks = 0; ks < 8; ks++) {
            uint32_t af[4];
            const float* p0 = &psh[(wm + gid) * ATP + ks * 8 + tg];
            const float* p8 = p0 + 8 * ATP;
            af[0] = *(const uint32_t*)(p0);
            af[1] = *(const uint32_t*)(p8);
            af[2] = *(const uint32_t*)(p0 + 4);
            af[3] = *(const uint32_t*)(p8 + 4);
            uint32_t bf[8][2];
            #pragma unroll
            for (int nf = 0; nf < 8; nf++) {
                const float* p = &vsh[(ks * 8 + tg) * ATP + nf * 8 + gid];
                bf[nf][0] = *(const uint32_t*)(p);
                bf[nf][1] = *(const uint32_t*)(p + 4 * ATP);
            }
            #pragma unroll
            for (int nf = 0; nf < 8; nf++)
                mma_tf32(oacc[nf], af, bf[nf]);
        }
        __syncthreads();
    }

    // ---- epilogue ----
    float inv0 = 1.0f / ol0, inv1 = 1.0f / ol1;
    float* o0 = &O[(size_t)(b * SEQ + r0) * EMB + h * HDIM];
    float* o8 = o0 + 8 * EMB;
    #pragma unroll
    for (int nf = 0; nf < 8; nf++) {
        int d = nf * 8 + 2 * tg;
        *(float2*)&o0[d] = make_float2(oacc[nf][0] * inv0, oacc[nf][1] * inv0);
        *(float2*)&o8[d] = make_float2(oacc[nf][2] * inv1, oacc[nf][3] * inv1);
    }
}

// ---------------- launch ----------------------------------------------------
extern "C" void kernel_launch(void* const* d_in, const int* in_sizes, int n_in,
                              void* d_out, int out_size)
{
    (void)in_sizes; (void)n_in; (void)out_size;
    const float* x     = (const float*)d_in[0];
    const float* wq    = (const float*)d_in[1];
    const float* bq    = (const float*)d_in[2];
    const float* wk    = (const float*)d_in[3];
    const float* bk    = (const float*)d_in[4];
    const float* wv    = (const float*)d_in[5];
    const float* bv    = (const float*)d_in[6];
    const float* wo    = (const float*)d_in[7];
    const float* bo    = (const float*)d_in[8];
    const float* w1    = (const float*)d_in[9];
    const float* b1    = (const float*)d_in[10];
    const float* w2    = (const float*)d_in[11];
    const float* b2    = (const float*)d_in[12];
    const float* ln1g  = (const float*)d_in[13];
    const float* ln1b  = (const float*)d_in[14];
    const float* ln2g  = (const float*)d_in[15];
    const float* ln2b  = (const float*)d_in[16];
    const float* a_att = (const float*)d_in[17];
    const float* a_ff  = (const float*)d_in[18];
    float* out = (float*)d_out;

    float *xln, *qkv, *attn, *x1, *xln2, *ff;
    float *wqkvt, *wot, *w1t, *w2t, *bqkv;
    cudaGetSymbolAddress((void**)&xln,   g_xln);
    cudaGetSymbolAddress((void**)&qkv,   g_qkv);
    cudaGetSymbolAddress((void**)&attn,  g_attn);
    cudaGetSymbolAddress((void**)&x1,    g_x1);
    cudaGetSymbolAddress((void**)&xln2,  g_xln2);
    cudaGetSymbolAddress((void**)&ff,    g_ff);
    cudaGetSymbolAddress((void**)&wqkvt, g_wqkvt);
    cudaGetSymbolAddress((void**)&wot,   g_wot);
    cudaGetSymbolAddress((void**)&w1t,   g_w1t);
    cudaGetSymbolAddress((void**)&w2t,   g_w2t);
    cudaGetSymbolAddress((void**)&bqkv,  g_bqkv);

    cudaFuncSetAttribute(gemm_mma<0>, cudaFuncAttributeMaxDynamicSharedMemorySize, GSMEM_DYN);
    cudaFuncSetAttribute(gemm_mma<1>, cudaFuncAttributeMaxDynamicSharedMemorySize, GSMEM_DYN);
    cudaFuncSetAttribute(gemm_mma<2>, cudaFuncAttributeMaxDynamicSharedMemorySize, GSMEM_DYN);
    cudaFuncSetAttribute(attn_mma,    cudaFuncAttributeMaxDynamicSharedMemorySize, AT_SMEM);

    dim3 tb(32, 8);
    transpose_kernel<<<dim3(EMB / 32, EMB / 32), tb>>>(wq, wqkvt,             EMB, EMB);
    transpose_kernel<<<dim3(EMB / 32, EMB / 32), tb>>>(wk, wqkvt + EMB*EMB,   EMB, EMB);
    transpose_kernel<<<dim3(EMB / 32, EMB / 32), tb>>>(wv, wqkvt + 2*EMB*EMB, EMB, EMB);
    transpose_kernel<<<dim3(EMB / 32, EMB / 32), tb>>>(wo, wot, EMB, EMB);
    transpose_kernel<<<dim3(FFD / 32, EMB / 32), tb>>>(w1, w1t, EMB, FFD);
    transpose_kernel<<<dim3(EMB / 32, FFD / 32), tb>>>(w2, w2t, FFD, EMB);
    concat_bias_kernel<<<QKV_LD / 256, 256>>>(bq, bk, bv, bqkv);

    // 1) LN1
    ln_kernel<<<NTOK, 256>>>(x, ln1g, ln1b, xln);
    // 2) fused QKV GEMM
    gemm_mma<0><<<dim3(QKV_LD / GBN, NTOK / GBM), 256, GSMEM_DYN>>>(
        xln, wqkvt, bqkv, nullptr, nullptr, qkv, NTOK, QKV_LD, EMB);
    // 3) causal attention (tf32 mma flash, double-buffered)
    attn_mma<<<dim3(SEQ / 64, BATCH * NHEAD), 128, AT_SMEM>>>(qkv, attn);
    // 4) O proj + residual
    gemm_mma<2><<<dim3(EMB / GBN, NTOK / GBM), 256, GSMEM_DYN>>>(
        attn, wot, bo, x, a_att, x1, NTOK, EMB, EMB);
    // 5) LN2
    ln_kernel<<<NTOK, 256>>>(x1, ln2g, ln2b, xln2);
    // 6) FF1 + GELU
    gemm_mma<1><<<dim3(FFD / GBN, NTOK / GBM), 256, GSMEM_DYN>>>(
        xln2, w1t, b1, nullptr, nullptr, ff, NTOK, FFD, EMB);
    // 7) FF2 + residual -> out
    gemm_mma<2><<<dim3(EMB / GBN, NTOK / GBM), 256, GSMEM_DYN>>>(
        ff, w2t, b2, x1, a_ff, out, NTOK, EMB, FFD);
}

// round 6
// speedup vs baseline: 4.4179x; 1.0346x over previous
#include <cuda_runtime.h>
#include <math.h>
#include <stdint.h>

#define NTOK 4096      // B*T
#define EMB  1024
#define FFD  4096
#define BATCH 2
#define SEQ  2048
#define NHEAD 16
#define HDIM 64
#define LN_EPS 1e-5f
#define QKV_LD 3072

// ---------------- scratch (device globals; no allocations allowed) ----------
__device__ float g_xln [NTOK * EMB];
__device__ float g_qkv [NTOK * QKV_LD];
__device__ float g_attn[NTOK * EMB];
__device__ float g_x1  [NTOK * EMB];
__device__ float g_xln2[NTOK * EMB];
__device__ float g_ff  [NTOK * FFD];

// ---------------- helpers ----------------------------------------------------
__device__ __forceinline__ uint32_t sm_u32(const void* p) {
    return (uint32_t)__cvta_generic_to_shared(p);
}
__device__ __forceinline__ void cp_async16(uint32_t smem, const void* gptr) {
    asm volatile("cp.async.cg.shared.global [%0], [%1], 16;"
                 :: "r"(smem), "l"(__cvta_generic_to_global(gptr)) : "memory");
}
__device__ __forceinline__ void cp_commit() {
    asm volatile("cp.async.commit_group;" ::: "memory");
}
template<int N>
__device__ __forceinline__ void cp_wait() {
    asm volatile("cp.async.wait_group %0;" :: "n"(N) : "memory");
}
__device__ __forceinline__ void mma_tf32(float* c, const uint32_t* a, const uint32_t* b) {
    asm volatile(
        "mma.sync.aligned.m16n8k8.row.col.f32.tf32.tf32.f32 "
        "{%0,%1,%2,%3}, {%4,%5,%6,%7}, {%8,%9}, {%0,%1,%2,%3};"
        : "+f"(c[0]), "+f"(c[1]), "+f"(c[2]), "+f"(c[3])
        : "r"(a[0]), "r"(a[1]), "r"(a[2]), "r"(a[3]), "r"(b[0]), "r"(b[1]));
}
__device__ __forceinline__ float gelu_exact(float c) {
    return 0.5f * c * (1.0f + erff(c * 0.70710678118654752f));
}

// ---------------- LayerNorm --------------------------------------------------
__global__ __launch_bounds__(256) void ln_kernel(
    const float* __restrict__ x, const float* __restrict__ g,
    const float* __restrict__ b, float* __restrict__ y)
{
    int row = blockIdx.x;
    int tid = threadIdx.x;
    const float* xr = x + row * EMB;
    float4 v = *(const float4*)&xr[tid * 4];
    float s  = v.x + v.y + v.z + v.w;
    float ss = v.x*v.x + v.y*v.y + v.z*v.z + v.w*v.w;

    #pragma unroll
    for (int off = 16; off > 0; off >>= 1) {
        s  += __shfl_down_sync(0xffffffffu, s,  off);
        ss += __shfl_down_sync(0xffffffffu, ss, off);
    }
    __shared__ float red_s[8], red_ss[8];
    int wid = tid >> 5, lid = tid & 31;
    if (lid == 0) { red_s[wid] = s; red_ss[wid] = ss; }
    __syncthreads();
    if (wid == 0) {
        float a  = (lid < 8) ? red_s[lid]  : 0.f;
        float a2 = (lid < 8) ? red_ss[lid] : 0.f;
        #pragma unroll
        for (int off = 4; off > 0; off >>= 1) {
            a  += __shfl_down_sync(0xffffffffu, a,  off);
            a2 += __shfl_down_sync(0xffffffffu, a2, off);
        }
        if (lid == 0) { red_s[0] = a; red_ss[0] = a2; }
    }
    __syncthreads();
    float mu  = red_s[0] * (1.0f / EMB);
    float var = red_ss[0] * (1.0f / EMB) - mu * mu;
    float rs  = rsqrtf(var + LN_EPS);

    float4 gv = *(const float4*)&g[tid * 4];
    float4 bv = *(const float4*)&b[tid * 4];
    float4 o;
    o.x = (v.x - mu) * rs * gv.x + bv.x;
    o.y = (v.y - mu) * rs * gv.y + bv.y;
    o.z = (v.z - mu) * rs * gv.z + bv.z;
    o.w = (v.w - mu) * rs * gv.w + bv.w;
    *(float4*)&y[row * EMB + tid * 4] = o;
}

// ---------------- tf32 mma.sync GEMM, B in natural [K,N] layout --------------
// C[M,N] = epilogue(A[M,K] @ W[K,N] + bias)
// MODE 0: +bias   MODE 1: gelu(+bias)   MODE 2: res + alpha*(+bias)
// NSEL 3: select W/bias from {0,1,2} by output column block (fused QKV)
#define GBM 128
#define GBN 128
#define GBK 32
#define APITCH 36
#define BPITCH 136                         // 136 mod 32 == 8 -> conflict-free frags
#define ABYTES (GBM * APITCH * 4)          // 18432
#define BBYTES (GBK * BPITCH * 4)          // 17408
#define STAGE_BYTES (ABYTES + BBYTES)      // 35840
#define GSTAGES 3
#define GSMEM_DYN (GSTAGES * STAGE_BYTES)  // 107520

template<int MODE, int NSEL>
__global__ __launch_bounds__(256, 2) void gemm_mma(
    const float* __restrict__ A,
    const float* __restrict__ W0, const float* __restrict__ W1,
    const float* __restrict__ W2,
    const float* __restrict__ bias0, const float* __restrict__ bias1,
    const float* __restrict__ bias2,
    const float* __restrict__ res, const float* __restrict__ alpha_p,
    float* __restrict__ C, int M, int N, int K, int Nw)
{
    extern __shared__ char dynsm[];
    int tid = threadIdx.x, wid = tid >> 5, lid = tid & 31;
    int gid = lid >> 2, tg = lid & 3;
    int wm = (wid & 1) * 64, wn = (wid >> 1) * 32;   // warp tile 64x32
    int bm = blockIdx.y * GBM, bn = blockIdx.x * GBN;

    const float* W = W0;
    const float* bias = bias0;
    int bnw = bn;
    if (NSEL == 3) {
        int sel = bn / Nw;
        W    = (sel == 0) ? W0 : ((sel == 1) ? W1 : W2);
        bias = (sel == 0) ? bias0 : ((sel == 1) ? bias1 : bias2);
        bnw  = bn - sel * Nw;
    }

    float acc[4][4][4];
    #pragma unroll
    for (int mf = 0; mf < 4; mf++)
        #pragma unroll
        for (int nf = 0; nf < 4; nf++)
            #pragma unroll
            for (int i = 0; i < 4; i++) acc[mf][nf][i] = 0.f;

    auto load_stage = [&](int s) {
        char* base = dynsm + (s % GSTAGES) * STAGE_BYTES;
        float* As = (float*)base;
        float* Bs = (float*)(base + ABYTES);
        const float* Ag = A + (size_t)bm * K + s * GBK;
        const float* Wg = W + (size_t)(s * GBK) * Nw + bnw;
        #pragma unroll
        for (int i = 0; i < 4; i++) {      // A: 128 rows x 8 x16B chunks
            int idx = tid + i * 256;
            int r = idx >> 3, c = idx & 7;
            cp_async16(sm_u32(As + r * APITCH + c * 4), Ag + (size_t)r * K + c * 4);
        }
        #pragma unroll
        for (int i = 0; i < 4; i++) {      // B: 32 k-rows x 32 x16B chunks
            int idx = tid + i * 256;
            int r = idx >> 5, c = idx & 31;
            cp_async16(sm_u32(Bs + r * BPITCH + c * 4), Wg + (size_t)r * Nw + c * 4);
        }
    };

    load_stage(0); cp_commit();
    load_stage(1); cp_commit();

    int nst = K / GBK;
    for (int s = 0; s < nst; s++) {
        cp_wait<1>();
        __syncthreads();
        if (s + 2 < nst) load_stage(s + 2);
        cp_commit();

        const char* base = dynsm + (s % GSTAGES) * STAGE_BYTES;
        const float* As = (const float*)base;
        const float* Bs = (const float*)(base + ABYTES);

        #pragma unroll
        for (int ks = 0; ks < 4; ks++) {
            int k0 = ks * 8;
            uint32_t af[4][4], bf[4][2];
            #pragma unroll
            for (int mf = 0; mf < 4; mf++) {
                const float* p = As + (wm + mf * 16 + gid) * APITCH + k0 + tg;
                af[mf][0] = *(const uint32_t*)(p);
                af[mf][1] = *(const uint32_t*)(p + 8 * APITCH);
                af[mf][2] = *(const uint32_t*)(p + 4);
                af[mf][3] = *(const uint32_t*)(p + 8 * APITCH + 4);
            }
            #pragma unroll
            for (int nf = 0; nf < 4; nf++) {
                const float* p = Bs + (k0 + tg) * BPITCH + wn + nf * 8 + gid;
                bf[nf][0] = *(const uint32_t*)(p);
                bf[nf][1] = *(const uint32_t*)(p + 4 * BPITCH);
            }
            #pragma unroll
            for (int mf = 0; mf < 4; mf++)
                #pragma unroll
                for (int nf = 0; nf < 4; nf++)
                    mma_tf32(acc[mf][nf], af[mf], bf[nf]);
        }
    }

    float alpha = (MODE == 2) ? *alpha_p : 1.0f;
    #pragma unroll
    for (int mf = 0; mf < 4; mf++) {
        int r0 = bm + wm + mf * 16 + gid;
        #pragma unroll
        for (int nf = 0; nf < 4; nf++) {
            int loc = wn + nf * 8 + 2 * tg;
            int col = bn + loc;
            float2 bv = *(const float2*)&bias[bnw + loc];
            float v0 = acc[mf][nf][0] + bv.x;
            float v1 = acc[mf][nf][1] + bv.y;
            float v2 = acc[mf][nf][2] + bv.x;
            float v3 = acc[mf][nf][3] + bv.y;
            if (MODE == 1) {
                v0 = gelu_exact(v0); v1 = gelu_exact(v1);
                v2 = gelu_exact(v2); v3 = gelu_exact(v3);
            }
            if (MODE == 2) {
                float2 ra = *(const float2*)&res[(size_t)r0 * N + col];
                float2 rb = *(const float2*)&res[(size_t)(r0 + 8) * N + col];
                v0 = ra.x + alpha * v0; v1 = ra.y + alpha * v1;
                v2 = rb.x + alpha * v2; v3 = rb.y + alpha * v3;
            }
            *(float2*)&C[(size_t)r0 * N + col]       = make_float2(v0, v1);
            *(float2*)&C[(size_t)(r0 + 8) * N + col] = make_float2(v2, v3);
        }
    }
}

// ---------------- tf32 mma flash attention (BQ=128, double-buffered) ---------
// 8 warps (16 q-rows each), BK=64 keys per tile.
#define ATP 68
#define AT_TILE (64 * ATP)                  // floats per K or V tile
#define AT_PSH  (4 * AT_TILE)               // after 2 x (K+V) buffers
#define AT_SMEM ((4 * AT_TILE + 128 * ATP) * 4)   // 69632 + 34816 = 104448 B

__global__ __launch_bounds__(256) void attn_mma(
    const float* __restrict__ QKV, float* __restrict__ O)
{
    extern __shared__ float ash[];
    float* psh = ash + AT_PSH;              // [128][68]

    int qt = gridDim.x - 1 - blockIdx.x;     // long blocks first
    int bh = blockIdx.y;
    int b  = bh >> 4, h = bh & 15;
    int tid = threadIdx.x, wid = tid >> 5, lid = tid & 31;
    int gid = lid >> 2, tg = lid & 3;
    int wm = wid * 16;
    int qb = qt * 128;
    const float scale = 0.125f;

    auto load_tile = [&](int kt, int buf) {
        float* kb = ash + buf * 2 * AT_TILE;
        float* vb = kb + AT_TILE;
        #pragma unroll
        for (int i = 0; i < 4; i++) {
            int idx = tid + i * 256;
            int r = idx >> 4, c4 = (idx & 15) * 4;
            const float* src = &QKV[(size_t)(b * SEQ + kt * 64 + r) * QKV_LD + h * HDIM + c4];
            cp_async16(sm_u32(kb + r * ATP + c4), src + EMB);
            cp_async16(sm_u32(vb + r * ATP + c4), src + 2 * EMB);
        }
    };

    // Q fragments for this warp's 16 rows (held for whole kernel)
    uint32_t qf[8][4];
    {
        const float* q0 = &QKV[(size_t)(b * SEQ + qb + wm + gid) * QKV_LD + h * HDIM];
        const float* q8 = q0 + 8 * QKV_LD;
        #pragma unroll
        for (int ks = 0; ks < 8; ks++) {
            qf[ks][0] = *(const uint32_t*)(q0 + ks * 8 + tg);
            qf[ks][1] = *(const uint32_t*)(q8 + ks * 8 + tg);
            qf[ks][2] = *(const uint32_t*)(q0 + ks * 8 + tg + 4);
            qf[ks][3] = *(const uint32_t*)(q8 + ks * 8 + tg + 4);
        }
    }

    float oacc[8][4];
    #pragma unroll
    for (int nf = 0; nf < 8; nf++)
        #pragma unroll
        for (int i = 0; i < 4; i++) oacc[nf][i] = 0.f;
    float om0 = -INFINITY, om1 = -INFINITY, ol0 = 0.f, ol1 = 0.f;

    int r0 = qb + wm + gid, r1 = r0 + 8;
    int nkt = 2 * qt + 2;

    load_tile(0, 0); cp_commit();

    for (int kt = 0; kt < nkt; kt++) {
        if (kt + 1 < nkt) load_tile(kt + 1, (kt + 1) & 1);
        cp_commit();
        cp_wait<1>();
        __syncthreads();

        const float* ksh = ash + (kt & 1) * 2 * AT_TILE;
        const float* vsh = ksh + AT_TILE;

        // ---- S = Q @ K^T ----
        float sacc[8][4];
        #pragma unroll
        for (int nf = 0; nf < 8; nf++)
            #pragma unroll
            for (int i = 0; i < 4; i++) sacc[nf][i] = 0.f;
        #pragma unroll
        for (int ks = 0; ks < 8; ks++) {
            uint32_t bf[8][2];
            #pragma unroll
            for (int nf = 0; nf < 8; nf++) {
                const float* p = &ksh[(nf * 8 + gid) * ATP + ks * 8 + tg];
                bf[nf][0] = *(const uint32_t*)(p);
                bf[nf][1] = *(const uint32_t*)(p + 4);
            }
            #pragma unroll
            for (int nf = 0; nf < 8; nf++)
                mma_tf32(sacc[nf], qf[ks], bf[nf]);
        }

        // ---- scale + causal mask + row max ----
        bool diag = (kt >= 2 * qt);
        float tmax0 = -INFINITY, tmax1 = -INFINITY;
        #pragma unroll
        for (int nf = 0; nf < 8; nf++) {
            int c0 = kt * 64 + nf * 8 + 2 * tg;
            #pragma unroll
            for (int c = 0; c < 2; c++) {
                float s0 = sacc[nf][c] * scale;
                float s1 = sacc[nf][2 + c] * scale;
                if (diag && c0 + c > r0) s0 = -INFINITY;
                if (diag && c0 + c > r1) s1 = -INFINITY;
                sacc[nf][c] = s0; sacc[nf][2 + c] = s1;
                tmax0 = fmaxf(tmax0, s0);
                tmax1 = fmaxf(tmax1, s1);
            }
        }
        tmax0 = fmaxf(tmax0, __shfl_xor_sync(0xffffffffu, tmax0, 1));
        tmax0 = fmaxf(tmax0, __shfl_xor_sync(0xffffffffu, tmax0, 2));
        tmax1 = fmaxf(tmax1, __shfl_xor_sync(0xffffffffu, tmax1, 1));
        tmax1 = fmaxf(tmax1, __shfl_xor_sync(0xffffffffu, tmax1, 2));

        float mn0 = fmaxf(om0, tmax0), mn1 = fmaxf(om1, tmax1);
        float corr0 = __expf(om0 - mn0), corr1 = __expf(om1 - mn1);
        om0 = mn0; om1 = mn1;

        float ps0 = 0.f, ps1 = 0.f;
        #pragma unroll
        for (int nf = 0; nf < 8; nf++) {
            #pragma unroll
            for (int c = 0; c < 2; c++) {
                float e0 = __expf(sacc[nf][c] - mn0);
                float e1 = __expf(sacc[nf][2 + c] - mn1);
                sacc[nf][c] = e0; sacc[nf][2 + c] = e1;
                ps0 += e0; ps1 += e1;
            }
        }
        ps0 += __shfl_xor_sync(0xffffffffu, ps0, 1);
        ps0 += __shfl_xor_sync(0xffffffffu, ps0, 2);
        ps1 += __shfl_xor_sync(0xffffffffu, ps1, 1);
        ps1 += __shfl_xor_sync(0xffffffffu, ps1, 2);
        ol0 = ol0 * corr0 + ps0;
        ol1 = ol1 * corr1 + ps1;

        #pragma unroll
        for (int nf = 0; nf < 8; nf++) {
            oacc[nf][0] *= corr0; oacc[nf][1] *= corr0;
            oacc[nf][2] *= corr1; oacc[nf][3] *= corr1;
        }

        // ---- P -> smem (warp-private rows) ----
        #pragma unroll
        for (int nf = 0; nf < 8; nf++) {
            int col = nf * 8 + 2 * tg;
            *(float2*)&psh[(wm + gid) * ATP + col]     = make_float2(sacc[nf][0], sacc[nf][1]);
            *(float2*)&psh[(wm + gid + 8) * ATP + col] = make_float2(sacc[nf][2], sacc[nf][3]);
        }
        __syncwarp();

        // ---- O += P @ V  (V read directly as [key][d]) ----
        #pragma unroll
        for (int ks = 0; ks < 8; ks++) {
            uint32_t af[4];
            const float* p0 = &psh[(wm + gid) * ATP + ks * 8 + tg];
            const float* p8 = p0 + 8 * ATP;
            af[0] = *(const uint32_t*)(p0);
            af[1] = *(const uint32_t*)(p8);
            af[2] = *(const uint32_t*)(p0 + 4);
            af[3] = *(const uint32_t*)(p8 + 4);
            uint32_t bf[8][2];
            #pragma unroll
            for (int nf = 0; nf < 8; nf++) {
                const float* p = &vsh[(ks * 8 + tg) * ATP + nf * 8 + gid];
                bf[nf][0] = *(const uint32_t*)(p);
                bf[nf][1] = *(const uint32_t*)(p + 4 * ATP);
            }
            #pragma unroll
            for (int nf = 0; nf < 8; nf++)
                mma_tf32(oacc[nf], af, bf[nf]);
        }
        __syncthreads();
    }

    // ---- epilogue ----
    float inv0 = 1.0f / ol0, inv1 = 1.0f / ol1;
    float* o0 = &O[(size_t)(b * SEQ + r0) * EMB + h * HDIM];
    float* o8 = o0 + 8 * EMB;
    #pragma unroll
    for (int nf = 0; nf < 8; nf++) {
        int d = nf * 8 + 2 * tg;
        *(float2*)&o0[d] = make_float2(oacc[nf][0] * inv0, oacc[nf][1] * inv0);
        *(float2*)&o8[d] = make_float2(oacc[nf][2] * inv1, oacc[nf][3] * inv1);
    }
}

// ---------------- launch ----------------------------------------------------
extern "C" void kernel_launch(void* const* d_in, const int* in_sizes, int n_in,
                              void* d_out, int out_size)
{
    (void)in_sizes; (void)n_in; (void)out_size;
    const float* x     = (const float*)d_in[0];
    const float* wq    = (const float*)d_in[1];
    const float* bq    = (const float*)d_in[2];
    const float* wk    = (const float*)d_in[3];
    const float* bk    = (const float*)d_in[4];
    const float* wv    = (const float*)d_in[5];
    const float* bv    = (const float*)d_in[6];
    const float* wo    = (const float*)d_in[7];
    const float* bo    = (const float*)d_in[8];
    const float* w1    = (const float*)d_in[9];
    const float* b1    = (const float*)d_in[10];
    const float* w2    = (const float*)d_in[11];
    const float* b2    = (const float*)d_in[12];
    const float* ln1g  = (const float*)d_in[13];
    const float* ln1b  = (const float*)d_in[14];
    const float* ln2g  = (const float*)d_in[15];
    const float* ln2b  = (const float*)d_in[16];
    const float* a_att = (const float*)d_in[17];
    const float* a_ff  = (const float*)d_in[18];
    float* out = (float*)d_out;

    float *xln, *qkv, *attn, *x1, *xln2, *ff;
    cudaGetSymbolAddress((void**)&xln,  g_xln);
    cudaGetSymbolAddress((void**)&qkv,  g_qkv);
    cudaGetSymbolAddress((void**)&attn, g_attn);
    cudaGetSymbolAddress((void**)&x1,   g_x1);
    cudaGetSymbolAddress((void**)&xln2, g_xln2);
    cudaGetSymbolAddress((void**)&ff,   g_ff);

    cudaFuncSetAttribute(gemm_mma<0,3>, cudaFuncAttributeMaxDynamicSharedMemorySize, GSMEM_DYN);
    cudaFuncSetAttribute(gemm_mma<1,1>, cudaFuncAttributeMaxDynamicSharedMemorySize, GSMEM_DYN);
    cudaFuncSetAttribute(gemm_mma<2,1>, cudaFuncAttributeMaxDynamicSharedMemorySize, GSMEM_DYN);
    cudaFuncSetAttribute(attn_mma,      cudaFuncAttributeMaxDynamicSharedMemorySize, AT_SMEM);

    // 1) LN1
    ln_kernel<<<NTOK, 256>>>(x, ln1g, ln1b, xln);
    // 2) fused QKV GEMM (per-block weight select, no transposes)
    gemm_mma<0,3><<<dim3(QKV_LD / GBN, NTOK / GBM), 256, GSMEM_DYN>>>(
        xln, wq, wk, wv, bq, bk, bv, nullptr, nullptr, qkv,
        NTOK, QKV_LD, EMB, EMB);
    // 3) causal attention (tf32 mma flash, BQ=128, double-buffered)
    attn_mma<<<dim3(SEQ / 128, BATCH * NHEAD), 256, AT_SMEM>>>(qkv, attn);
    // 4) O proj + residual
    gemm_mma<2,1><<<dim3(EMB / GBN, NTOK / GBM), 256, GSMEM_DYN>>>(
        attn, wo, nullptr, nullptr, bo, nullptr, nullptr, x, a_att, x1,
        NTOK, EMB, EMB, EMB);
    // 5) LN2
    ln_kernel<<<NTOK, 256>>>(x1, ln2g, ln2b, xln2);
    // 6) FF1 + GELU
    gemm_mma<1,1><<<dim3(FFD / GBN, NTOK / GBM), 256, GSMEM_DYN>>>(
        xln2, w1, nullptr, nullptr, b1, nullptr, nullptr, nullptr, nullptr, ff,
        NTOK, FFD, EMB, FFD);
    // 7) FF2 + residual -> out
    gemm_mma<2,1><<<dim3(EMB / GBN, NTOK / GBM), 256, GSMEM_DYN>>>(
        ff, w2, nullptr, nullptr, b2, nullptr, nullptr, x1, a_ff, out,
        NTOK, EMB, FFD, EMB);
}

// round 7
// speedup vs baseline: 4.6333x; 1.0487x over previous
#include <cuda_runtime.h>
#include <math.h>
#include <stdint.h>

#define NTOK 4096      // B*T
#define EMB  1024
#define FFD  4096
#define BATCH 2
#define SEQ  2048
#define NHEAD 16
#define HDIM 64
#define LN_EPS 1e-5f
#define QKV_LD 3072

// ---------------- scratch (device globals; no allocations allowed) ----------
__device__ float g_xln [NTOK * EMB];
__device__ float g_qkv [NTOK * QKV_LD];
__device__ float g_attn[NTOK * EMB];
__device__ float g_x1  [NTOK * EMB];
__device__ float g_xln2[NTOK * EMB];
__device__ float g_ff  [NTOK * FFD];

// ---------------- helpers ----------------------------------------------------
__device__ __forceinline__ uint32_t sm_u32(const void* p) {
    return (uint32_t)__cvta_generic_to_shared(p);
}
__device__ __forceinline__ void cp_async16(uint32_t smem, const void* gptr) {
    asm volatile("cp.async.cg.shared.global [%0], [%1], 16;"
                 :: "r"(smem), "l"(__cvta_generic_to_global(gptr)) : "memory");
}
__device__ __forceinline__ void cp_commit() {
    asm volatile("cp.async.commit_group;" ::: "memory");
}
template<int N>
__device__ __forceinline__ void cp_wait() {
    asm volatile("cp.async.wait_group %0;" :: "n"(N) : "memory");
}
__device__ __forceinline__ void mma_tf32(float* c, const uint32_t* a, const uint32_t* b) {
    asm volatile(
        "mma.sync.aligned.m16n8k8.row.col.f32.tf32.tf32.f32 "
        "{%0,%1,%2,%3}, {%4,%5,%6,%7}, {%8,%9}, {%0,%1,%2,%3};"
        : "+f"(c[0]), "+f"(c[1]), "+f"(c[2]), "+f"(c[3])
        : "r"(a[0]), "r"(a[1]), "r"(a[2]), "r"(a[3]), "r"(b[0]), "r"(b[1]));
}
__device__ __forceinline__ void ldsm_x4(uint32_t* r, uint32_t addr) {
    asm volatile("ldmatrix.sync.aligned.m8n8.x4.shared.b16 {%0,%1,%2,%3}, [%4];"
                 : "=r"(r[0]), "=r"(r[1]), "=r"(r[2]), "=r"(r[3]) : "r"(addr));
}
__device__ __forceinline__ float gelu_exact(float c) {
    return 0.5f * c * (1.0f + erff(c * 0.70710678118654752f));
}

// ---------------- LayerNorm --------------------------------------------------
__global__ __launch_bounds__(256) void ln_kernel(
    const float* __restrict__ x, const float* __restrict__ g,
    const float* __restrict__ b, float* __restrict__ y)
{
    int row = blockIdx.x;
    int tid = threadIdx.x;
    const float* xr = x + row * EMB;
    float4 v = *(const float4*)&xr[tid * 4];
    float s  = v.x + v.y + v.z + v.w;
    float ss = v.x*v.x + v.y*v.y + v.z*v.z + v.w*v.w;

    #pragma unroll
    for (int off = 16; off > 0; off >>= 1) {
        s  += __shfl_down_sync(0xffffffffu, s,  off);
        ss += __shfl_down_sync(0xffffffffu, ss, off);
    }
    __shared__ float red_s[8], red_ss[8];
    int wid = tid >> 5, lid = tid & 31;
    if (lid == 0) { red_s[wid] = s; red_ss[wid] = ss; }
    __syncthreads();
    if (wid == 0) {
        float a  = (lid < 8) ? red_s[lid]  : 0.f;
        float a2 = (lid < 8) ? red_ss[lid] : 0.f;
        #pragma unroll
        for (int off = 4; off > 0; off >>= 1) {
            a  += __shfl_down_sync(0xffffffffu, a,  off);
            a2 += __shfl_down_sync(0xffffffffu, a2, off);
        }
        if (lid == 0) { red_s[0] = a; red_ss[0] = a2; }
    }
    __syncthreads();
    float mu  = red_s[0] * (1.0f / EMB);
    float var = red_ss[0] * (1.0f / EMB) - mu * mu;
    float rs  = rsqrtf(var + LN_EPS);

    float4 gv = *(const float4*)&g[tid * 4];
    float4 bv = *(const float4*)&b[tid * 4];
    float4 o;
    o.x = (v.x - mu) * rs * gv.x + bv.x;
    o.y = (v.y - mu) * rs * gv.y + bv.y;
    o.z = (v.z - mu) * rs * gv.z + bv.z;
    o.w = (v.w - mu) * rs * gv.w + bv.w;
    *(float4*)&y[row * EMB + tid * 4] = o;
}

// ---------------- tf32 mma.sync GEMM, ldmatrix A fragments -------------------
// C[M,N] = epilogue(A[M,K] @ W[K,N] + bias)
// MODE 0: +bias   MODE 1: gelu(+bias)   MODE 2: res + alpha*(+bias)
// NSEL 3: select W/bias from {0,1,2} by output column block (fused QKV)
#define GBM 128
#define GBN 128
#define GBK 32
#define APITCH 36
#define BPITCH 136                         // 136 mod 32 == 8 -> conflict-free frags
#define ABYTES (GBM * APITCH * 4)          // 18432
#define BBYTES (GBK * BPITCH * 4)          // 17408
#define STAGE_BYTES (ABYTES + BBYTES)      // 35840
#define GSTAGES 3
#define GSMEM_DYN (GSTAGES * STAGE_BYTES)  // 107520

template<int MODE, int NSEL>
__global__ __launch_bounds__(256, 2) void gemm_mma(
    const float* __restrict__ A,
    const float* __restrict__ W0, const float* __restrict__ W1,
    const float* __restrict__ W2,
    const float* __restrict__ bias0, const float* __restrict__ bias1,
    const float* __restrict__ bias2,
    const float* __restrict__ res, const float* __restrict__ alpha_p,
    float* __restrict__ C, int M, int N, int K, int Nw)
{
    extern __shared__ char dynsm[];
    int tid = threadIdx.x, wid = tid >> 5, lid = tid & 31;
    int gid = lid >> 2, tg = lid & 3;
    int wm = (wid & 1) * 64, wn = (wid >> 1) * 32;   // warp tile 64x32
    int bm = blockIdx.y * GBM, bn = blockIdx.x * GBN;

    const float* W = W0;
    const float* bias = bias0;
    int bnw = bn;
    if (NSEL == 3) {
        int sel = bn / Nw;
        W    = (sel == 0) ? W0 : ((sel == 1) ? W1 : W2);
        bias = (sel == 0) ? bias0 : ((sel == 1) ? bias1 : bias2);
        bnw  = bn - sel * Nw;
    }

    // ldmatrix lane address offsets for A (bytes, within a stage's As)
    // tile t = lid>>3: t&1 -> +8 rows, t>>1 -> +4 k
    uint32_t a_lane_off[4];
    {
        int t = lid >> 3, l7 = lid & 7;
        int arow = wm + (t & 1) * 8 + l7;
        int acol = (t >> 1) * 4;
        #pragma unroll
        for (int mf = 0; mf < 4; mf++)
            a_lane_off[mf] = (uint32_t)(((arow + mf * 16) * APITCH + acol) * 4);
    }

    float acc[4][4][4];
    #pragma unroll
    for (int mf = 0; mf < 4; mf++)
        #pragma unroll
        for (int nf = 0; nf < 4; nf++)
            #pragma unroll
            for (int i = 0; i < 4; i++) acc[mf][nf][i] = 0.f;

    auto load_stage = [&](int s) {
        char* base = dynsm + (s % GSTAGES) * STAGE_BYTES;
        float* As = (float*)base;
        float* Bs = (float*)(base + ABYTES);
        const float* Ag = A + (size_t)bm * K + s * GBK;
        const float* Wg = W + (size_t)(s * GBK) * Nw + bnw;
        #pragma unroll
        for (int i = 0; i < 4; i++) {      // A: 128 rows x 8 x16B chunks
            int idx = tid + i * 256;
            int r = idx >> 3, c = idx & 7;
            cp_async16(sm_u32(As + r * APITCH + c * 4), Ag + (size_t)r * K + c * 4);
        }
        #pragma unroll
        for (int i = 0; i < 4; i++) {      // B: 32 k-rows x 32 x16B chunks
            int idx = tid + i * 256;
            int r = idx >> 5, c = idx & 31;
            cp_async16(sm_u32(Bs + r * BPITCH + c * 4), Wg + (size_t)r * Nw + c * 4);
        }
    };

    load_stage(0); cp_commit();
    load_stage(1); cp_commit();

    int nst = K / GBK;
    for (int s = 0; s < nst; s++) {
        cp_wait<1>();
        __syncthreads();
        if (s + 2 < nst) load_stage(s + 2);
        cp_commit();

        char* base = dynsm + (s % GSTAGES) * STAGE_BYTES;
        uint32_t as_u32 = sm_u32(base);
        const float* Bs = (const float*)(base + ABYTES);

        #pragma unroll
        for (int ks = 0; ks < 4; ks++) {
            int k0 = ks * 8;
            uint32_t af[4][4], bf[4][2];
            #pragma unroll
            for (int mf = 0; mf < 4; mf++)
                ldsm_x4(af[mf], as_u32 + a_lane_off[mf] + (uint32_t)(k0 * 4));
            #pragma unroll
            for (int nf = 0; nf < 4; nf++) {
                const float* p = Bs + (k0 + tg) * BPITCH + wn + nf * 8 + gid;
                bf[nf][0] = *(const uint32_t*)(p);
                bf[nf][1] = *(const uint32_t*)(p + 4 * BPITCH);
            }
            #pragma unroll
            for (int mf = 0; mf < 4; mf++)
                #pragma unroll
                for (int nf = 0; nf < 4; nf++)
                    mma_tf32(acc[mf][nf], af[mf], bf[nf]);
        }
    }

    float alpha = (MODE == 2) ? *alpha_p : 1.0f;
    #pragma unroll
    for (int mf = 0; mf < 4; mf++) {
        int r0 = bm + wm + mf * 16 + gid;
        #pragma unroll
        for (int nf = 0; nf < 4; nf++) {
            int loc = wn + nf * 8 + 2 * tg;
            int col = bn + loc;
            float2 bv = *(const float2*)&bias[bnw + loc];
            float v0 = acc[mf][nf][0] + bv.x;
            float v1 = acc[mf][nf][1] + bv.y;
            float v2 = acc[mf][nf][2] + bv.x;
            float v3 = acc[mf][nf][3] + bv.y;
            if (MODE == 1) {
                v0 = gelu_exact(v0); v1 = gelu_exact(v1);
                v2 = gelu_exact(v2); v3 = gelu_exact(v3);
            }
            if (MODE == 2) {
                float2 ra = *(const float2*)&res[(size_t)r0 * N + col];
                float2 rb = *(const float2*)&res[(size_t)(r0 + 8) * N + col];
                v0 = ra.x + alpha * v0; v1 = ra.y + alpha * v1;
                v2 = rb.x + alpha * v2; v3 = rb.y + alpha * v3;
            }
            *(float2*)&C[(size_t)r0 * N + col]       = make_float2(v0, v1);
            *(float2*)&C[(size_t)(r0 + 8) * N + col] = make_float2(v2, v3);
        }
    }
}

// ---------------- tf32 mma flash attention (BQ=128, double-buffered) ---------
// 8 warps (16 q-rows each), BK=64 keys per tile.
#define ATP 68
#define AT_TILE (64 * ATP)                  // floats per K or V tile
#define AT_PSH  (4 * AT_TILE)               // after 2 x (K+V) buffers
#define AT_SMEM ((4 * AT_TILE + 128 * ATP) * 4)   // 104448 B

__global__ __launch_bounds__(256) void attn_mma(
    const float* __restrict__ QKV, float* __restrict__ O)
{
    extern __shared__ float ash[];
    float* psh = ash + AT_PSH;              // [128][68]

    int qt = gridDim.x - 1 - blockIdx.x;     // long blocks first
    int bh = blockIdx.y;
    int b  = bh >> 4, h = bh & 15;
    int tid = threadIdx.x, wid = tid >> 5, lid = tid & 31;
    int gid = lid >> 2, tg = lid & 3;
    int wm = wid * 16;
    int qb = qt * 128;
    const float scale = 0.125f;

    auto load_tile = [&](int kt, int buf) {
        float* kb = ash + buf * 2 * AT_TILE;
        float* vb = kb + AT_TILE;
        #pragma unroll
        for (int i = 0; i < 4; i++) {
            int idx = tid + i * 256;
            int r = idx >> 4, c4 = (idx & 15) * 4;
            const float* src = &QKV[(size_t)(b * SEQ + kt * 64 + r) * QKV_LD + h * HDIM + c4];
            cp_async16(sm_u32(kb + r * ATP + c4), src + EMB);
            cp_async16(sm_u32(vb + r * ATP + c4), src + 2 * EMB);
        }
    };

    // Q fragments for this warp's 16 rows (held for whole kernel)
    uint32_t qf[8][4];
    {
        const float* q0 = &QKV[(size_t)(b * SEQ + qb + wm + gid) * QKV_LD + h * HDIM];
        const float* q8 = q0 + 8 * QKV_LD;
        #pragma unroll
        for (int ks = 0; ks < 8; ks++) {
            qf[ks][0] = *(const uint32_t*)(q0 + ks * 8 + tg);
            qf[ks][1] = *(const uint32_t*)(q8 + ks * 8 + tg);
            qf[ks][2] = *(const uint32_t*)(q0 + ks * 8 + tg + 4);
            qf[ks][3] = *(const uint32_t*)(q8 + ks * 8 + tg + 4);
        }
    }

    float oacc[8][4];
    #pragma unroll
    for (int nf = 0; nf < 8; nf++)
        #pragma unroll
        for (int i = 0; i < 4; i++) oacc[nf][i] = 0.f;
    float om0 = -INFINITY, om1 = -INFINITY, ol0 = 0.f, ol1 = 0.f;

    int r0 = qb + wm + gid, r1 = r0 + 8;
    int nkt = 2 * qt + 2;

    load_tile(0, 0); cp_commit();

    for (int kt = 0; kt < nkt; kt++) {
        if (kt + 1 < nkt) load_tile(kt + 1, (kt + 1) & 1);
        cp_commit();
        cp_wait<1>();
        __syncthreads();

        const float* ksh = ash + (kt & 1) * 2 * AT_TILE;
        const float* vsh = ksh + AT_TILE;

        // ---- S = Q @ K^T ----
        float sacc[8][4];
        #pragma unroll
        for (int nf = 0; nf < 8; nf++)
            #pragma unroll
            for (int i = 0; i < 4; i++) sacc[nf][i] = 0.f;
        #pragma unroll
        for (int ks = 0; ks < 8; ks++) {
            uint32_t bf[8][2];
            #pragma unroll
            for (int nf = 0; nf < 8; nf++) {
                const float* p = &ksh[(nf * 8 + gid) * ATP + ks * 8 + tg];
                bf[nf][0] = *(const uint32_t*)(p);
                bf[nf][1] = *(const uint32_t*)(p + 4);
            }
            #pragma unroll
            for (int nf = 0; nf < 8; nf++)
                mma_tf32(sacc[nf], qf[ks], bf[nf]);
        }

        // ---- scale + causal mask + row max ----
        bool diag = (kt >= 2 * qt);
        float tmax0 = -INFINITY, tmax1 = -INFINITY;
        #pragma unroll
        for (int nf = 0; nf < 8; nf++) {
            int c0 = kt * 64 + nf * 8 + 2 * tg;
            #pragma unroll
            for (int c = 0; c < 2; c++) {
                float s0 = sacc[nf][c] * scale;
                float s1 = sacc[nf][2 + c] * scale;
                if (diag && c0 + c > r0) s0 = -INFINITY;
                if (diag && c0 + c > r1) s1 = -INFINITY;
                sacc[nf][c] = s0; sacc[nf][2 + c] = s1;
                tmax0 = fmaxf(tmax0, s0);
                tmax1 = fmaxf(tmax1, s1);
            }
        }
        tmax0 = fmaxf(tmax0, __shfl_xor_sync(0xffffffffu, tmax0, 1));
        tmax0 = fmaxf(tmax0, __shfl_xor_sync(0xffffffffu, tmax0, 2));
        tmax1 = fmaxf(tmax1, __shfl_xor_sync(0xffffffffu, tmax1, 1));
        tmax1 = fmaxf(tmax1, __shfl_xor_sync(0xffffffffu, tmax1, 2));

        float mn0 = fmaxf(om0, tmax0), mn1 = fmaxf(om1, tmax1);
        float corr0 = __expf(om0 - mn0), corr1 = __expf(om1 - mn1);
        om0 = mn0; om1 = mn1;

        float ps0 = 0.f, ps1 = 0.f;
        #pragma unroll
        for (int nf = 0; nf < 8; nf++) {
            #pragma unroll
            for (int c = 0; c < 2; c++) {
                float e0 = __expf(sacc[nf][c] - mn0);
                float e1 = __expf(sacc[nf][2 + c] - mn1);
                sacc[nf][c] = e0; sacc[nf][2 + c] = e1;
                ps0 += e0; ps1 += e1;
            }
        }
        ps0 += __shfl_xor_sync(0xffffffffu, ps0, 1);
        ps0 += __shfl_xor_sync(0xffffffffu, ps0, 2);
        ps1 += __shfl_xor_sync(0xffffffffu, ps1, 1);
        ps1 += __shfl_xor_sync(0xffffffffu, ps1, 2);
        ol0 = ol0 * corr0 + ps0;
        ol1 = ol1 * corr1 + ps1;

        #pragma unroll
        for (int nf = 0; nf < 8; nf++) {
            oacc[nf][0] *= corr0; oacc[nf][1] *= corr0;
            oacc[nf][2] *= corr1; oacc[nf][3] *= corr1;
        }

        // ---- P -> smem (warp-private rows) ----
        #pragma unroll
        for (int nf = 0; nf < 8; nf++) {
            int col = nf * 8 + 2 * tg;
            *(float2*)&psh[(wm + gid) * ATP + col]     = make_float2(sacc[nf][0], sacc[nf][1]);
            *(float2*)&psh[(wm + gid + 8) * ATP + col] = make_float2(sacc[nf][2], sacc[nf][3]);
        }
        __syncwarp();

        // ---- O += P @ V  (V read directly as [key][d]) ----
        #pragma unroll
        for (int ks = 0; ks < 8; ks++) {
            uint32_t af[4];
            const float* p0 = &psh[(wm + gid) * ATP + ks * 8 + tg];
            const float* p8 = p0 + 8 * ATP;
            af[0] = *(const uint32_t*)(p0);
            af[1] = *(const uint32_t*)(p8);
            af[2] = *(const uint32_t*)(p0 + 4);
            af[3] = *(const uint32_t*)(p8 + 4);
            uint32_t bf[8][2];
            #pragma unroll
            for (int nf = 0; nf < 8; nf++) {
                const float* p = &vsh[(ks * 8 + tg) * ATP + nf * 8 + gid];
                bf[nf][0] = *(const uint32_t*)(p);
                bf[nf][1] = *(const uint32_t*)(p + 4 * ATP);
            }
            #pragma unroll
            for (int nf = 0; nf < 8; nf++)
                mma_tf32(oacc[nf], af, bf[nf]);
        }
        __syncthreads();
    }

    // ---- epilogue ----
    float inv0 = 1.0f / ol0, inv1 = 1.0f / ol1;
    float* o0 = &O[(size_t)(b * SEQ + r0) * EMB + h * HDIM];
    float* o8 = o0 + 8 * EMB;
    #pragma unroll
    for (int nf = 0; nf < 8; nf++) {
        int d = nf * 8 + 2 * tg;
        *(float2*)&o0[d] = make_float2(oacc[nf][0] * inv0, oacc[nf][1] * inv0);
        *(float2*)&o8[d] = make_float2(oacc[nf][2] * inv1, oacc[nf][3] * inv1);
    }
}

// ---------------- launch ----------------------------------------------------
extern "C" void kernel_launch(void* const* d_in, const int* in_sizes, int n_in,
                              void* d_out, int out_size)
{
    (void)in_sizes; (void)n_in; (void)out_size;
    const float* x     = (const float*)d_in[0];
    const float* wq    = (const float*)d_in[1];
    const float* bq    = (const float*)d_in[2];
    const float* wk    = (const float*)d_in[3];
    const float* bk    = (const float*)d_in[4];
    const float* wv    = (const float*)d_in[5];
    const float* bv    = (const float*)d_in[6];
    const float* wo    = (const float*)d_in[7];
    const float* bo    = (const float*)d_in[8];
    const float* w1    = (const float*)d_in[9];
    const float* b1    = (const float*)d_in[10];
    const float* w2    = (const float*)d_in[11];
    const float* b2    = (const float*)d_in[12];
    const float* ln1g  = (const float*)d_in[13];
    const float* ln1b  = (const float*)d_in[14];
    const float* ln2g  = (const float*)d_in[15];
    const float* ln2b  = (const float*)d_in[16];
    const float* a_att = (const float*)d_in[17];
    const float* a_ff  = (const float*)d_in[18];
    float* out = (float*)d_out;

    float *xln, *qkv, *attn, *x1, *xln2, *ff;
    cudaGetSymbolAddress((void**)&xln,  g_xln);
    cudaGetSymbolAddress((void**)&qkv,  g_qkv);
    cudaGetSymbolAddress((void**)&attn, g_attn);
    cudaGetSymbolAddress((void**)&x1,   g_x1);
    cudaGetSymbolAddress((void**)&xln2, g_xln2);
    cudaGetSymbolAddress((void**)&ff,   g_ff);

    cudaFuncSetAttribute(gemm_mma<0,3>, cudaFuncAttributeMaxDynamicSharedMemorySize, GSMEM_DYN);
    cudaFuncSetAttribute(gemm_mma<1,1>, cudaFuncAttributeMaxDynamicSharedMemorySize, GSMEM_DYN);
    cudaFuncSetAttribute(gemm_mma<2,1>, cudaFuncAttributeMaxDynamicSharedMemorySize, GSMEM_DYN);
    cudaFuncSetAttribute(attn_mma,      cudaFuncAttributeMaxDynamicSharedMemorySize, AT_SMEM);

    // 1) LN1
    ln_kernel<<<NTOK, 256>>>(x, ln1g, ln1b, xln);
    // 2) fused QKV GEMM (per-block weight select, no transposes)
    gemm_mma<0,3><<<dim3(QKV_LD / GBN, NTOK / GBM), 256, GSMEM_DYN>>>(
        xln, wq, wk, wv, bq, bk, bv, nullptr, nullptr, qkv,
        NTOK, QKV_LD, EMB, EMB);
    // 3) causal attention (tf32 mma flash, BQ=128, double-buffered)
    attn_mma<<<dim3(SEQ / 128, BATCH * NHEAD), 256, AT_SMEM>>>(qkv, attn);
    // 4) O proj + residual
    gemm_mma<2,1><<<dim3(EMB / GBN, NTOK / GBM), 256, GSMEM_DYN>>>(
        attn, wo, nullptr, nullptr, bo, nullptr, nullptr, x, a_att, x1,
        NTOK, EMB, EMB, EMB);
    // 5) LN2
    ln_kernel<<<NTOK, 256>>>(x1, ln2g, ln2b, xln2);
    // 6) FF1 + GELU
    gemm_mma<1,1><<<dim3(FFD / GBN, NTOK / GBM), 256, GSMEM_DYN>>>(
        xln2, w1, nullptr, nullptr, b1, nullptr, nullptr, nullptr, nullptr, ff,
        NTOK, FFD, EMB, FFD);
    // 7) FF2 + residual -> out
    gemm_mma<2,1><<<dim3(EMB / GBN, NTOK / GBM), 256, GSMEM_DYN>>>(
        ff, w2, nullptr, nullptr, b2, nullptr, nullptr, x1, a_ff, out,
        NTOK, EMB, FFD, EMB);
}

// round 9
// speedup vs baseline: 4.6946x; 1.0132x over previous
#include <cuda_runtime.h>
#include <math.h>
#include <stdint.h>

#define NTOK 4096      // B*T
#define EMB  1024
#define FFD  4096
#define BATCH 2
#define SEQ  2048
#define NHEAD 16
#define HDIM 64
#define LN_EPS 1e-5f
#define QKV_LD 3072

// ---------------- scratch (device globals; no allocations allowed) ----------
__device__ float g_xln [NTOK * EMB];
__device__ float g_qkv [NTOK * QKV_LD];
__device__ float g_attn[NTOK * EMB];
__device__ float g_x1  [NTOK * EMB];
__device__ float g_xln2[NTOK * EMB];
__device__ float g_ff  [NTOK * FFD];

// ---------------- helpers ----------------------------------------------------
__device__ __forceinline__ uint32_t sm_u32(const void* p) {
    return (uint32_t)__cvta_generic_to_shared(p);
}
__device__ __forceinline__ void cp_async16(uint32_t smem, const void* gptr) {
    asm volatile("cp.async.cg.shared.global [%0], [%1], 16;"
                 :: "r"(smem), "l"(__cvta_generic_to_global(gptr)) : "memory");
}
__device__ __forceinline__ void cp_commit() {
    asm volatile("cp.async.commit_group;" ::: "memory");
}
template<int N>
__device__ __forceinline__ void cp_wait() {
    asm volatile("cp.async.wait_group %0;" :: "n"(N) : "memory");
}
__device__ __forceinline__ void mma_tf32(float* c, const uint32_t* a, const uint32_t* b) {
    asm volatile(
        "mma.sync.aligned.m16n8k8.row.col.f32.tf32.tf32.f32 "
        "{%0,%1,%2,%3}, {%4,%5,%6,%7}, {%8,%9}, {%0,%1,%2,%3};"
        : "+f"(c[0]), "+f"(c[1]), "+f"(c[2]), "+f"(c[3])
        : "r"(a[0]), "r"(a[1]), "r"(a[2]), "r"(a[3]), "r"(b[0]), "r"(b[1]));
}
__device__ __forceinline__ void ldsm_x4(uint32_t* r, uint32_t addr) {
    asm volatile("ldmatrix.sync.aligned.m8n8.x4.shared.b16 {%0,%1,%2,%3}, [%4];"
                 : "=r"(r[0]), "=r"(r[1]), "=r"(r[2]), "=r"(r[3]) : "r"(addr));
}
__device__ __forceinline__ float gelu_exact(float c) {
    return 0.5f * c * (1.0f + erff(c * 0.70710678118654752f));
}

// ---------------- LayerNorm --------------------------------------------------
__global__ __launch_bounds__(256) void ln_kernel(
    const float* __restrict__ x, const float* __restrict__ g,
    const float* __restrict__ b, float* __restrict__ y)
{
    int row = blockIdx.x;
    int tid = threadIdx.x;
    const float* xr = x + row * EMB;
    float4 v = *(const float4*)&xr[tid * 4];
    float s  = v.x + v.y + v.z + v.w;
    float ss = v.x*v.x + v.y*v.y + v.z*v.z + v.w*v.w;

    #pragma unroll
    for (int off = 16; off > 0; off >>= 1) {
        s  += __shfl_down_sync(0xffffffffu, s,  off);
        ss += __shfl_down_sync(0xffffffffu, ss, off);
    }
    __shared__ float red_s[8], red_ss[8];
    int wid = tid >> 5, lid = tid & 31;
    if (lid == 0) { red_s[wid] = s; red_ss[wid] = ss; }
    __syncthreads();
    if (wid == 0) {
        float a  = (lid < 8) ? red_s[lid]  : 0.f;
        float a2 = (lid < 8) ? red_ss[lid] : 0.f;
        #pragma unroll
        for (int off = 4; off > 0; off >>= 1) {
            a  += __shfl_down_sync(0xffffffffu, a,  off);
            a2 += __shfl_down_sync(0xffffffffu, a2, off);
        }
        if (lid == 0) { red_s[0] = a; red_ss[0] = a2; }
    }
    __syncthreads();
    float mu  = red_s[0] * (1.0f / EMB);
    float var = red_ss[0] * (1.0f / EMB) - mu * mu;
    float rs  = rsqrtf(var + LN_EPS);

    float4 gv = *(const float4*)&g[tid * 4];
    float4 bv = *(const float4*)&b[tid * 4];
    float4 o;
    o.x = (v.x - mu) * rs * gv.x + bv.x;
    o.y = (v.y - mu) * rs * gv.y + bv.y;
    o.z = (v.z - mu) * rs * gv.z + bv.z;
    o.w = (v.w - mu) * rs * gv.w + bv.w;
    *(float4*)&y[row * EMB + tid * 4] = o;
}

// ---------------- tf32 mma.sync GEMM, ldmatrix A fragments -------------------
// C[M,N] = epilogue(A[M,K] @ W[K,N] + bias)
// MODE 0: +bias   MODE 1: gelu(+bias)   MODE 2: res + alpha*(+bias)
// NSEL 3: select W/bias from {0,1,2} by output column block (fused QKV)
#define GBM 128
#define GBN 128
#define GBK 32
#define APITCH 36
#define BPITCH 136                         // 136 mod 32 == 8 -> conflict-free frags
#define ABYTES (GBM * APITCH * 4)          // 18432
#define BBYTES (GBK * BPITCH * 4)          // 17408
#define STAGE_BYTES (ABYTES + BBYTES)      // 35840
#define GSTAGES 3
#define GSMEM_DYN (GSTAGES * STAGE_BYTES)  // 107520

template<int MODE, int NSEL>
__global__ __launch_bounds__(256, 2) void gemm_mma(
    const float* __restrict__ A,
    const float* __restrict__ W0, const float* __restrict__ W1,
    const float* __restrict__ W2,
    const float* __restrict__ bias0, const float* __restrict__ bias1,
    const float* __restrict__ bias2,
    const float* __restrict__ res, const float* __restrict__ alpha_p,
    float* __restrict__ C, int M, int N, int K, int Nw)
{
    extern __shared__ char dynsm[];
    int tid = threadIdx.x, wid = tid >> 5, lid = tid & 31;
    int gid = lid >> 2, tg = lid & 3;
    int wm = (wid & 1) * 64, wn = (wid >> 1) * 32;   // warp tile 64x32
    int bm = blockIdx.y * GBM, bn = blockIdx.x * GBN;

    const float* W = W0;
    const float* bias = bias0;
    int bnw = bn;
    if (NSEL == 3) {
        int sel = bn / Nw;
        W    = (sel == 0) ? W0 : ((sel == 1) ? W1 : W2);
        bias = (sel == 0) ? bias0 : ((sel == 1) ? bias1 : bias2);
        bnw  = bn - sel * Nw;
    }

    // ldmatrix lane address offsets for A (bytes, within a stage's As)
    uint32_t a_lane_off[4];
    {
        int t = lid >> 3, l7 = lid & 7;
        int arow = wm + (t & 1) * 8 + l7;
        int acol = (t >> 1) * 4;
        #pragma unroll
        for (int mf = 0; mf < 4; mf++)
            a_lane_off[mf] = (uint32_t)(((arow + mf * 16) * APITCH + acol) * 4);
    }

    float acc[4][4][4];
    #pragma unroll
    for (int mf = 0; mf < 4; mf++)
        #pragma unroll
        for (int nf = 0; nf < 4; nf++)
            #pragma unroll
            for (int i = 0; i < 4; i++) acc[mf][nf][i] = 0.f;

    auto load_stage = [&](int s) {
        char* base = dynsm + (s % GSTAGES) * STAGE_BYTES;
        float* As = (float*)base;
        float* Bs = (float*)(base + ABYTES);
        const float* Ag = A + (size_t)bm * K + s * GBK;
        const float* Wg = W + (size_t)(s * GBK) * Nw + bnw;
        #pragma unroll
        for (int i = 0; i < 4; i++) {      // A: 128 rows x 8 x16B chunks
            int idx = tid + i * 256;
            int r = idx >> 3, c = idx & 7;
            cp_async16(sm_u32(As + r * APITCH + c * 4), Ag + (size_t)r * K + c * 4);
        }
        #pragma unroll
        for (int i = 0; i < 4; i++) {      // B: 32 k-rows x 32 x16B chunks
            int idx = tid + i * 256;
            int r = idx >> 5, c = idx & 31;
            cp_async16(sm_u32(Bs + r * BPITCH + c * 4), Wg + (size_t)r * Nw + c * 4);
        }
    };

    load_stage(0); cp_commit();
    load_stage(1); cp_commit();

    int nst = K / GBK;
    for (int s = 0; s < nst; s++) {
        cp_wait<1>();
        __syncthreads();
        if (s + 2 < nst) load_stage(s + 2);
        cp_commit();

        char* base = dynsm + (s % GSTAGES) * STAGE_BYTES;
        uint32_t as_u32 = sm_u32(base);
        const float* Bs = (const float*)(base + ABYTES);

        #pragma unroll
        for (int ks = 0; ks < 4; ks++) {
            int k0 = ks * 8;
            uint32_t af[4][4], bf[4][2];
            #pragma unroll
            for (int mf = 0; mf < 4; mf++)
                ldsm_x4(af[mf], as_u32 + a_lane_off[mf] + (uint32_t)(k0 * 4));
            #pragma unroll
            for (int nf = 0; nf < 4; nf++) {
                const float* p = Bs + (k0 + tg) * BPITCH + wn + nf * 8 + gid;
                bf[nf][0] = *(const uint32_t*)(p);
                bf[nf][1] = *(const uint32_t*)(p + 4 * BPITCH);
            }
            #pragma unroll
            for (int mf = 0; mf < 4; mf++)
                #pragma unroll
                for (int nf = 0; nf < 4; nf++)
                    mma_tf32(acc[mf][nf], af[mf], bf[nf]);
        }
    }

    float alpha = (MODE == 2) ? *alpha_p : 1.0f;
    #pragma unroll
    for (int mf = 0; mf < 4; mf++) {
        int r0 = bm + wm + mf * 16 + gid;
        #pragma unroll
        for (int nf = 0; nf < 4; nf++) {
            int loc = wn + nf * 8 + 2 * tg;
            int col = bn + loc;
            float2 bv = *(const float2*)&bias[bnw + loc];
            float v0 = acc[mf][nf][0] + bv.x;
            float v1 = acc[mf][nf][1] + bv.y;
            float v2 = acc[mf][nf][2] + bv.x;
            float v3 = acc[mf][nf][3] + bv.y;
            if (MODE == 1) {
                v0 = gelu_exact(v0); v1 = gelu_exact(v1);
                v2 = gelu_exact(v2); v3 = gelu_exact(v3);
            }
            if (MODE == 2) {
                float2 ra = *(const float2*)&res[(size_t)r0 * N + col];
                float2 rb = *(const float2*)&res[(size_t)(r0 + 8) * N + col];
                v0 = ra.x + alpha * v0; v1 = ra.y + alpha * v1;
                v2 = rb.x + alpha * v2; v3 = rb.y + alpha * v3;
            }
            *(float2*)&C[(size_t)r0 * N + col]       = make_float2(v0, v1);
            *(float2*)&C[(size_t)(r0 + 8) * N + col] = make_float2(v2, v3);
        }
    }
}

// ---------------- tf32 mma flash attention (BQ=128, ldmatrix frags) ----------
// 8 warps (16 q-rows each), BK=64 keys per tile.
#define ATP 68
#define AT_TILE (64 * ATP)                  // floats per K or V tile
#define AT_PSH  (4 * AT_TILE)               // after 2 x (K+V) buffers
#define AT_SMEM ((4 * AT_TILE + 128 * ATP) * 4)   // 104448 B

__global__ __launch_bounds__(256) void attn_mma(
    const float* __restrict__ QKV, float* __restrict__ O)
{
    extern __shared__ float ash[];
    float* psh = ash + AT_PSH;              // [128][68]
    uint32_t ash_u32 = sm_u32(ash);
    uint32_t psh_u32 = sm_u32(psh);

    int qt = gridDim.x - 1 - blockIdx.x;     // long blocks first
    int bh = blockIdx.y;
    int b  = bh >> 4, h = bh & 15;
    int tid = threadIdx.x, wid = tid >> 5, lid = tid & 31;
    int gid = lid >> 2, tg = lid & 3;
    int wm = wid * 16;
    int qb = qt * 128;
    const float scale = 0.125f;

    // per-lane ldmatrix offsets (bytes)
    int l7 = lid & 7;
    // K-frag (B-op): tiles = (n-half, k-half); row = half16*8+l7, col k4
    uint32_t k_lane_off = (uint32_t)((((lid >> 4) * 8 + l7) * ATP + ((lid >> 3) & 1) * 4) * 4);
    // P-frag (A-op): t = lid>>3: (t&1)->+8 rows, (t>>1)->+4 k
    uint32_t p_lane_off = (uint32_t)(((wm + ((lid >> 3) & 1) * 8 + l7) * ATP + (lid >> 4) * 4) * 4);

    auto load_tile = [&](int kt, int buf) {
        float* kb = ash + buf * 2 * AT_TILE;
        float* vb = kb + AT_TILE;
        #pragma unroll
        for (int i = 0; i < 4; i++) {
            int idx = tid + i * 256;
            int r = idx >> 4, c4 = (idx & 15) * 4;
            const float* src = &QKV[(size_t)(b * SEQ + kt * 64 + r) * QKV_LD + h * HDIM + c4];
            cp_async16(sm_u32(kb + r * ATP + c4), src + EMB);
            cp_async16(sm_u32(vb + r * ATP + c4), src + 2 * EMB);
        }
    };

    // Q fragments for this warp's 16 rows (held for whole kernel)
    uint32_t qf[8][4];
    {
        const float* q0 = &QKV[(size_t)(b * SEQ + qb + wm + gid) * QKV_LD + h * HDIM];
        const float* q8 = q0 + 8 * QKV_LD;
        #pragma unroll
        for (int ks = 0; ks < 8; ks++) {
            qf[ks][0] = *(const uint32_t*)(q0 + ks * 8 + tg);
            qf[ks][1] = *(const uint32_t*)(q8 + ks * 8 + tg);
            qf[ks][2] = *(const uint32_t*)(q0 + ks * 8 + tg + 4);
            qf[ks][3] = *(const uint32_t*)(q8 + ks * 8 + tg + 4);
        }
    }

    float oacc[8][4];
    #pragma unroll
    for (int nf = 0; nf < 8; nf++)
        #pragma unroll
        for (int i = 0; i < 4; i++) oacc[nf][i] = 0.f;
    float om0 = -INFINITY, om1 = -INFINITY, ol0 = 0.f, ol1 = 0.f;

    int r0 = qb + wm + gid, r1 = r0 + 8;
    int nkt = 2 * qt + 2;

    load_tile(0, 0); cp_commit();

    for (int kt = 0; kt < nkt; kt++) {
        if (kt + 1 < nkt) load_tile(kt + 1, (kt + 1) & 1);
        cp_commit();
        cp_wait<1>();
        __syncthreads();

        uint32_t ksh_u32 = ash_u32 + (uint32_t)((kt & 1) * 2 * AT_TILE) * 4u;
        const float* vsh = ash + (kt & 1) * 2 * AT_TILE + AT_TILE;

        // ---- S = Q @ K^T (K frags via ldmatrix.x4: 2 nf per instr) ----
        float sacc[8][4];
        #pragma unroll
        for (int nf = 0; nf < 8; nf++)
            #pragma unroll
            for (int i = 0; i < 4; i++) sacc[nf][i] = 0.f;
        #pragma unroll
        for (int ks = 0; ks < 8; ks++) {
            uint32_t bf[8][2];
            #pragma unroll
            for (int np = 0; np < 4; np++) {
                uint32_t r[4];
                ldsm_x4(r, ksh_u32 + k_lane_off +
                           (uint32_t)((np * 16 * ATP + ks * 8) * 4));
                bf[2*np][0]   = r[0]; bf[2*np][1]   = r[1];
                bf[2*np+1][0] = r[2]; bf[2*np+1][1] = r[3];
            }
            #pragma unroll
            for (int nf = 0; nf < 8; nf++)
                mma_tf32(sacc[nf], qf[ks], bf[nf]);
        }

        // ---- scale + causal mask + row max ----
        bool diag = (kt >= 2 * qt);
        float tmax0 = -INFINITY, tmax1 = -INFINITY;
        #pragma unroll
        for (int nf = 0; nf < 8; nf++) {
            int c0 = kt * 64 + nf * 8 + 2 * tg;
            #pragma unroll
            for (int c = 0; c < 2; c++) {
                float s0 = sacc[nf][c] * scale;
                float s1 = sacc[nf][2 + c] * scale;
                if (diag && c0 + c > r0) s0 = -INFINITY;
                if (diag && c0 + c > r1) s1 = -INFINITY;
                sacc[nf][c] = s0; sacc[nf][2 + c] = s1;
                tmax0 = fmaxf(tmax0, s0);
                tmax1 = fmaxf(tmax1, s1);
            }
        }
        tmax0 = fmaxf(tmax0, __shfl_xor_sync(0xffffffffu, tmax0, 1));
        tmax0 = fmaxf(tmax0, __shfl_xor_sync(0xffffffffu, tmax0, 2));
        tmax1 = fmaxf(tmax1, __shfl_xor_sync(0xffffffffu, tmax1, 1));
        tmax1 = fmaxf(tmax1, __shfl_xor_sync(0xffffffffu, tmax1, 2));

        float mn0 = fmaxf(om0, tmax0), mn1 = fmaxf(om1, tmax1);
        float corr0 = __expf(om0 - mn0), corr1 = __expf(om1 - mn1);
        om0 = mn0; om1 = mn1;

        float ps0 = 0.f, ps1 = 0.f;
        #pragma unroll
        for (int nf = 0; nf < 8; nf++) {
            #pragma unroll
            for (int c = 0; c < 2; c++) {
                float e0 = __expf(sacc[nf][c] - mn0);
                float e1 = __expf(sacc[nf][2 + c] - mn1);
                sacc[nf][c] = e0; sacc[nf][2 + c] = e1;
                ps0 += e0; ps1 += e1;
            }
        }
        ps0 += __shfl_xor_sync(0xffffffffu, ps0, 1);
        ps0 += __shfl_xor_sync(0xffffffffu, ps0, 2);
        ps1 += __shfl_xor_sync(0xffffffffu, ps1, 1);
        ps1 += __shfl_xor_sync(0xffffffffu, ps1, 2);
        ol0 = ol0 * corr0 + ps0;
        ol1 = ol1 * corr1 + ps1;

        #pragma unroll
        for (int nf = 0; nf < 8; nf++) {
            oacc[nf][0] *= corr0; oacc[nf][1] *= corr0;
            oacc[nf][2] *= corr1; oacc[nf][3] *= corr1;
        }

        // ---- P -> smem (warp-private rows) ----
        #pragma unroll
        for (int nf = 0; nf < 8; nf++) {
            int col = nf * 8 + 2 * tg;
            *(float2*)&psh[(wm + gid) * ATP + col]     = make_float2(sacc[nf][0], sacc[nf][1]);
            *(float2*)&psh[(wm + gid + 8) * ATP + col] = make_float2(sacc[nf][2], sacc[nf][3]);
        }
        __syncwarp();

        // ---- O += P @ V (P frags via ldmatrix; V scalar, conflict-free) ----
        #pragma unroll
        for (int ks = 0; ks < 8; ks++) {
            uint32_t af[4];
            ldsm_x4(af, psh_u32 + p_lane_off + (uint32_t)(ks * 8 * 4));
            uint32_t bf[8][2];
            #pragma unroll
            for (int nf = 0; nf < 8; nf++) {
                const float* p = &vsh[(ks * 8 + tg) * ATP + nf * 8 + gid];
                bf[nf][0] = *(const uint32_t*)(p);
                bf[nf][1] = *(const uint32_t*)(p + 4 * ATP);
            }
            #pragma unroll
            for (int nf = 0; nf < 8; nf++)
                mma_tf32(oacc[nf], af, bf[nf]);
        }
        __syncthreads();
    }

    // ---- epilogue ----
    float inv0 = 1.0f / ol0, inv1 = 1.0f / ol1;
    float* o0 = &O[(size_t)(b * SEQ + r0) * EMB + h * HDIM];
    float* o8 = o0 + 8 * EMB;
    #pragma unroll
    for (int nf = 0; nf < 8; nf++) {
        int d = nf * 8 + 2 * tg;
        *(float2*)&o0[d] = make_float2(oacc[nf][0] * inv0, oacc[nf][1] * inv0);
        *(float2*)&o8[d] = make_float2(oacc[nf][2] * inv1, oacc[nf][3] * inv1);
    }
}

// ---------------- launch ----------------------------------------------------
extern "C" void kernel_launch(void* const* d_in, const int* in_sizes, int n_in,
                              void* d_out, int out_size)
{
    (void)in_sizes; (void)n_in; (void)out_size;
    const float* x     = (const float*)d_in[0];
    const float* wq    = (const float*)d_in[1];
    const float* bq    = (const float*)d_in[2];
    const float* wk    = (const float*)d_in[3];
    const float* bk    = (const float*)d_in[4];
    const float* wv    = (const float*)d_in[5];
    const float* bv    = (const float*)d_in[6];
    const float* wo    = (const float*)d_in[7];
    const float* bo    = (const float*)d_in[8];
    const float* w1    = (const float*)d_in[9];
    const float* b1    = (const float*)d_in[10];
    const float* w2    = (const float*)d_in[11];
    const float* b2    = (const float*)d_in[12];
    const float* ln1g  = (const float*)d_in[13];
    const float* ln1b  = (const float*)d_in[14];
    const float* ln2g  = (const float*)d_in[15];
    const float* ln2b  = (const float*)d_in[16];
    const float* a_att = (const float*)d_in[17];
    const float* a_ff  = (const float*)d_in[18];
    float* out = (float*)d_out;

    float *xln, *qkv, *attn, *x1, *xln2, *ff;
    cudaGetSymbolAddress((void**)&xln,  g_xln);
    cudaGetSymbolAddress((void**)&qkv,  g_qkv);
    cudaGetSymbolAddress((void**)&attn, g_attn);
    cudaGetSymbolAddress((void**)&x1,   g_x1);
    cudaGetSymbolAddress((void**)&xln2, g_xln2);
    cudaGetSymbolAddress((void**)&ff,   g_ff);

    cudaFuncSetAttribute(gemm_mma<0,3>, cudaFuncAttributeMaxDynamicSharedMemorySize, GSMEM_DYN);
    cudaFuncSetAttribute(gemm_mma<1,1>, cudaFuncAttributeMaxDynamicSharedMemorySize, GSMEM_DYN);
    cudaFuncSetAttribute(gemm_mma<2,1>, cudaFuncAttributeMaxDynamicSharedMemorySize, GSMEM_DYN);
    cudaFuncSetAttribute(attn_mma,      cudaFuncAttributeMaxDynamicSharedMemorySize, AT_SMEM);

    // 1) LN1
    ln_kernel<<<NTOK, 256>>>(x, ln1g, ln1b, xln);
    // 2) fused QKV GEMM (per-block weight select, no transposes)
    gemm_mma<0,3><<<dim3(QKV_LD / GBN, NTOK / GBM), 256, GSMEM_DYN>>>(
        xln, wq, wk, wv, bq, bk, bv, nullptr, nullptr, qkv,
        NTOK, QKV_LD, EMB, EMB);
    // 3) causal attention (tf32 mma flash, ldmatrix fragments)
    attn_mma<<<dim3(SEQ / 128, BATCH * NHEAD), 256, AT_SMEM>>>(qkv, attn);
    // 4) O proj + residual
    gemm_mma<2,1><<<dim3(EMB / GBN, NTOK / GBM), 256, GSMEM_DYN>>>(
        attn, wo, nullptr, nullptr, bo, nullptr, nullptr, x, a_att, x1,
        NTOK, EMB, EMB, EMB);
    // 5) LN2
    ln_kernel<<<NTOK, 256>>>(x1, ln2g, ln2b, xln2);
    // 6) FF1 + GELU
    gemm_mma<1,1><<<dim3(FFD / GBN, NTOK / GBM), 256, GSMEM_DYN>>>(
        xln2, w1, nullptr, nullptr, b1, nullptr, nullptr, nullptr, nullptr, ff,
        NTOK, FFD, EMB, FFD);
    // 7) FF2 + residual -> out
    gemm_mma<2,1><<<dim3(EMB / GBN, NTOK / GBM), 256, GSMEM_DYN>>>(
        ff, w2, nullptr, nullptr, b2, nullptr, nullptr, x1, a_ff, out,
        NTOK, EMB, FFD, EMB);
}

// round 11
// speedup vs baseline: 5.4976x; 1.1710x over previous
#include <cuda_runtime.h>
#include <cuda_fp16.h>
#include <math.h>
#include <stdint.h>

#define NTOK 4096      // B*T
#define EMB  1024
#define FFD  4096
#define BATCH 2
#define SEQ  2048
#define NHEAD 16
#define HDIM 64
#define LN_EPS 1e-5f
#define QKV_LD 3072

// ---------------- scratch (device globals; no allocations allowed) ----------
__device__ __half g_xln [NTOK * EMB];
__device__ __half g_qkv [NTOK * QKV_LD];
__device__ __half g_attn[NTOK * EMB];
__device__ float  g_x1  [NTOK * EMB];
__device__ __half g_xln2[NTOK * EMB];
__device__ __half g_ff  [NTOK * FFD];
// half weights
__device__ __half g_wqh[EMB * EMB];
__device__ __half g_wkh[EMB * EMB];
__device__ __half g_wvh[EMB * EMB];
__device__ __half g_woh[EMB * EMB];
__device__ __half g_w1h[EMB * FFD];
__device__ __half g_w2h[FFD * EMB];

// ---------------- helpers ----------------------------------------------------
__device__ __forceinline__ uint32_t sm_u32(const void* p) {
    return (uint32_t)__cvta_generic_to_shared(p);
}
__device__ __forceinline__ void cp_async16(uint32_t smem, const void* gptr) {
    asm volatile("cp.async.cg.shared.global [%0], [%1], 16;"
                 :: "r"(smem), "l"(__cvta_generic_to_global(gptr)) : "memory");
}
__device__ __forceinline__ void cp_commit() {
    asm volatile("cp.async.commit_group;" ::: "memory");
}
template<int N>
__device__ __forceinline__ void cp_wait() {
    asm volatile("cp.async.wait_group %0;" :: "n"(N) : "memory");
}
// fp16 mma with fp32 accumulate: D = A(16x16) * B(16x8) + D
__device__ __forceinline__ void mma_f16(float* c, const uint32_t* a, const uint32_t* b) {
    asm volatile(
        "mma.sync.aligned.m16n8k16.row.col.f32.f16.f16.f32 "
        "{%0,%1,%2,%3}, {%4,%5,%6,%7}, {%8,%9}, {%0,%1,%2,%3};"
        : "+f"(c[0]), "+f"(c[1]), "+f"(c[2]), "+f"(c[3])
        : "r"(a[0]), "r"(a[1]), "r"(a[2]), "r"(a[3]), "r"(b[0]), "r"(b[1]));
}
__device__ __forceinline__ void ldsm_x4(uint32_t* r, uint32_t addr) {
    asm volatile("ldmatrix.sync.aligned.m8n8.x4.shared.b16 {%0,%1,%2,%3}, [%4];"
                 : "=r"(r[0]), "=r"(r[1]), "=r"(r[2]), "=r"(r[3]) : "r"(addr));
}
__device__ __forceinline__ void ldsm_x4t(uint32_t* r, uint32_t addr) {
    asm volatile("ldmatrix.sync.aligned.m8n8.x4.trans.shared.b16 {%0,%1,%2,%3}, [%4];"
                 : "=r"(r[0]), "=r"(r[1]), "=r"(r[2]), "=r"(r[3]) : "r"(addr));
}
__device__ __forceinline__ float gelu_exact(float c) {
    return 0.5f * c * (1.0f + erff(c * 0.70710678118654752f));
}

// ---------------- fp32 -> fp16 convert ---------------------------------------
__global__ __launch_bounds__(256) void f2h_kernel(
    const float* __restrict__ s, __half* __restrict__ d, int n)
{
    int i = (blockIdx.x * 256 + threadIdx.x) * 4;
    if (i < n) {
        float4 v = *(const float4*)&s[i];
        *(half2*)&d[i]     = __floats2half2_rn(v.x, v.y);
        *(half2*)&d[i + 2] = __floats2half2_rn(v.z, v.w);
    }
}

// ---------------- LayerNorm (fp32 in, fp16 out) ------------------------------
__global__ __launch_bounds__(256) void ln_kernel(
    const float* __restrict__ x, const float* __restrict__ g,
    const float* __restrict__ b, __half* __restrict__ y)
{
    int row = blockIdx.x;
    int tid = threadIdx.x;
    const float* xr = x + row * EMB;
    float4 v = *(const float4*)&xr[tid * 4];
    float s  = v.x + v.y + v.z + v.w;
    float ss = v.x*v.x + v.y*v.y + v.z*v.z + v.w*v.w;

    #pragma unroll
    for (int off = 16; off > 0; off >>= 1) {
        s  += __shfl_down_sync(0xffffffffu, s,  off);
        ss += __shfl_down_sync(0xffffffffu, ss, off);
    }
    __shared__ float red_s[8], red_ss[8];
    int wid = tid >> 5, lid = tid & 31;
    if (lid == 0) { red_s[wid] = s; red_ss[wid] = ss; }
    __syncthreads();
    if (wid == 0) {
        float a  = (lid < 8) ? red_s[lid]  : 0.f;
        float a2 = (lid < 8) ? red_ss[lid] : 0.f;
        #pragma unroll
        for (int off = 4; off > 0; off >>= 1) {
            a  += __shfl_down_sync(0xffffffffu, a,  off);
            a2 += __shfl_down_sync(0xffffffffu, a2, off);
        }
        if (lid == 0) { red_s[0] = a; red_ss[0] = a2; }
    }
    __syncthreads();
    float mu  = red_s[0] * (1.0f / EMB);
    float var = red_ss[0] * (1.0f / EMB) - mu * mu;
    float rs  = rsqrtf(var + LN_EPS);

    float4 gv = *(const float4*)&g[tid * 4];
    float4 bv = *(const float4*)&b[tid * 4];
    float o0 = (v.x - mu) * rs * gv.x + bv.x;
    float o1 = (v.y - mu) * rs * gv.y + bv.y;
    float o2 = (v.z - mu) * rs * gv.z + bv.z;
    float o3 = (v.w - mu) * rs * gv.w + bv.w;
    __half* yp = y + row * EMB + tid * 4;
    *(half2*)(yp)     = __floats2half2_rn(o0, o1);
    *(half2*)(yp + 2) = __floats2half2_rn(o2, o3);
}

// ---------------- fp16 mma.sync GEMM -----------------------------------------
// C[M,N] = epilogue(A_half[M,K] @ W_half[K,N] + bias_f32)
// MODE 0: +bias -> half   MODE 1: gelu(+bias) -> half   MODE 2: res + alpha*() -> float
// NSEL 3: select W/bias by output column block (fused QKV)
#define GBM 128
#define GBN 128
#define GBK 32
#define APITCH 40                          // halves; 80B row -> ldmatrix conflict-free
#define BPITCH 136                         // halves; 272B row
#define ABYTES (GBM * APITCH * 2)          // 10240
#define BBYTES (GBK * BPITCH * 2)          // 8704
#define STAGE_BYTES (ABYTES + BBYTES)      // 18944
#define GSTAGES 3
#define GSMEM_DYN (GSTAGES * STAGE_BYTES)  // 56832

template<int MODE, int NSEL>
__global__ __launch_bounds__(256, 2) void gemm_mma(
    const __half* __restrict__ A,
    const __half* __restrict__ W0, const __half* __restrict__ W1,
    const __half* __restrict__ W2,
    const float* __restrict__ bias0, const float* __restrict__ bias1,
    const float* __restrict__ bias2,
    const float* __restrict__ res, const float* __restrict__ alpha_p,
    void* __restrict__ Cv, int M, int N, int K, int Nw)
{
    extern __shared__ char dynsm[];
    int tid = threadIdx.x, wid = tid >> 5, lid = tid & 31;
    int gid = lid >> 2, tg = lid & 3;
    int wm = (wid & 1) * 64, wn = (wid >> 1) * 32;   // warp tile 64x32
    int bm = blockIdx.y * GBM, bn = blockIdx.x * GBN;

    const __half* W = W0;
    const float* bias = bias0;
    int bnw = bn;
    if (NSEL == 3) {
        int sel = bn / Nw;
        W    = (sel == 0) ? W0 : ((sel == 1) ? W1 : W2);
        bias = (sel == 0) ? bias0 : ((sel == 1) ? bias1 : bias2);
        bnw  = bn - sel * Nw;
    }

    int l7 = lid & 7, t8 = lid >> 3;
    // A frags: tile t: row=(t&1)*8+l7, kcol=(t>>1)*8 (halves)
    uint32_t a_lane_off[4];
    #pragma unroll
    for (int mf = 0; mf < 4; mf++)
        a_lane_off[mf] = (uint32_t)(((wm + mf * 16 + (t8 & 1) * 8 + l7) * APITCH
                                     + (t8 >> 1) * 8) * 2);
    // B frags (trans): tile t: krow=(t&1)*8+l7, ncol=(t>>1)*8
    uint32_t b_lane_off = (uint32_t)((((t8 & 1) * 8 + l7) * BPITCH + (t8 >> 1) * 8) * 2);

    float acc[4][4][4];
    #pragma unroll
    for (int mf = 0; mf < 4; mf++)
        #pragma unroll
        for (int nf = 0; nf < 4; nf++)
            #pragma unroll
            for (int i = 0; i < 4; i++) acc[mf][nf][i] = 0.f;

    auto load_stage = [&](int s) {
        char* base = dynsm + (s % GSTAGES) * STAGE_BYTES;
        __half* As = (__half*)base;
        __half* Bs = (__half*)(base + ABYTES);
        const __half* Ag = A + (size_t)bm * K + s * GBK;
        const __half* Wg = W + (size_t)(s * GBK) * Nw + bnw;
        #pragma unroll
        for (int i = 0; i < 2; i++) {      // A: 128 rows x 4 x16B chunks
            int idx = tid + i * 256;
            int r = idx >> 2, c = idx & 3;
            cp_async16(sm_u32(As + r * APITCH + c * 8), Ag + (size_t)r * K + c * 8);
        }
        #pragma unroll
        for (int i = 0; i < 2; i++) {      // B: 32 k-rows x 16 x16B chunks
            int idx = tid + i * 256;
            int r = idx >> 4, c = idx & 15;
            cp_async16(sm_u32(Bs + r * BPITCH + c * 8), Wg + (size_t)r * Nw + c * 8);
        }
    };

    load_stage(0); cp_commit();
    load_stage(1); cp_commit();

    int nst = K / GBK;
    for (int s = 0; s < nst; s++) {
        cp_wait<1>();
        __syncthreads();
        if (s + 2 < nst) load_stage(s + 2);
        cp_commit();

        char* base = dynsm + (s % GSTAGES) * STAGE_BYTES;
        uint32_t as_u32 = sm_u32(base);
        uint32_t bs_u32 = sm_u32(base + ABYTES);

        #pragma unroll
        for (int ks = 0; ks < 2; ks++) {
            int k0 = ks * 16;
            uint32_t af[4][4], bf[4][2];
            #pragma unroll
            for (int mf = 0; mf < 4; mf++)
                ldsm_x4(af[mf], as_u32 + a_lane_off[mf] + (uint32_t)(k0 * 2));
            #pragma unroll
            for (int nb = 0; nb < 2; nb++) {
                uint32_t r[4];
                ldsm_x4t(r, bs_u32 + b_lane_off +
                            (uint32_t)((k0 * BPITCH + wn + nb * 16) * 2));
                bf[2*nb][0]   = r[0]; bf[2*nb][1]   = r[1];
                bf[2*nb+1][0] = r[2]; bf[2*nb+1][1] = r[3];
            }
            #pragma unroll
            for (int mf = 0; mf < 4; mf++)
                #pragma unroll
                for (int nf = 0; nf < 4; nf++)
                    mma_f16(acc[mf][nf], af[mf], bf[nf]);
        }
    }

    float alpha = (MODE == 2) ? *alpha_p : 1.0f;
    #pragma unroll
    for (int mf = 0; mf < 4; mf++) {
        int r0 = bm + wm + mf * 16 + gid;
        #pragma unroll
        for (int nf = 0; nf < 4; nf++) {
            int loc = wn + nf * 8 + 2 * tg;
            int col = bn + loc;
            float2 bv = *(const float2*)&bias[bnw + loc];
            float v0 = acc[mf][nf][0] + bv.x;
            float v1 = acc[mf][nf][1] + bv.y;
            float v2 = acc[mf][nf][2] + bv.x;
            float v3 = acc[mf][nf][3] + bv.y;
            if (MODE == 1) {
                v0 = gelu_exact(v0); v1 = gelu_exact(v1);
                v2 = gelu_exact(v2); v3 = gelu_exact(v3);
            }
            if (MODE == 2) {
                float* C = (float*)Cv;
                float2 ra = *(const float2*)&res[(size_t)r0 * N + col];
                float2 rb = *(const float2*)&res[(size_t)(r0 + 8) * N + col];
                *(float2*)&C[(size_t)r0 * N + col] =
                    make_float2(ra.x + alpha * v0, ra.y + alpha * v1);
                *(float2*)&C[(size_t)(r0 + 8) * N + col] =
                    make_float2(rb.x + alpha * v2, rb.y + alpha * v3);
            } else {
                __half* C = (__half*)Cv;
                *(half2*)&C[(size_t)r0 * N + col]       = __floats2half2_rn(v0, v1);
                *(half2*)&C[(size_t)(r0 + 8) * N + col] = __floats2half2_rn(v2, v3);
            }
        }
    }
}

// ---------------- fp16 mma flash attention (BQ=128) --------------------------
// 8 warps (16 q-rows each), BK=64 keys per tile; all fragments via ldmatrix.
#define ATP 72                               // halves per row (144B)
#define AT_TILE (64 * ATP)                   // halves per K or V tile
#define AT_PSH  (4 * AT_TILE)                // after 2 x (K+V) buffers
#define AT_SMEM ((4 * AT_TILE + 128 * ATP) * 2)   // 36864 + 18432 = 55296 B

__global__ __launch_bounds__(256) void attn_mma(
    const __half* __restrict__ QKV, __half* __restrict__ O)
{
    extern __shared__ __half ash[];
    __half* psh = ash + AT_PSH;              // [128][72] halves
    uint32_t ash_u32 = sm_u32(ash);
    uint32_t psh_u32 = sm_u32(psh);

    int qt = gridDim.x - 1 - blockIdx.x;     // long blocks first
    int bh = blockIdx.y;
    int b  = bh >> 4, h = bh & 15;
    int tid = threadIdx.x, wid = tid >> 5, lid = tid & 31;
    int gid = lid >> 2, tg = lid & 3;
    int wm = wid * 16;
    int qb = qt * 128;
    const float scale = 0.125f;

    int l7 = lid & 7, t8 = lid >> 3;
    // K frag (B-op, no trans): tile t: nrow=(t>>1 is n-block? see order) ----
    // order: t0=(n0,k0) t1=(n0,k8) t2=(n8,k0) t3=(n8,k8)
    uint32_t k_lane_off = (uint32_t)((((lid >> 4) * 8 + l7) * ATP + ((t8 & 1) * 8)) * 2);
    // V frag (B-op, trans): t0=(k0,n0) t1=(k8,n0) t2=(k0,n8) t3=(k8,n8)
    uint32_t v_lane_off = (uint32_t)((((t8 & 1) * 8 + l7) * ATP + (lid >> 4) * 8) * 2);
    // P frag (A-op): t: row=(t&1)*8+l7, kcol=(t>>1)*8
    uint32_t p_lane_off = (uint32_t)(((wm + (t8 & 1) * 8 + l7) * ATP + (t8 >> 1) * 8) * 2);

    auto load_tile = [&](int kt, int buf) {
        __half* kb = ash + buf * 2 * AT_TILE;
        __half* vb = kb + AT_TILE;
        #pragma unroll
        for (int i = 0; i < 2; i++) {
            int idx = tid + i * 256;
            int r = idx >> 3, c = idx & 7;          // 64 rows x 8 chunks
            const __half* src = &QKV[(size_t)(b * SEQ + kt * 64 + r) * QKV_LD
                                     + h * HDIM + c * 8];
            cp_async16(sm_u32(kb + r * ATP + c * 8), src + EMB);
            cp_async16(sm_u32(vb + r * ATP + c * 8), src + 2 * EMB);
        }
    };

    // Q fragments (A-op, global half, held whole kernel): 4 k16-steps
    uint32_t qf[4][4];
    {
        const __half* q0 = &QKV[(size_t)(b * SEQ + qb + wm + gid) * QKV_LD + h * HDIM];
        const __half* q8 = q0 + 8 * QKV_LD;
        #pragma unroll
        for (int ks = 0; ks < 4; ks++) {
            qf[ks][0] = *(const uint32_t*)(q0 + ks * 16 + 2 * tg);
            qf[ks][1] = *(const uint32_t*)(q8 + ks * 16 + 2 * tg);
            qf[ks][2] = *(const uint32_t*)(q0 + ks * 16 + 8 + 2 * tg);
            qf[ks][3] = *(const uint32_t*)(q8 + ks * 16 + 8 + 2 * tg);
        }
    }

    float oacc[8][4];
    #pragma unroll
    for (int nf = 0; nf < 8; nf++)
        #pragma unroll
        for (int i = 0; i < 4; i++) oacc[nf][i] = 0.f;
    float om0 = -INFINITY, om1 = -INFINITY, ol0 = 0.f, ol1 = 0.f;

    int r0 = qb + wm + gid, r1 = r0 + 8;
    int nkt = 2 * qt + 2;

    load_tile(0, 0); cp_commit();

    for (int kt = 0; kt < nkt; kt++) {
        if (kt + 1 < nkt) load_tile(kt + 1, (kt + 1) & 1);
        cp_commit();
        cp_wait<1>();
        __syncthreads();

        uint32_t ksh_u32 = ash_u32 + (uint32_t)((kt & 1) * 2 * AT_TILE) * 2u;
        uint32_t vsh_u32 = ksh_u32 + (uint32_t)AT_TILE * 2u;

        // ---- S = Q @ K^T ----
        float sacc[8][4];
        #pragma unroll
        for (int nf = 0; nf < 8; nf++)
            #pragma unroll
            for (int i = 0; i < 4; i++) sacc[nf][i] = 0.f;
        #pragma unroll
        for (int ks = 0; ks < 4; ks++) {
            uint32_t bf[8][2];
            #pragma unroll
            for (int np = 0; np < 4; np++) {
                uint32_t r[4];
                ldsm_x4(r, ksh_u32 + k_lane_off +
                           (uint32_t)((np * 16 * ATP + ks * 16) * 2));
                bf[2*np][0]   = r[0]; bf[2*np][1]   = r[1];
                bf[2*np+1][0] = r[2]; bf[2*np+1][1] = r[3];
            }
            #pragma unroll
            for (int nf = 0; nf < 8; nf++)
                mma_f16(sacc[nf], qf[ks], bf[nf]);
        }

        // ---- scale + causal mask + row max ----
        bool diag = (kt >= 2 * qt);
        float tmax0 = -INFINITY, tmax1 = -INFINITY;
        #pragma unroll
        for (int nf = 0; nf < 8; nf++) {
            int c0 = kt * 64 + nf * 8 + 2 * tg;
            #pragma unroll
            for (int c = 0; c < 2; c++) {
                float s0 = sacc[nf][c] * scale;
                float s1 = sacc[nf][2 + c] * scale;
                if (diag && c0 + c > r0) s0 = -INFINITY;
                if (diag && c0 + c > r1) s1 = -INFINITY;
                sacc[nf][c] = s0; sacc[nf][2 + c] = s1;
                tmax0 = fmaxf(tmax0, s0);
                tmax1 = fmaxf(tmax1, s1);
            }
        }
        tmax0 = fmaxf(tmax0, __shfl_xor_sync(0xffffffffu, tmax0, 1));
        tmax0 = fmaxf(tmax0, __shfl_xor_sync(0xffffffffu, tmax0, 2));
        tmax1 = fmaxf(tmax1, __shfl_xor_sync(0xffffffffu, tmax1, 1));
        tmax1 = fmaxf(tmax1, __shfl_xor_sync(0xffffffffu, tmax1, 2));

        float mn0 = fmaxf(om0, tmax0), mn1 = fmaxf(om1, tmax1);
        float corr0 = __expf(om0 - mn0), corr1 = __expf(om1 - mn1);
        om0 = mn0; om1 = mn1;

        float ps0 = 0.f, ps1 = 0.f;
        #pragma unroll
        for (int nf = 0; nf < 8; nf++) {
            #pragma unroll
            for (int c = 0; c < 2; c++) {
                float e0 = __expf(sacc[nf][c] - mn0);
                float e1 = __expf(sacc[nf][2 + c] - mn1);
                sacc[nf][c] = e0; sacc[nf][2 + c] = e1;
                ps0 += e0; ps1 += e1;
            }
        }
        ps0 += __shfl_xor_sync(0xffffffffu, ps0, 1);
        ps0 += __shfl_xor_sync(0xffffffffu, ps0, 2);
        ps1 += __shfl_xor_sync(0xffffffffu, ps1, 1);
        ps1 += __shfl_xor_sync(0xffffffffu, ps1, 2);
        ol0 = ol0 * corr0 + ps0;
        ol1 = ol1 * corr1 + ps1;

        #pragma unroll
        for (int nf = 0; nf < 8; nf++) {
            oacc[nf][0] *= corr0; oacc[nf][1] *= corr0;
            oacc[nf][2] *= corr1; oacc[nf][3] *= corr1;
        }

        // ---- P -> smem as half (warp-private rows) ----
        #pragma unroll
        for (int nf = 0; nf < 8; nf++) {
            int col = nf * 8 + 2 * tg;
            *(half2*)&psh[(wm + gid) * ATP + col]     = __floats2half2_rn(sacc[nf][0], sacc[nf][1]);
            *(half2*)&psh[(wm + gid + 8) * ATP + col] = __floats2half2_rn(sacc[nf][2], sacc[nf][3]);
        }
        __syncwarp();

        // ---- O += P @ V ----
        #pragma unroll
        for (int ks = 0; ks < 4; ks++) {
            uint32_t af[4];
            ldsm_x4(af, psh_u32 + p_lane_off + (uint32_t)(ks * 16 * 2));
            uint32_t bf[8][2];
            #pragma unroll
            for (int nv = 0; nv < 4; nv++) {
                uint32_t r[4];
                ldsm_x4t(r, vsh_u32 + v_lane_off +
                            (uint32_t)((ks * 16 * ATP + nv * 16) * 2));
                bf[2*nv][0]   = r[0]; bf[2*nv][1]   = r[1];
                bf[2*nv+1][0] = r[2]; bf[2*nv+1][1] = r[3];
            }
            #pragma unroll
            for (int nf = 0; nf < 8; nf++)
                mma_f16(oacc[nf], af, bf[nf]);
        }
        __syncthreads();
    }

    // ---- epilogue (half output) ----
    float inv0 = 1.0f / ol0, inv1 = 1.0f / ol1;
    __half* o0 = &O[(size_t)(b * SEQ + r0) * EMB + h * HDIM];
    __half* o8 = o0 + 8 * EMB;
    #pragma unroll
    for (int nf = 0; nf < 8; nf++) {
        int d = nf * 8 + 2 * tg;
        *(half2*)&o0[d] = __floats2half2_rn(oacc[nf][0] * inv0, oacc[nf][1] * inv0);
        *(half2*)&o8[d] = __floats2half2_rn(oacc[nf][2] * inv1, oacc[nf][3] * inv1);
    }
}

// ---------------- launch ----------------------------------------------------
extern "C" void kernel_launch(void* const* d_in, const int* in_sizes, int n_in,
                              void* d_out, int out_size)
{
    (void)in_sizes; (void)n_in; (void)out_size;
    const float* x     = (const float*)d_in[0];
    const float* wq    = (const float*)d_in[1];
    const float* bq    = (const float*)d_in[2];
    const float* wk    = (const float*)d_in[3];
    const float* bk    = (const float*)d_in[4];
    const float* wv    = (const float*)d_in[5];
    const float* bv    = (const float*)d_in[6];
    const float* wo    = (const float*)d_in[7];
    const float* bo    = (const float*)d_in[8];
    const float* w1    = (const float*)d_in[9];
    const float* b1    = (const float*)d_in[10];
    const float* w2    = (const float*)d_in[11];
    const float* b2    = (const float*)d_in[12];
    const float* ln1g  = (const float*)d_in[13];
    const float* ln1b  = (const float*)d_in[14];
    const float* ln2g  = (const float*)d_in[15];
    const float* ln2b  = (const float*)d_in[16];
    const float* a_att = (const float*)d_in[17];
    const float* a_ff  = (const float*)d_in[18];
    float* out = (float*)d_out;

    __half *xln, *qkv, *attn, *xln2, *ff;
    __half *wqh, *wkh, *wvh, *woh, *w1h, *w2h;
    float  *x1;
    cudaGetSymbolAddress((void**)&xln,  g_xln);
    cudaGetSymbolAddress((void**)&qkv,  g_qkv);
    cudaGetSymbolAddress((void**)&attn, g_attn);
    cudaGetSymbolAddress((void**)&x1,   g_x1);
    cudaGetSymbolAddress((void**)&xln2, g_xln2);
    cudaGetSymbolAddress((void**)&ff,   g_ff);
    cudaGetSymbolAddress((void**)&wqh,  g_wqh);
    cudaGetSymbolAddress((void**)&wkh,  g_wkh);
    cudaGetSymbolAddress((void**)&wvh,  g_wvh);
    cudaGetSymbolAddress((void**)&woh,  g_woh);
    cudaGetSymbolAddress((void**)&w1h,  g_w1h);
    cudaGetSymbolAddress((void**)&w2h,  g_w2h);

    cudaFuncSetAttribute(gemm_mma<0,3>, cudaFuncAttributeMaxDynamicSharedMemorySize, GSMEM_DYN);
    cudaFuncSetAttribute(gemm_mma<1,1>, cudaFuncAttributeMaxDynamicSharedMemorySize, GSMEM_DYN);
    cudaFuncSetAttribute(gemm_mma<2,1>, cudaFuncAttributeMaxDynamicSharedMemorySize, GSMEM_DYN);
    cudaFuncSetAttribute(attn_mma,      cudaFuncAttributeMaxDynamicSharedMemorySize, AT_SMEM);

    // 0) weight conversions fp32 -> fp16
    f2h_kernel<<<EMB * EMB / 1024, 256>>>(wq, wqh, EMB * EMB);
    f2h_kernel<<<EMB * EMB / 1024, 256>>>(wk, wkh, EMB * EMB);
    f2h_kernel<<<EMB * EMB / 1024, 256>>>(wv, wvh, EMB * EMB);
    f2h_kernel<<<EMB * EMB / 1024, 256>>>(wo, woh, EMB * EMB);
    f2h_kernel<<<EMB * FFD / 1024, 256>>>(w1, w1h, EMB * FFD);
    f2h_kernel<<<EMB * FFD / 1024, 256>>>(w2, w2h, FFD * EMB);

    // 1) LN1 (fp32 -> fp16)
    ln_kernel<<<NTOK, 256>>>(x, ln1g, ln1b, xln);
    // 2) fused QKV GEMM (fp16 mma)
    gemm_mma<0,3><<<dim3(QKV_LD / GBN, NTOK / GBM), 256, GSMEM_DYN>>>(
        xln, wqh, wkh, wvh, bq, bk, bv, nullptr, nullptr, qkv,
        NTOK, QKV_LD, EMB, EMB);
    // 3) causal attention (fp16 mma flash)
    attn_mma<<<dim3(SEQ / 128, BATCH * NHEAD), 256, AT_SMEM>>>(qkv, attn);
    // 4) O proj + residual (fp32 out)
    gemm_mma<2,1><<<dim3(EMB / GBN, NTOK / GBM), 256, GSMEM_DYN>>>(
        attn, woh, nullptr, nullptr, bo, nullptr, nullptr, x, a_att, x1,
        NTOK, EMB, EMB, EMB);
    // 5) LN2
    ln_kernel<<<NTOK, 256>>>(x1, ln2g, ln2b, xln2);
    // 6) FF1 + GELU (fp16 out)
    gemm_mma<1,1><<<dim3(FFD / GBN, NTOK / GBM), 256, GSMEM_DYN>>>(
        xln2, w1h, nullptr, nullptr, b1, nullptr, nullptr, nullptr, nullptr, ff,
        NTOK, FFD, EMB, FFD);
    // 7) FF2 + residual -> out (fp32)
    gemm_mma<2,1><<<dim3(EMB / GBN, NTOK / GBM), 256, GSMEM_DYN>>>(
        ff, w2h, nullptr, nullptr, b2, nullptr, nullptr, x1, a_ff, out,
        NTOK, EMB, FFD, EMB);
}

// round 13
// speedup vs baseline: 8.4448x; 1.5361x over previous
#include <cuda_runtime.h>
#include <cuda_fp16.h>
#include <math.h>
#include <stdint.h>

#define NTOK 4096      // B*T
#define EMB  1024
#define FFD  4096
#define BATCH 2
#define SEQ  2048
#define NHEAD 16
#define HDIM 64
#define LN_EPS 1e-5f
#define QKV_LD 3072

// ---------------- scratch (device globals; no allocations allowed) ----------
__device__ __half g_xln [NTOK * EMB];
__device__ __half g_qkv [NTOK * QKV_LD];
__device__ __half g_attn[NTOK * EMB];
__device__ float  g_x1  [NTOK * EMB];
__device__ __half g_xln2[NTOK * EMB];
__device__ __half g_ff  [NTOK * FFD];
// half weights
__device__ __half g_wqh[EMB * EMB];
__device__ __half g_wkh[EMB * EMB];
__device__ __half g_wvh[EMB * EMB];
__device__ __half g_woh[EMB * EMB];
__device__ __half g_w1h[EMB * FFD];
__device__ __half g_w2h[FFD * EMB];

// ---------------- helpers ----------------------------------------------------
__device__ __forceinline__ uint32_t sm_u32(const void* p) {
    return (uint32_t)__cvta_generic_to_shared(p);
}
__device__ __forceinline__ void cp_async16(uint32_t smem, const void* gptr) {
    asm volatile("cp.async.cg.shared.global [%0], [%1], 16;"
                 :: "r"(smem), "l"(__cvta_generic_to_global(gptr)) : "memory");
}
__device__ __forceinline__ void cp_commit() {
    asm volatile("cp.async.commit_group;" ::: "memory");
}
template<int N>
__device__ __forceinline__ void cp_wait() {
    asm volatile("cp.async.wait_group %0;" :: "n"(N) : "memory");
}
// fp16 mma with fp32 accumulate: D = A(16x16) * B(16x8) + D
__device__ __forceinline__ void mma_f16(float* c, const uint32_t* a, const uint32_t* b) {
    asm volatile(
        "mma.sync.aligned.m16n8k16.row.col.f32.f16.f16.f32 "
        "{%0,%1,%2,%3}, {%4,%5,%6,%7}, {%8,%9}, {%0,%1,%2,%3};"
        : "+f"(c[0]), "+f"(c[1]), "+f"(c[2]), "+f"(c[3])
        : "r"(a[0]), "r"(a[1]), "r"(a[2]), "r"(a[3]), "r"(b[0]), "r"(b[1]));
}
__device__ __forceinline__ void ldsm_x4(uint32_t* r, uint32_t addr) {
    asm volatile("ldmatrix.sync.aligned.m8n8.x4.shared.b16 {%0,%1,%2,%3}, [%4];"
                 : "=r"(r[0]), "=r"(r[1]), "=r"(r[2]), "=r"(r[3]) : "r"(addr));
}
__device__ __forceinline__ void ldsm_x4t(uint32_t* r, uint32_t addr) {
    asm volatile("ldmatrix.sync.aligned.m8n8.x4.trans.shared.b16 {%0,%1,%2,%3}, [%4];"
                 : "=r"(r[0]), "=r"(r[1]), "=r"(r[2]), "=r"(r[3]) : "r"(addr));
}
__device__ __forceinline__ float gelu_exact(float c) {
    return 0.5f * c * (1.0f + erff(c * 0.70710678118654752f));
}

// ---------------- fused fp32 -> fp16 weight convert (one launch) -------------
#define WSEG (EMB * EMB)                    // 1M elems
__global__ __launch_bounds__(256) void f2h_all(
    const float* __restrict__ wq, const float* __restrict__ wk,
    const float* __restrict__ wv, const float* __restrict__ wo,
    const float* __restrict__ w1, const float* __restrict__ w2,
    __half* __restrict__ dq, __half* __restrict__ dk,
    __half* __restrict__ dv, __half* __restrict__ dod,
    __half* __restrict__ d1, __half* __restrict__ d2)
{
    int i = (blockIdx.x * 256 + threadIdx.x) * 4;
    const float* s; __half* d; int off;
    if      (i < 1 * WSEG) { s = wq; d = dq;  off = 0; }
    else if (i < 2 * WSEG) { s = wk; d = dk;  off = 1 * WSEG; }
    else if (i < 3 * WSEG) { s = wv; d = dv;  off = 2 * WSEG; }
    else if (i < 4 * WSEG) { s = wo; d = dod; off = 3 * WSEG; }
    else if (i < 8 * WSEG) { s = w1; d = d1;  off = 4 * WSEG; }
    else                   { s = w2; d = d2;  off = 8 * WSEG; }
    int j = i - off;
    float4 v = *(const float4*)&s[j];
    *(half2*)&d[j]     = __floats2half2_rn(v.x, v.y);
    *(half2*)&d[j + 2] = __floats2half2_rn(v.z, v.w);
}

// ---------------- LayerNorm (fp32 in, fp16 out) ------------------------------
__global__ __launch_bounds__(256) void ln_kernel(
    const float* __restrict__ x, const float* __restrict__ g,
    const float* __restrict__ b, __half* __restrict__ y)
{
    int row = blockIdx.x;
    int tid = threadIdx.x;
    const float* xr = x + row * EMB;
    float4 v = *(const float4*)&xr[tid * 4];
    float s  = v.x + v.y + v.z + v.w;
    float ss = v.x*v.x + v.y*v.y + v.z*v.z + v.w*v.w;

    #pragma unroll
    for (int off = 16; off > 0; off >>= 1) {
        s  += __shfl_down_sync(0xffffffffu, s,  off);
        ss += __shfl_down_sync(0xffffffffu, ss, off);
    }
    __shared__ float red_s[8], red_ss[8];
    int wid = tid >> 5, lid = tid & 31;
    if (lid == 0) { red_s[wid] = s; red_ss[wid] = ss; }
    __syncthreads();
    if (wid == 0) {
        float a  = (lid < 8) ? red_s[lid]  : 0.f;
        float a2 = (lid < 8) ? red_ss[lid] : 0.f;
        #pragma unroll
        for (int off = 4; off > 0; off >>= 1) {
            a  += __shfl_down_sync(0xffffffffu, a,  off);
            a2 += __shfl_down_sync(0xffffffffu, a2, off);
        }
        if (lid == 0) { red_s[0] = a; red_ss[0] = a2; }
    }
    __syncthreads();
    float mu  = red_s[0] * (1.0f / EMB);
    float var = red_ss[0] * (1.0f / EMB) - mu * mu;
    float rs  = rsqrtf(var + LN_EPS);

    float4 gv = *(const float4*)&g[tid * 4];
    float4 bv = *(const float4*)&b[tid * 4];
    float o0 = (v.x - mu) * rs * gv.x + bv.x;
    float o1 = (v.y - mu) * rs * gv.y + bv.y;
    float o2 = (v.z - mu) * rs * gv.z + bv.z;
    float o3 = (v.w - mu) * rs * gv.w + bv.w;
    __half* yp = y + row * EMB + tid * 4;
    *(half2*)(yp)     = __floats2half2_rn(o0, o1);
    *(half2*)(yp + 2) = __floats2half2_rn(o2, o3);
}

// ---------------- fp16 mma.sync GEMM (GBK=64) --------------------------------
// C[M,N] = epilogue(A_half[M,K] @ W_half[K,N] + bias_f32)
// MODE 0: +bias -> half   MODE 1: gelu(+bias) -> half   MODE 2: res + alpha*() -> float
// NSEL 3: select W/bias by output column block (fused QKV)
#define GBM 128
#define GBN 128
#define GBK 64
#define APITCH 72                          // halves; 144B row, ldmatrix conflict-free
#define BPITCH 136                         // halves; 272B row
#define ABYTES (GBM * APITCH * 2)          // 18432
#define BBYTES (GBK * BPITCH * 2)          // 17408
#define STAGE_BYTES (ABYTES + BBYTES)      // 35840
#define GSTAGES 3
#define GSMEM_DYN (GSTAGES * STAGE_BYTES)  // 107520

template<int MODE, int NSEL>
__global__ __launch_bounds__(256, 2) void gemm_mma(
    const __half* __restrict__ A,
    const __half* __restrict__ W0, const __half* __restrict__ W1,
    const __half* __restrict__ W2,
    const float* __restrict__ bias0, const float* __restrict__ bias1,
    const float* __restrict__ bias2,
    const float* __restrict__ res, const float* __restrict__ alpha_p,
    void* __restrict__ Cv, int M, int N, int K, int Nw)
{
    extern __shared__ char dynsm[];
    int tid = threadIdx.x, wid = tid >> 5, lid = tid & 31;
    int gid = lid >> 2, tg = lid & 3;
    int wm = (wid & 1) * 64, wn = (wid >> 1) * 32;   // warp tile 64x32
    int bm = blockIdx.y * GBM, bn = blockIdx.x * GBN;

    const __half* W = W0;
    const float* bias = bias0;
    int bnw = bn;
    if (NSEL == 3) {
        int sel = bn / Nw;
        W    = (sel == 0) ? W0 : ((sel == 1) ? W1 : W2);
        bias = (sel == 0) ? bias0 : ((sel == 1) ? bias1 : bias2);
        bnw  = bn - sel * Nw;
    }

    int l7 = lid & 7, t8 = lid >> 3;
    // A frags: tile t: row=(t&1)*8+l7, kcol=(t>>1)*8 (halves)
    uint32_t a_lane_off[4];
    #pragma unroll
    for (int mf = 0; mf < 4; mf++)
        a_lane_off[mf] = (uint32_t)(((wm + mf * 16 + (t8 & 1) * 8 + l7) * APITCH
                                     + (t8 >> 1) * 8) * 2);
    // B frags (trans): tile t: krow=(t&1)*8+l7, ncol=(t>>1)*8
    uint32_t b_lane_off = (uint32_t)((((t8 & 1) * 8 + l7) * BPITCH + (t8 >> 1) * 8) * 2);

    float acc[4][4][4];
    #pragma unroll
    for (int mf = 0; mf < 4; mf++)
        #pragma unroll
        for (int nf = 0; nf < 4; nf++)
            #pragma unroll
            for (int i = 0; i < 4; i++) acc[mf][nf][i] = 0.f;

    auto load_stage = [&](int s) {
        char* base = dynsm + (s % GSTAGES) * STAGE_BYTES;
        __half* As = (__half*)base;
        __half* Bs = (__half*)(base + ABYTES);
        const __half* Ag = A + (size_t)bm * K + s * GBK;
        const __half* Wg = W + (size_t)(s * GBK) * Nw + bnw;
        #pragma unroll
        for (int i = 0; i < 4; i++) {      // A: 128 rows x 8 x16B chunks
            int idx = tid + i * 256;
            int r = idx >> 3, c = idx & 7;
            cp_async16(sm_u32(As + r * APITCH + c * 8), Ag + (size_t)r * K + c * 8);
        }
        #pragma unroll
        for (int i = 0; i < 4; i++) {      // B: 64 k-rows x 16 x16B chunks
            int idx = tid + i * 256;
            int r = idx >> 4, c = idx & 15;
            cp_async16(sm_u32(Bs + r * BPITCH + c * 8), Wg + (size_t)r * Nw + c * 8);
        }
    };

    load_stage(0); cp_commit();
    load_stage(1); cp_commit();

    int nst = K / GBK;
    for (int s = 0; s < nst; s++) {
        cp_wait<1>();
        __syncthreads();
        if (s + 2 < nst) load_stage(s + 2);
        cp_commit();

        char* base = dynsm + (s % GSTAGES) * STAGE_BYTES;
        uint32_t as_u32 = sm_u32(base);
        uint32_t bs_u32 = sm_u32(base + ABYTES);

        #pragma unroll
        for (int ks = 0; ks < 4; ks++) {
            int k0 = ks * 16;
            uint32_t af[4][4], bf[4][2];
            #pragma unroll
            for (int mf = 0; mf < 4; mf++)
                ldsm_x4(af[mf], as_u32 + a_lane_off[mf] + (uint32_t)(k0 * 2));
            #pragma unroll
            for (int nb = 0; nb < 2; nb++) {
                uint32_t r[4];
                ldsm_x4t(r, bs_u32 + b_lane_off +
                            (uint32_t)((k0 * BPITCH + wn + nb * 16) * 2));
                bf[2*nb][0]   = r[0]; bf[2*nb][1]   = r[1];
                bf[2*nb+1][0] = r[2]; bf[2*nb+1][1] = r[3];
            }
            #pragma unroll
            for (int mf = 0; mf < 4; mf++)
                #pragma unroll
                for (int nf = 0; nf < 4; nf++)
                    mma_f16(acc[mf][nf], af[mf], bf[nf]);
        }
    }

    float alpha = (MODE == 2) ? *alpha_p : 1.0f;
    #pragma unroll
    for (int mf = 0; mf < 4; mf++) {
        int r0 = bm + wm + mf * 16 + gid;
        #pragma unroll
        for (int nf = 0; nf < 4; nf++) {
            int loc = wn + nf * 8 + 2 * tg;
            int col = bn + loc;
            float2 bv = *(const float2*)&bias[bnw + loc];
            float v0 = acc[mf][nf][0] + bv.x;
            float v1 = acc[mf][nf][1] + bv.y;
            float v2 = acc[mf][nf][2] + bv.x;
            float v3 = acc[mf][nf][3] + bv.y;
            if (MODE == 1) {
                v0 = gelu_exact(v0); v1 = gelu_exact(v1);
                v2 = gelu_exact(v2); v3 = gelu_exact(v3);
            }
            if (MODE == 2) {
                float* C = (float*)Cv;
                float2 ra = *(const float2*)&res[(size_t)r0 * N + col];
                float2 rb = *(const float2*)&res[(size_t)(r0 + 8) * N + col];
                *(float2*)&C[(size_t)r0 * N + col] =
                    make_float2(ra.x + alpha * v0, ra.y + alpha * v1);
                *(float2*)&C[(size_t)(r0 + 8) * N + col] =
                    make_float2(rb.x + alpha * v2, rb.y + alpha * v3);
            } else {
                __half* C = (__half*)Cv;
                *(half2*)&C[(size_t)r0 * N + col]       = __floats2half2_rn(v0, v1);
                *(half2*)&C[(size_t)(r0 + 8) * N + col] = __floats2half2_rn(v2, v3);
            }
        }
    }
}

// ---------------- fp16 mma flash attention (BQ=128) --------------------------
// 8 warps (16 q-rows each), BK=64 keys per tile; all fragments via ldmatrix.
#define ATP 72                               // halves per row (144B)
#define AT_TILE (64 * ATP)                   // halves per K or V tile
#define AT_PSH  (4 * AT_TILE)                // after 2 x (K+V) buffers
#define AT_SMEM ((4 * AT_TILE + 128 * ATP) * 2)   // 55296 B

__global__ __launch_bounds__(256) void attn_mma(
    const __half* __restrict__ QKV, __half* __restrict__ O)
{
    extern __shared__ __half ash[];
    __half* psh = ash + AT_PSH;              // [128][72] halves
    uint32_t ash_u32 = sm_u32(ash);
    uint32_t psh_u32 = sm_u32(psh);

    int qt = gridDim.x - 1 - blockIdx.x;     // long blocks first
    int bh = blockIdx.y;
    int b  = bh >> 4, h = bh & 15;
    int tid = threadIdx.x, wid = tid >> 5, lid = tid & 31;
    int gid = lid >> 2, tg = lid & 3;
    int wm = wid * 16;
    int qb = qt * 128;
    const float scale = 0.125f;

    int l7 = lid & 7, t8 = lid >> 3;
    uint32_t k_lane_off = (uint32_t)((((lid >> 4) * 8 + l7) * ATP + ((t8 & 1) * 8)) * 2);
    uint32_t v_lane_off = (uint32_t)((((t8 & 1) * 8 + l7) * ATP + (lid >> 4) * 8) * 2);
    uint32_t p_lane_off = (uint32_t)(((wm + (t8 & 1) * 8 + l7) * ATP + (t8 >> 1) * 8) * 2);

    auto load_tile = [&](int kt, int buf) {
        __half* kb = ash + buf * 2 * AT_TILE;
        __half* vb = kb + AT_TILE;
        #pragma unroll
        for (int i = 0; i < 2; i++) {
            int idx = tid + i * 256;
            int r = idx >> 3, c = idx & 7;          // 64 rows x 8 chunks
            const __half* src = &QKV[(size_t)(b * SEQ + kt * 64 + r) * QKV_LD
                                     + h * HDIM + c * 8];
            cp_async16(sm_u32(kb + r * ATP + c * 8), src + EMB);
            cp_async16(sm_u32(vb + r * ATP + c * 8), src + 2 * EMB);
        }
    };

    // Q fragments (A-op, global half, held whole kernel): 4 k16-steps
    uint32_t qf[4][4];
    {
        const __half* q0 = &QKV[(size_t)(b * SEQ + qb + wm + gid) * QKV_LD + h * HDIM];
        const __half* q8 = q0 + 8 * QKV_LD;
        #pragma unroll
        for (int ks = 0; ks < 4; ks++) {
            qf[ks][0] = *(const uint32_t*)(q0 + ks * 16 + 2 * tg);
            qf[ks][1] = *(const uint32_t*)(q8 + ks * 16 + 2 * tg);
            qf[ks][2] = *(const uint32_t*)(q0 + ks * 16 + 8 + 2 * tg);
            qf[ks][3] = *(const uint32_t*)(q8 + ks * 16 + 8 + 2 * tg);
        }
    }

    float oacc[8][4];
    #pragma unroll
    for (int nf = 0; nf < 8; nf++)
        #pragma unroll
        for (int i = 0; i < 4; i++) oacc[nf][i] = 0.f;
    float om0 = -INFINITY, om1 = -INFINITY, ol0 = 0.f, ol1 = 0.f;

    int r0 = qb + wm + gid, r1 = r0 + 8;
    int nkt = 2 * qt + 2;

    load_tile(0, 0); cp_commit();

    for (int kt = 0; kt < nkt; kt++) {
        if (kt + 1 < nkt) load_tile(kt + 1, (kt + 1) & 1);
        cp_commit();
        cp_wait<1>();
        __syncthreads();

        uint32_t ksh_u32 = ash_u32 + (uint32_t)((kt & 1) * 2 * AT_TILE) * 2u;
        uint32_t vsh_u32 = ksh_u32 + (uint32_t)AT_TILE * 2u;

        // ---- S = Q @ K^T ----
        float sacc[8][4];
        #pragma unroll
        for (int nf = 0; nf < 8; nf++)
            #pragma unroll
            for (int i = 0; i < 4; i++) sacc[nf][i] = 0.f;
        #pragma unroll
        for (int ks = 0; ks < 4; ks++) {
            uint32_t bf[8][2];
            #pragma unroll
            for (int np = 0; np < 4; np++) {
                uint32_t r[4];
                ldsm_x4(r, ksh_u32 + k_lane_off +
                           (uint32_t)((np * 16 * ATP + ks * 16) * 2));
                bf[2*np][0]   = r[0]; bf[2*np][1]   = r[1];
                bf[2*np+1][0] = r[2]; bf[2*np+1][1] = r[3];
            }
            #pragma unroll
            for (int nf = 0; nf < 8; nf++)
                mma_f16(sacc[nf], qf[ks], bf[nf]);
        }

        // ---- scale + causal mask + row max ----
        bool diag = (kt >= 2 * qt);
        float tmax0 = -INFINITY, tmax1 = -INFINITY;
        #pragma unroll
        for (int nf = 0; nf < 8; nf++) {
            int c0 = kt * 64 + nf * 8 + 2 * tg;
            #pragma unroll
            for (int c = 0; c < 2; c++) {
                float s0 = sacc[nf][c] * scale;
                float s1 = sacc[nf][2 + c] * scale;
                if (diag && c0 + c > r0) s0 = -INFINITY;
                if (diag && c0 + c > r1) s1 = -INFINITY;
                sacc[nf][c] = s0; sacc[nf][2 + c] = s1;
                tmax0 = fmaxf(tmax0, s0);
                tmax1 = fmaxf(tmax1, s1);
            }
        }
        tmax0 = fmaxf(tmax0, __shfl_xor_sync(0xffffffffu, tmax0, 1));
        tmax0 = fmaxf(tmax0, __shfl_xor_sync(0xffffffffu, tmax0, 2));
        tmax1 = fmaxf(tmax1, __shfl_xor_sync(0xffffffffu, tmax1, 1));
        tmax1 = fmaxf(tmax1, __shfl_xor_sync(0xffffffffu, tmax1, 2));

        float mn0 = fmaxf(om0, tmax0), mn1 = fmaxf(om1, tmax1);
        float corr0 = __expf(om0 - mn0), corr1 = __expf(om1 - mn1);
        om0 = mn0; om1 = mn1;

        float ps0 = 0.f, ps1 = 0.f;
        #pragma unroll
        for (int nf = 0; nf < 8; nf++) {
            #pragma unroll
            for (int c = 0; c < 2; c++) {
                float e0 = __expf(sacc[nf][c] - mn0);
                float e1 = __expf(sacc[nf][2 + c] - mn1);
                sacc[nf][c] = e0; sacc[nf][2 + c] = e1;
                ps0 += e0; ps1 += e1;
            }
        }
        ps0 += __shfl_xor_sync(0xffffffffu, ps0, 1);
        ps0 += __shfl_xor_sync(0xffffffffu, ps0, 2);
        ps1 += __shfl_xor_sync(0xffffffffu, ps1, 1);
        ps1 += __shfl_xor_sync(0xffffffffu, ps1, 2);
        ol0 = ol0 * corr0 + ps0;
        ol1 = ol1 * corr1 + ps1;

        #pragma unroll
        for (int nf = 0; nf < 8; nf++) {
            oacc[nf][0] *= corr0; oacc[nf][1] *= corr0;
            oacc[nf][2] *= corr1; oacc[nf][3] *= corr1;
        }

        // ---- P -> smem as half (warp-private rows) ----
        #pragma unroll
        for (int nf = 0; nf < 8; nf++) {
            int col = nf * 8 + 2 * tg;
            *(half2*)&psh[(wm + gid) * ATP + col]     = __floats2half2_rn(sacc[nf][0], sacc[nf][1]);
            *(half2*)&psh[(wm + gid + 8) * ATP + col] = __floats2half2_rn(sacc[nf][2], sacc[nf][3]);
        }
        __syncwarp();

        // ---- O += P @ V ----
        #pragma unroll
        for (int ks = 0; ks < 4; ks++) {
            uint32_t af[4];
            ldsm_x4(af, psh_u32 + p_lane_off + (uint32_t)(ks * 16 * 2));
            uint32_t bf[8][2];
            #pragma unroll
            for (int nv = 0; nv < 4; nv++) {
                uint32_t r[4];
                ldsm_x4t(r, vsh_u32 + v_lane_off +
                            (uint32_t)((ks * 16 * ATP + nv * 16) * 2));
                bf[2*nv][0]   = r[0]; bf[2*nv][1]   = r[1];
                bf[2*nv+1][0] = r[2]; bf[2*nv+1][1] = r[3];
            }
            #pragma unroll
            for (int nf = 0; nf < 8; nf++)
                mma_f16(oacc[nf], af, bf[nf]);
        }
        __syncthreads();
    }

    // ---- epilogue (half output) ----
    float inv0 = 1.0f / ol0, inv1 = 1.0f / ol1;
    __half* o0 = &O[(size_t)(b * SEQ + r0) * EMB + h * HDIM];
    __half* o8 = o0 + 8 * EMB;
    #pragma unroll
    for (int nf = 0; nf < 8; nf++) {
        int d = nf * 8 + 2 * tg;
        *(half2*)&o0[d] = __floats2half2_rn(oacc[nf][0] * inv0, oacc[nf][1] * inv0);
        *(half2*)&o8[d] = __floats2half2_rn(oacc[nf][2] * inv1, oacc[nf][3] * inv1);
    }
}

// ---------------- launch ----------------------------------------------------
extern "C" void kernel_launch(void* const* d_in, const int* in_sizes, int n_in,
                              void* d_out, int out_size)
{
    (void)in_sizes; (void)n_in; (void)out_size;
    const float* x     = (const float*)d_in[0];
    const float* wq    = (const float*)d_in[1];
    const float* bq    = (const float*)d_in[2];
    const float* wk    = (const float*)d_in[3];
    const float* bk    = (const float*)d_in[4];
    const float* wv    = (const float*)d_in[5];
    const float* bv    = (const float*)d_in[6];
    const float* wo    = (const float*)d_in[7];
    const float* bo    = (const float*)d_in[8];
    const float* w1    = (const float*)d_in[9];
    const float* b1    = (const float*)d_in[10];
    const float* w2    = (const float*)d_in[11];
    const float* b2    = (const float*)d_in[12];
    const float* ln1g  = (const float*)d_in[13];
    const float* ln1b  = (const float*)d_in[14];
    const float* ln2g  = (const float*)d_in[15];
    const float* ln2b  = (const float*)d_in[16];
    const float* a_att = (const float*)d_in[17];
    const float* a_ff  = (const float*)d_in[18];
    float* out = (float*)d_out;

    __half *xln, *qkv, *attn, *xln2, *ff;
    __half *wqh, *wkh, *wvh, *woh, *w1h, *w2h;
    float  *x1;
    cudaGetSymbolAddress((void**)&xln,  g_xln);
    cudaGetSymbolAddress((void**)&qkv,  g_qkv);
    cudaGetSymbolAddress((void**)&attn, g_attn);
    cudaGetSymbolAddress((void**)&x1,   g_x1);
    cudaGetSymbolAddress((void**)&xln2, g_xln2);
    cudaGetSymbolAddress((void**)&ff,   g_ff);
    cudaGetSymbolAddress((void**)&wqh,  g_wqh);
    cudaGetSymbolAddress((void**)&wkh,  g_wkh);
    cudaGetSymbolAddress((void**)&wvh,  g_wvh);
    cudaGetSymbolAddress((void**)&woh,  g_woh);
    cudaGetSymbolAddress((void**)&w1h,  g_w1h);
    cudaGetSymbolAddress((void**)&w2h,  g_w2h);

    cudaFuncSetAttribute(gemm_mma<0,3>, cudaFuncAttributeMaxDynamicSharedMemorySize, GSMEM_DYN);
    cudaFuncSetAttribute(gemm_mma<1,1>, cudaFuncAttributeMaxDynamicSharedMemorySize, GSMEM_DYN);
    cudaFuncSetAttribute(gemm_mma<2,1>, cudaFuncAttributeMaxDynamicSharedMemorySize, GSMEM_DYN);
    cudaFuncSetAttribute(attn_mma,      cudaFuncAttributeMaxDynamicSharedMemorySize, AT_SMEM);

    // 0) all weight conversions in ONE launch (12M elems / 4 per thread)
    f2h_all<<<12 * WSEG / 1024, 256>>>(wq, wk, wv, wo, w1, w2,
                                       wqh, wkh, wvh, woh, w1h, w2h);

    // 1) LN1 (fp32 -> fp16)
    ln_kernel<<<NTOK, 256>>>(x, ln1g, ln1b, xln);
    // 2) fused QKV GEMM (fp16 mma, GBK=64)
    gemm_mma<0,3><<<dim3(QKV_LD / GBN, NTOK / GBM), 256, GSMEM_DYN>>>(
        xln, wqh, wkh, wvh, bq, bk, bv, nullptr, nullptr, qkv,
        NTOK, QKV_LD, EMB, EMB);
    // 3) causal attention (fp16 mma flash)
    attn_mma<<<dim3(SEQ / 128, BATCH * NHEAD), 256, AT_SMEM>>>(qkv, attn);
    // 4) O proj + residual (fp32 out)
    gemm_mma<2,1><<<dim3(EMB / GBN, NTOK / GBM), 256, GSMEM_DYN>>>(
        attn, woh, nullptr, nullptr, bo, nullptr, nullptr, x, a_att, x1,
        NTOK, EMB, EMB, EMB);
    // 5) LN2
    ln_kernel<<<NTOK, 256>>>(x1, ln2g, ln2b, xln2);
    // 6) FF1 + GELU (fp16 out)
    gemm_mma<1,1><<<dim3(FFD / GBN, NTOK / GBM), 256, GSMEM_DYN>>>(
        xln2, w1h, nullptr, nullptr, b1, nullptr, nullptr, nullptr, nullptr, ff,
        NTOK, FFD, EMB, FFD);
    // 7) FF2 + residual -> out (fp32)
    gemm_mma<2,1><<<dim3(EMB / GBN, NTOK / GBM), 256, GSMEM_DYN>>>(
        ff, w2h, nullptr, nullptr, b2, nullptr, nullptr, x1, a_ff, out,
        NTOK, EMB, FFD, EMB);
}

// round 15
// speedup vs baseline: 8.5426x; 1.0116x over previous
#include <cuda_runtime.h>
#include <cuda_fp16.h>
#include <math.h>
#include <stdint.h>
#include <string.h>

#define NTOK 4096      // B*T
#define EMB  1024
#define FFD  4096
#define BATCH 2
#define SEQ  2048
#define NHEAD 16
#define HDIM 64
#define LN_EPS 1e-5f
#define QKV_LD 3072

// ---------------- scratch (device globals; no allocations allowed) ----------
__device__ __half g_xln [NTOK * EMB];
__device__ __half g_qkv [NTOK * QKV_LD];
__device__ __half g_attn[NTOK * EMB];
__device__ float  g_x1  [NTOK * EMB];
__device__ __half g_xln2[NTOK * EMB];
__device__ __half g_ff  [NTOK * FFD];
// half weights
__device__ __half g_wqh[EMB * EMB];
__device__ __half g_wkh[EMB * EMB];
__device__ __half g_wvh[EMB * EMB];
__device__ __half g_woh[EMB * EMB];
__device__ __half g_w1h[EMB * FFD];
__device__ __half g_w2h[FFD * EMB];

// ---------------- helpers ----------------------------------------------------
__device__ __forceinline__ uint32_t sm_u32(const void* p) {
    return (uint32_t)__cvta_generic_to_shared(p);
}
__device__ __forceinline__ void cp_async16(uint32_t smem, const void* gptr) {
    asm volatile("cp.async.cg.shared.global [%0], [%1], 16;"
                 :: "r"(smem), "l"(__cvta_generic_to_global(gptr)) : "memory");
}
__device__ __forceinline__ void cp_commit() {
    asm volatile("cp.async.commit_group;" ::: "memory");
}
template<int N>
__device__ __forceinline__ void cp_wait() {
    asm volatile("cp.async.wait_group %0;" :: "n"(N) : "memory");
}
// fp16 mma with fp32 accumulate: D = A(16x16) * B(16x8) + D
__device__ __forceinline__ void mma_f16(float* c, const uint32_t* a, const uint32_t* b) {
    asm volatile(
        "mma.sync.aligned.m16n8k16.row.col.f32.f16.f16.f32 "
        "{%0,%1,%2,%3}, {%4,%5,%6,%7}, {%8,%9}, {%0,%1,%2,%3};"
        : "+f"(c[0]), "+f"(c[1]), "+f"(c[2]), "+f"(c[3])
        : "r"(a[0]), "r"(a[1]), "r"(a[2]), "r"(a[3]), "r"(b[0]), "r"(b[1]));
}
__device__ __forceinline__ void ldsm_x4(uint32_t* r, uint32_t addr) {
    asm volatile("ldmatrix.sync.aligned.m8n8.x4.shared.b16 {%0,%1,%2,%3}, [%4];"
                 : "=r"(r[0]), "=r"(r[1]), "=r"(r[2]), "=r"(r[3]) : "r"(addr));
}
__device__ __forceinline__ void ldsm_x4t(uint32_t* r, uint32_t addr) {
    asm volatile("ldmatrix.sync.aligned.m8n8.x4.trans.shared.b16 {%0,%1,%2,%3}, [%4];"
                 : "=r"(r[0]), "=r"(r[1]), "=r"(r[2]), "=r"(r[3]) : "r"(addr));
}
__device__ __forceinline__ float gelu_exact(float c) {
    return 0.5f * c * (1.0f + erff(c * 0.70710678118654752f));
}
__device__ __forceinline__ uint32_t packh2(float a, float b) {
    half2 h = __floats2half2_rn(a, b);
    uint32_t u;
    memcpy(&u, &h, 4);
    return u;
}

// ---------------- fused fp32 -> fp16 weight convert (one launch) -------------
#define WSEG (EMB * EMB)                    // 1M elems
__global__ __launch_bounds__(256) void f2h_all(
    const float* __restrict__ wq, const float* __restrict__ wk,
    const float* __restrict__ wv, const float* __restrict__ wo,
    const float* __restrict__ w1, const float* __restrict__ w2,
    __half* __restrict__ dq, __half* __restrict__ dk,
    __half* __restrict__ dv, __half* __restrict__ dod,
    __half* __restrict__ d1, __half* __restrict__ d2)
{
    int i = (blockIdx.x * 256 + threadIdx.x) * 4;
    const float* s; __half* d; int off;
    if      (i < 1 * WSEG) { s = wq; d = dq;  off = 0; }
    else if (i < 2 * WSEG) { s = wk; d = dk;  off = 1 * WSEG; }
    else if (i < 3 * WSEG) { s = wv; d = dv;  off = 2 * WSEG; }
    else if (i < 4 * WSEG) { s = wo; d = dod; off = 3 * WSEG; }
    else if (i < 8 * WSEG) { s = w1; d = d1;  off = 4 * WSEG; }
    else                   { s = w2; d = d2;  off = 8 * WSEG; }
    int j = i - off;
    float4 v = *(const float4*)&s[j];
    *(half2*)&d[j]     = __floats2half2_rn(v.x, v.y);
    *(half2*)&d[j + 2] = __floats2half2_rn(v.z, v.w);
}

// ---------------- LayerNorm (fp32 in, fp16 out) ------------------------------
__global__ __launch_bounds__(256) void ln_kernel(
    const float* __restrict__ x, const float* __restrict__ g,
    const float* __restrict__ b, __half* __restrict__ y)
{
    int row = blockIdx.x;
    int tid = threadIdx.x;
    const float* xr = x + row * EMB;
    float4 v = *(const float4*)&xr[tid * 4];
    float s  = v.x + v.y + v.z + v.w;
    float ss = v.x*v.x + v.y*v.y + v.z*v.z + v.w*v.w;

    #pragma unroll
    for (int off = 16; off > 0; off >>= 1) {
        s  += __shfl_down_sync(0xffffffffu, s,  off);
        ss += __shfl_down_sync(0xffffffffu, ss, off);
    }
    __shared__ float red_s[8], red_ss[8];
    int wid = tid >> 5, lid = tid & 31;
    if (lid == 0) { red_s[wid] = s; red_ss[wid] = ss; }
    __syncthreads();
    if (wid == 0) {
        float a  = (lid < 8) ? red_s[lid]  : 0.f;
        float a2 = (lid < 8) ? red_ss[lid] : 0.f;
        #pragma unroll
        for (int off = 4; off > 0; off >>= 1) {
            a  += __shfl_down_sync(0xffffffffu, a,  off);
            a2 += __shfl_down_sync(0xffffffffu, a2, off);
        }
        if (lid == 0) { red_s[0] = a; red_ss[0] = a2; }
    }
    __syncthreads();
    float mu  = red_s[0] * (1.0f / EMB);
    float var = red_ss[0] * (1.0f / EMB) - mu * mu;
    float rs  = rsqrtf(var + LN_EPS);

    float4 gv = *(const float4*)&g[tid * 4];
    float4 bv = *(const float4*)&b[tid * 4];
    float o0 = (v.x - mu) * rs * gv.x + bv.x;
    float o1 = (v.y - mu) * rs * gv.y + bv.y;
    float o2 = (v.z - mu) * rs * gv.z + bv.z;
    float o3 = (v.w - mu) * rs * gv.w + bv.w;
    __half* yp = y + row * EMB + tid * 4;
    *(half2*)(yp)     = __floats2half2_rn(o0, o1);
    *(half2*)(yp + 2) = __floats2half2_rn(o2, o3);
}

// ---------------- fp16 mma.sync GEMM (GBK=64) --------------------------------
#define GBM 128
#define GBN 128
#define GBK 64
#define APITCH 72
#define BPITCH 136
#define ABYTES (GBM * APITCH * 2)
#define BBYTES (GBK * BPITCH * 2)
#define STAGE_BYTES (ABYTES + BBYTES)
#define GSTAGES 3
#define GSMEM_DYN (GSTAGES * STAGE_BYTES)

template<int MODE, int NSEL>
__global__ __launch_bounds__(256, 2) void gemm_mma(
    const __half* __restrict__ A,
    const __half* __restrict__ W0, const __half* __restrict__ W1,
    const __half* __restrict__ W2,
    const float* __restrict__ bias0, const float* __restrict__ bias1,
    const float* __restrict__ bias2,
    const float* __restrict__ res, const float* __restrict__ alpha_p,
    void* __restrict__ Cv, int M, int N, int K, int Nw)
{
    extern __shared__ char dynsm[];
    int tid = threadIdx.x, wid = tid >> 5, lid = tid & 31;
    int gid = lid >> 2, tg = lid & 3;
    int wm = (wid & 1) * 64, wn = (wid >> 1) * 32;
    int bm = blockIdx.y * GBM, bn = blockIdx.x * GBN;

    const __half* W = W0;
    const float* bias = bias0;
    int bnw = bn;
    if (NSEL == 3) {
        int sel = bn / Nw;
        W    = (sel == 0) ? W0 : ((sel == 1) ? W1 : W2);
        bias = (sel == 0) ? bias0 : ((sel == 1) ? bias1 : bias2);
        bnw  = bn - sel * Nw;
    }

    int l7 = lid & 7, t8 = lid >> 3;
    uint32_t a_lane_off[4];
    #pragma unroll
    for (int mf = 0; mf < 4; mf++)
        a_lane_off[mf] = (uint32_t)(((wm + mf * 16 + (t8 & 1) * 8 + l7) * APITCH
                                     + (t8 >> 1) * 8) * 2);
    uint32_t b_lane_off = (uint32_t)((((t8 & 1) * 8 + l7) * BPITCH + (t8 >> 1) * 8) * 2);

    float acc[4][4][4];
    #pragma unroll
    for (int mf = 0; mf < 4; mf++)
        #pragma unroll
        for (int nf = 0; nf < 4; nf++)
            #pragma unroll
            for (int i = 0; i < 4; i++) acc[mf][nf][i] = 0.f;

    auto load_stage = [&](int s) {
        char* base = dynsm + (s % GSTAGES) * STAGE_BYTES;
        __half* As = (__half*)base;
        __half* Bs = (__half*)(base + ABYTES);
        const __half* Ag = A + (size_t)bm * K + s * GBK;
        const __half* Wg = W + (size_t)(s * GBK) * Nw + bnw;
        #pragma unroll
        for (int i = 0; i < 4; i++) {
            int idx = tid + i * 256;
            int r = idx >> 3, c = idx & 7;
            cp_async16(sm_u32(As + r * APITCH + c * 8), Ag + (size_t)r * K + c * 8);
        }
        #pragma unroll
        for (int i = 0; i < 4; i++) {
            int idx = tid + i * 256;
            int r = idx >> 4, c = idx & 15;
            cp_async16(sm_u32(Bs + r * BPITCH + c * 8), Wg + (size_t)r * Nw + c * 8);
        }
    };

    load_stage(0); cp_commit();
    load_stage(1); cp_commit();

    int nst = K / GBK;
    for (int s = 0; s < nst; s++) {
        cp_wait<1>();
        __syncthreads();
        if (s + 2 < nst) load_stage(s + 2);
        cp_commit();

        char* base = dynsm + (s % GSTAGES) * STAGE_BYTES;
        uint32_t as_u32 = sm_u32(base);
        uint32_t bs_u32 = sm_u32(base + ABYTES);

        #pragma unroll
        for (int ks = 0; ks < 4; ks++) {
            int k0 = ks * 16;
            uint32_t af[4][4], bf[4][2];
            #pragma unroll
            for (int mf = 0; mf < 4; mf++)
                ldsm_x4(af[mf], as_u32 + a_lane_off[mf] + (uint32_t)(k0 * 2));
            #pragma unroll
            for (int nb = 0; nb < 2; nb++) {
                uint32_t r[4];
                ldsm_x4t(r, bs_u32 + b_lane_off +
                            (uint32_t)((k0 * BPITCH + wn + nb * 16) * 2));
                bf[2*nb][0]   = r[0]; bf[2*nb][1]   = r[1];
                bf[2*nb+1][0] = r[2]; bf[2*nb+1][1] = r[3];
            }
            #pragma unroll
            for (int mf = 0; mf < 4; mf++)
                #pragma unroll
                for (int nf = 0; nf < 4; nf++)
                    mma_f16(acc[mf][nf], af[mf], bf[nf]);
        }
    }

    float alpha = (MODE == 2) ? *alpha_p : 1.0f;
    #pragma unroll
    for (int mf = 0; mf < 4; mf++) {
        int r0 = bm + wm + mf * 16 + gid;
        #pragma unroll
        for (int nf = 0; nf < 4; nf++) {
            int loc = wn + nf * 8 + 2 * tg;
            int col = bn + loc;
            float2 bv = *(const float2*)&bias[bnw + loc];
            float v0 = acc[mf][nf][0] + bv.x;
            float v1 = acc[mf][nf][1] + bv.y;
            float v2 = acc[mf][nf][2] + bv.x;
            float v3 = acc[mf][nf][3] + bv.y;
            if (MODE == 1) {
                v0 = gelu_exact(v0); v1 = gelu_exact(v1);
                v2 = gelu_exact(v2); v3 = gelu_exact(v3);
            }
            if (MODE == 2) {
                float* C = (float*)Cv;
                float2 ra = *(const float2*)&res[(size_t)r0 * N + col];
                float2 rb = *(const float2*)&res[(size_t)(r0 + 8) * N + col];
                *(float2*)&C[(size_t)r0 * N + col] =
                    make_float2(ra.x + alpha * v0, ra.y + alpha * v1);
                *(float2*)&C[(size_t)(r0 + 8) * N + col] =
                    make_float2(rb.x + alpha * v2, rb.y + alpha * v3);
            } else {
                __half* C = (__half*)Cv;
                *(half2*)&C[(size_t)r0 * N + col]       = __floats2half2_rn(v0, v1);
                *(half2*)&C[(size_t)(r0 + 8) * N + col] = __floats2half2_rn(v2, v3);
            }
        }
    }
}

// ---------------- fp16 mma flash attention (register P, exp2 softmax) --------
// 8 warps (16 q-rows each), BQ=128, BK=64 keys per tile. No psh smem.
#define ATP 72                               // halves per row (144B)
#define AT_TILE (64 * ATP)                   // halves per K or V tile
#define AT_SMEM (4 * AT_TILE * 2)            // 36864 B (2 bufs x (K+V))

__global__ __launch_bounds__(256) void attn_mma(
    const __half* __restrict__ QKV, __half* __restrict__ O)
{
    extern __shared__ __half ash[];
    uint32_t ash_u32 = sm_u32(ash);

    int qt = gridDim.x - 1 - blockIdx.x;     // long blocks first
    int bh = blockIdx.y;
    int b  = bh >> 4, h = bh & 15;
    int tid = threadIdx.x, wid = tid >> 5, lid = tid & 31;
    int gid = lid >> 2, tg = lid & 3;
    int wm = wid * 16;
    int qb = qt * 128;
    const float qs = 0.125f * 1.44269504089f;   // scale * log2(e), folded into Q

    int l7 = lid & 7, t8 = lid >> 3;
    uint32_t k_lane_off = (uint32_t)((((lid >> 4) * 8 + l7) * ATP + ((t8 & 1) * 8)) * 2);
    uint32_t v_lane_off = (uint32_t)((((t8 & 1) * 8 + l7) * ATP + (lid >> 4) * 8) * 2);

    auto load_tile = [&](int kt, int buf) {
        __half* kb = ash + buf * 2 * AT_TILE;
        __half* vb = kb + AT_TILE;
        #pragma unroll
        for (int i = 0; i < 2; i++) {
            int idx = tid + i * 256;
            int r = idx >> 3, c = idx & 7;
            const __half* src = &QKV[(size_t)(b * SEQ + kt * 64 + r) * QKV_LD
                                     + h * HDIM + c * 8];
            cp_async16(sm_u32(kb + r * ATP + c * 8), src + EMB);
            cp_async16(sm_u32(vb + r * ATP + c * 8), src + 2 * EMB);
        }
    };

    // Q fragments, prescaled by qs in fp32 then packed to half
    uint32_t qf[4][4];
    {
        const __half* q0 = &QKV[(size_t)(b * SEQ + qb + wm + gid) * QKV_LD + h * HDIM];
        const __half* q8 = q0 + 8 * QKV_LD;
        #pragma unroll
        for (int ks = 0; ks < 4; ks++) {
            const __half* p[4] = { q0 + ks * 16 + 2 * tg, q8 + ks * 16 + 2 * tg,
                                   q0 + ks * 16 + 8 + 2 * tg, q8 + ks * 16 + 8 + 2 * tg };
            #pragma unroll
            for (int r = 0; r < 4; r++) {
                float2 f = __half22float2(*(const half2*)p[r]);
                qf[ks][r] = packh2(f.x * qs, f.y * qs);
            }
        }
    }

    float oacc[8][4];
    #pragma unroll
    for (int nf = 0; nf < 8; nf++)
        #pragma unroll
        for (int i = 0; i < 4; i++) oacc[nf][i] = 0.f;
    float om0 = -INFINITY, om1 = -INFINITY, ol0 = 0.f, ol1 = 0.f;

    int r0 = qb + wm + gid, r1 = r0 + 8;
    int nkt = 2 * qt + 2;

    load_tile(0, 0); cp_commit();

    for (int kt = 0; kt < nkt; kt++) {
        if (kt + 1 < nkt) load_tile(kt + 1, (kt + 1) & 1);
        cp_commit();
        cp_wait<1>();
        __syncthreads();

        uint32_t ksh_u32 = ash_u32 + (uint32_t)((kt & 1) * 2 * AT_TILE) * 2u;
        uint32_t vsh_u32 = ksh_u32 + (uint32_t)AT_TILE * 2u;

        // ---- S = (Q*qs) @ K^T  (log2-domain scores) ----
        float sacc[8][4];
        #pragma unroll
        for (int nf = 0; nf < 8; nf++)
            #pragma unroll
            for (int i = 0; i < 4; i++) sacc[nf][i] = 0.f;
        #pragma unroll
        for (int ks = 0; ks < 4; ks++) {
            uint32_t bf[8][2];
            #pragma unroll
            for (int np = 0; np < 4; np++) {
                uint32_t r[4];
                ldsm_x4(r, ksh_u32 + k_lane_off +
                           (uint32_t)((np * 16 * ATP + ks * 16) * 2));
                bf[2*np][0]   = r[0]; bf[2*np][1]   = r[1];
                bf[2*np+1][0] = r[2]; bf[2*np+1][1] = r[3];
            }
            #pragma unroll
            for (int nf = 0; nf < 8; nf++)
                mma_f16(sacc[nf], qf[ks], bf[nf]);
        }

        // ---- causal mask + row max (no scale multiply — folded into Q) ----
        bool diag = (kt >= 2 * qt);
        float tmax0 = -INFINITY, tmax1 = -INFINITY;
        #pragma unroll
        for (int nf = 0; nf < 8; nf++) {
            int c0 = kt * 64 + nf * 8 + 2 * tg;
            #pragma unroll
            for (int c = 0; c < 2; c++) {
                float s0 = sacc[nf][c];
                float s1 = sacc[nf][2 + c];
                if (diag && c0 + c > r0) s0 = -INFINITY;
                if (diag && c0 + c > r1) s1 = -INFINITY;
                sacc[nf][c] = s0; sacc[nf][2 + c] = s1;
                tmax0 = fmaxf(tmax0, s0);
                tmax1 = fmaxf(tmax1, s1);
            }
        }
        tmax0 = fmaxf(tmax0, __shfl_xor_sync(0xffffffffu, tmax0, 1));
        tmax0 = fmaxf(tmax0, __shfl_xor_sync(0xffffffffu, tmax0, 2));
        tmax1 = fmaxf(tmax1, __shfl_xor_sync(0xffffffffu, tmax1, 1));
        tmax1 = fmaxf(tmax1, __shfl_xor_sync(0xffffffffu, tmax1, 2));

        float mn0 = fmaxf(om0, tmax0), mn1 = fmaxf(om1, tmax1);
        float corr0 = exp2f(om0 - mn0), corr1 = exp2f(om1 - mn1);
        om0 = mn0; om1 = mn1;

        float ps0 = 0.f, ps1 = 0.f;
        #pragma unroll
        for (int nf = 0; nf < 8; nf++) {
            #pragma unroll
            for (int c = 0; c < 2; c++) {
                float e0 = exp2f(sacc[nf][c] - mn0);
                float e1 = exp2f(sacc[nf][2 + c] - mn1);
                sacc[nf][c] = e0; sacc[nf][2 + c] = e1;
                ps0 += e0; ps1 += e1;
            }
        }
        ps0 += __shfl_xor_sync(0xffffffffu, ps0, 1);
        ps0 += __shfl_xor_sync(0xffffffffu, ps0, 2);
        ps1 += __shfl_xor_sync(0xffffffffu, ps1, 1);
        ps1 += __shfl_xor_sync(0xffffffffu, ps1, 2);
        ol0 = ol0 * corr0 + ps0;
        ol1 = ol1 * corr1 + ps1;

        #pragma unroll
        for (int nf = 0; nf < 8; nf++) {
            oacc[nf][0] *= corr0; oacc[nf][1] *= corr0;
            oacc[nf][2] *= corr1; oacc[nf][3] *= corr1;
        }

        // ---- O += P @ V  (P straight from registers: C-frag == A-frag) ----
        #pragma unroll
        for (int ks = 0; ks < 4; ks++) {
            uint32_t af[4];
            af[0] = packh2(sacc[2*ks][0],   sacc[2*ks][1]);     // row gid,  k 0-7
            af[1] = packh2(sacc[2*ks][2],   sacc[2*ks][3]);     // row gid+8,k 0-7
            af[2] = packh2(sacc[2*ks+1][0], sacc[2*ks+1][1]);   // row gid,  k 8-15
            af[3] = packh2(sacc[2*ks+1][2], sacc[2*ks+1][3]);   // row gid+8,k 8-15
            uint32_t bf[8][2];
            #pragma unroll
            for (int nv = 0; nv < 4; nv++) {
                uint32_t r[4];
                ldsm_x4t(r, vsh_u32 + v_lane_off +
                            (uint32_t)((ks * 16 * ATP + nv * 16) * 2));
                bf[2*nv][0]   = r[0]; bf[2*nv][1]   = r[1];
                bf[2*nv+1][0] = r[2]; bf[2*nv+1][1] = r[3];
            }
            #pragma unroll
            for (int nf = 0; nf < 8; nf++)
                mma_f16(oacc[nf], af, bf[nf]);
        }
        __syncthreads();
    }

    // ---- epilogue (half output) ----
    float inv0 = 1.0f / ol0, inv1 = 1.0f / ol1;
    __half* o0 = &O[(size_t)(b * SEQ + r0) * EMB + h * HDIM];
    __half* o8 = o0 + 8 * EMB;
    #pragma unroll
    for (int nf = 0; nf < 8; nf++) {
        int d = nf * 8 + 2 * tg;
        *(half2*)&o0[d] = __floats2half2_rn(oacc[nf][0] * inv0, oacc[nf][1] * inv0);
        *(half2*)&o8[d] = __floats2half2_rn(oacc[nf][2] * inv1, oacc[nf][3] * inv1);
    }
}

// ---------------- launch ----------------------------------------------------
extern "C" void kernel_launch(void* const* d_in, const int* in_sizes, int n_in,
                              void* d_out, int out_size)
{
    (void)in_sizes; (void)n_in; (void)out_size;
    const float* x     = (const float*)d_in[0];
    const float* wq    = (const float*)d_in[1];
    const float* bq    = (const float*)d_in[2];
    const float* wk    = (const float*)d_in[3];
    const float* bk    = (const float*)d_in[4];
    const float* wv    = (const float*)d_in[5];
    const float* bv    = (const float*)d_in[6];
    const float* wo    = (const float*)d_in[7];
    const float* bo    = (const float*)d_in[8];
    const float* w1    = (const float*)d_in[9];
    const float* b1    = (const float*)d_in[10];
    const float* w2    = (const float*)d_in[11];
    const float* b2    = (const float*)d_in[12];
    const float* ln1g  = (const float*)d_in[13];
    const float* ln1b  = (const float*)d_in[14];
    const float* ln2g  = (const float*)d_in[15];
    const float* ln2b  = (const float*)d_in[16];
    const float* a_att = (const float*)d_in[17];
    const float* a_ff  = (const float*)d_in[18];
    float* out = (float*)d_out;

    __half *xln, *qkv, *attn, *xln2, *ff;
    __half *wqh, *wkh, *wvh, *woh, *w1h, *w2h;
    float  *x1;
    cudaGetSymbolAddress((void**)&xln,  g_xln);
    cudaGetSymbolAddress((void**)&qkv,  g_qkv);
    cudaGetSymbolAddress((void**)&attn, g_attn);
    cudaGetSymbolAddress((void**)&x1,   g_x1);
    cudaGetSymbolAddress((void**)&xln2, g_xln2);
    cudaGetSymbolAddress((void**)&ff,   g_ff);
    cudaGetSymbolAddress((void**)&wqh,  g_wqh);
    cudaGetSymbolAddress((void**)&wkh,  g_wkh);
    cudaGetSymbolAddress((void**)&wvh,  g_wvh);
    cudaGetSymbolAddress((void**)&woh,  g_woh);
    cudaGetSymbolAddress((void**)&w1h,  g_w1h);
    cudaGetSymbolAddress((void**)&w2h,  g_w2h);

    cudaFuncSetAttribute(gemm_mma<0,3>, cudaFuncAttributeMaxDynamicSharedMemorySize, GSMEM_DYN);
    cudaFuncSetAttribute(gemm_mma<1,1>, cudaFuncAttributeMaxDynamicSharedMemorySize, GSMEM_DYN);
    cudaFuncSetAttribute(gemm_mma<2,1>, cudaFuncAttributeMaxDynamicSharedMemorySize, GSMEM_DYN);
    cudaFuncSetAttribute(attn_mma,      cudaFuncAttributeMaxDynamicSharedMemorySize, AT_SMEM);

    // 0) all weight conversions in ONE launch
    f2h_all<<<12 * WSEG / 1024, 256>>>(wq, wk, wv, wo, w1, w2,
                                       wqh, wkh, wvh, woh, w1h, w2h);

    // 1) LN1 (fp32 -> fp16)
    ln_kernel<<<NTOK, 256>>>(x, ln1g, ln1b, xln);
    // 2) fused QKV GEMM (fp16 mma, GBK=64)
    gemm_mma<0,3><<<dim3(QKV_LD / GBN, NTOK / GBM), 256, GSMEM_DYN>>>(
        xln, wqh, wkh, wvh, bq, bk, bv, nullptr, nullptr, qkv,
        NTOK, QKV_LD, EMB, EMB);
    // 3) causal attention (fp16 mma flash, register P)
    attn_mma<<<dim3(SEQ / 128, BATCH * NHEAD), 256, AT_SMEM>>>(qkv, attn);
    // 4) O proj + residual (fp32 out)
    gemm_mma<2,1><<<dim3(EMB / GBN, NTOK / GBM), 256, GSMEM_DYN>>>(
        attn, woh, nullptr, nullptr, bo, nullptr, nullptr, x, a_att, x1,
        NTOK, EMB, EMB, EMB);
    // 5) LN2
    ln_kernel<<<NTOK, 256>>>(x1, ln2g, ln2b, xln2);
    // 6) FF1 + GELU (fp16 out)
    gemm_mma<1,1><<<dim3(FFD / GBN, NTOK / GBM), 256, GSMEM_DYN>>>(
        xln2, w1h, nullptr, nullptr, b1, nullptr, nullptr, nullptr, nullptr, ff,
        NTOK, FFD, EMB, FFD);
    // 7) FF2 + residual -> out (fp32)
    gemm_mma<2,1><<<dim3(EMB / GBN, NTOK / GBM), 256, GSMEM_DYN>>>(
        ff, w2h, nullptr, nullptr, b2, nullptr, nullptr, x1, a_ff, out,
        NTOK, EMB, FFD, EMB);
}

// round 16
// speedup vs baseline: 8.8193x; 1.0324x over previous
#include <cuda_runtime.h>
#include <cuda_fp16.h>
#include <math.h>
#include <stdint.h>
#include <string.h>

#define NTOK 4096      // B*T
#define EMB  1024
#define FFD  4096
#define BATCH 2
#define SEQ  2048
#define NHEAD 16
#define HDIM 64
#define LN_EPS 1e-5f
#define QKV_LD 3072

// ---------------- scratch (device globals; no allocations allowed) ----------
__device__ __half g_xln [NTOK * EMB];
__device__ __half g_qkv [NTOK * QKV_LD];
__device__ __half g_attn[NTOK * EMB];
__device__ float  g_x1  [NTOK * EMB];
__device__ __half g_xln2[NTOK * EMB];
__device__ __half g_ff  [NTOK * FFD];
// half weights
__device__ __half g_wqh[EMB * EMB];
__device__ __half g_wkh[EMB * EMB];
__device__ __half g_wvh[EMB * EMB];
__device__ __half g_woh[EMB * EMB];
__device__ __half g_w1h[EMB * FFD];
__device__ __half g_w2h[FFD * EMB];

// ---------------- helpers ----------------------------------------------------
__device__ __forceinline__ uint32_t sm_u32(const void* p) {
    return (uint32_t)__cvta_generic_to_shared(p);
}
__device__ __forceinline__ void cp_async16(uint32_t smem, const void* gptr) {
    asm volatile("cp.async.cg.shared.global [%0], [%1], 16;"
                 :: "r"(smem), "l"(__cvta_generic_to_global(gptr)) : "memory");
}
__device__ __forceinline__ void cp_commit() {
    asm volatile("cp.async.commit_group;" ::: "memory");
}
template<int N>
__device__ __forceinline__ void cp_wait() {
    asm volatile("cp.async.wait_group %0;" :: "n"(N) : "memory");
}
// fp16 mma with fp32 accumulate: D = A(16x16) * B(16x8) + D
__device__ __forceinline__ void mma_f16(float* c, const uint32_t* a, const uint32_t* b) {
    asm volatile(
        "mma.sync.aligned.m16n8k16.row.col.f32.f16.f16.f32 "
        "{%0,%1,%2,%3}, {%4,%5,%6,%7}, {%8,%9}, {%0,%1,%2,%3};"
        : "+f"(c[0]), "+f"(c[1]), "+f"(c[2]), "+f"(c[3])
        : "r"(a[0]), "r"(a[1]), "r"(a[2]), "r"(a[3]), "r"(b[0]), "r"(b[1]));
}
__device__ __forceinline__ void ldsm_x4(uint32_t* r, uint32_t addr) {
    asm volatile("ldmatrix.sync.aligned.m8n8.x4.shared.b16 {%0,%1,%2,%3}, [%4];"
                 : "=r"(r[0]), "=r"(r[1]), "=r"(r[2]), "=r"(r[3]) : "r"(addr));
}
__device__ __forceinline__ void ldsm_x4t(uint32_t* r, uint32_t addr) {
    asm volatile("ldmatrix.sync.aligned.m8n8.x4.trans.shared.b16 {%0,%1,%2,%3}, [%4];"
                 : "=r"(r[0]), "=r"(r[1]), "=r"(r[2]), "=r"(r[3]) : "r"(addr));
}
__device__ __forceinline__ float gelu_exact(float c) {
    return 0.5f * c * (1.0f + erff(c * 0.70710678118654752f));
}
__device__ __forceinline__ uint32_t packh2(float a, float b) {
    half2 h = __floats2half2_rn(a, b);
    uint32_t u;
    memcpy(&u, &h, 4);
    return u;
}

// ---------------- fused fp32 -> fp16 weight convert (one launch) -------------
#define WSEG (EMB * EMB)                    // 1M elems
__global__ __launch_bounds__(256) void f2h_all(
    const float* __restrict__ wq, const float* __restrict__ wk,
    const float* __restrict__ wv, const float* __restrict__ wo,
    const float* __restrict__ w1, const float* __restrict__ w2,
    __half* __restrict__ dq, __half* __restrict__ dk,
    __half* __restrict__ dv, __half* __restrict__ dod,
    __half* __restrict__ d1, __half* __restrict__ d2)
{
    int i = (blockIdx.x * 256 + threadIdx.x) * 4;
    const float* s; __half* d; int off;
    if      (i < 1 * WSEG) { s = wq; d = dq;  off = 0; }
    else if (i < 2 * WSEG) { s = wk; d = dk;  off = 1 * WSEG; }
    else if (i < 3 * WSEG) { s = wv; d = dv;  off = 2 * WSEG; }
    else if (i < 4 * WSEG) { s = wo; d = dod; off = 3 * WSEG; }
    else if (i < 8 * WSEG) { s = w1; d = d1;  off = 4 * WSEG; }
    else                   { s = w2; d = d2;  off = 8 * WSEG; }
    int j = i - off;
    float4 v = *(const float4*)&s[j];
    *(half2*)&d[j]     = __floats2half2_rn(v.x, v.y);
    *(half2*)&d[j + 2] = __floats2half2_rn(v.z, v.w);
}

// ---------------- LayerNorm (fp32 in, fp16 out) ------------------------------
__global__ __launch_bounds__(256) void ln_kernel(
    const float* __restrict__ x, const float* __restrict__ g,
    const float* __restrict__ b, __half* __restrict__ y)
{
    int row = blockIdx.x;
    int tid = threadIdx.x;
    const float* xr = x + row * EMB;
    float4 v = *(const float4*)&xr[tid * 4];
    float s  = v.x + v.y + v.z + v.w;
    float ss = v.x*v.x + v.y*v.y + v.z*v.z + v.w*v.w;

    #pragma unroll
    for (int off = 16; off > 0; off >>= 1) {
        s  += __shfl_down_sync(0xffffffffu, s,  off);
        ss += __shfl_down_sync(0xffffffffu, ss, off);
    }
    __shared__ float red_s[8], red_ss[8];
    int wid = tid >> 5, lid = tid & 31;
    if (lid == 0) { red_s[wid] = s; red_ss[wid] = ss; }
    __syncthreads();
    if (wid == 0) {
        float a  = (lid < 8) ? red_s[lid]  : 0.f;
        float a2 = (lid < 8) ? red_ss[lid] : 0.f;
        #pragma unroll
        for (int off = 4; off > 0; off >>= 1) {
            a  += __shfl_down_sync(0xffffffffu, a,  off);
            a2 += __shfl_down_sync(0xffffffffu, a2, off);
        }
        if (lid == 0) { red_s[0] = a; red_ss[0] = a2; }
    }
    __syncthreads();
    float mu  = red_s[0] * (1.0f / EMB);
    float var = red_ss[0] * (1.0f / EMB) - mu * mu;
    float rs  = rsqrtf(var + LN_EPS);

    float4 gv = *(const float4*)&g[tid * 4];
    float4 bv = *(const float4*)&b[tid * 4];
    float o0 = (v.x - mu) * rs * gv.x + bv.x;
    float o1 = (v.y - mu) * rs * gv.y + bv.y;
    float o2 = (v.z - mu) * rs * gv.z + bv.z;
    float o3 = (v.w - mu) * rs * gv.w + bv.w;
    __half* yp = y + row * EMB + tid * 4;
    *(half2*)(yp)     = __floats2half2_rn(o0, o1);
    *(half2*)(yp + 2) = __floats2half2_rn(o2, o3);
}

// ---------------- fp16 mma.sync GEMM (GBK=64) --------------------------------
#define GBM 128
#define GBN 128
#define GBK 64
#define APITCH 72
#define BPITCH 136
#define ABYTES (GBM * APITCH * 2)
#define BBYTES (GBK * BPITCH * 2)
#define STAGE_BYTES (ABYTES + BBYTES)
#define GSTAGES 3
#define GSMEM_DYN (GSTAGES * STAGE_BYTES)

template<int MODE, int NSEL>
__global__ __launch_bounds__(256, 2) void gemm_mma(
    const __half* __restrict__ A,
    const __half* __restrict__ W0, const __half* __restrict__ W1,
    const __half* __restrict__ W2,
    const float* __restrict__ bias0, const float* __restrict__ bias1,
    const float* __restrict__ bias2,
    const float* __restrict__ res, const float* __restrict__ alpha_p,
    void* __restrict__ Cv, int M, int N, int K, int Nw)
{
    extern __shared__ char dynsm[];
    int tid = threadIdx.x, wid = tid >> 5, lid = tid & 31;
    int gid = lid >> 2, tg = lid & 3;
    int wm = (wid & 1) * 64, wn = (wid >> 1) * 32;
    int bm = blockIdx.y * GBM, bn = blockIdx.x * GBN;

    const __half* W = W0;
    const float* bias = bias0;
    int bnw = bn;
    if (NSEL == 3) {
        int sel = bn / Nw;
        W    = (sel == 0) ? W0 : ((sel == 1) ? W1 : W2);
        bias = (sel == 0) ? bias0 : ((sel == 1) ? bias1 : bias2);
        bnw  = bn - sel * Nw;
    }

    int l7 = lid & 7, t8 = lid >> 3;
    uint32_t a_lane_off[4];
    #pragma unroll
    for (int mf = 0; mf < 4; mf++)
        a_lane_off[mf] = (uint32_t)(((wm + mf * 16 + (t8 & 1) * 8 + l7) * APITCH
                                     + (t8 >> 1) * 8) * 2);
    uint32_t b_lane_off = (uint32_t)((((t8 & 1) * 8 + l7) * BPITCH + (t8 >> 1) * 8) * 2);

    float acc[4][4][4];
    #pragma unroll
    for (int mf = 0; mf < 4; mf++)
        #pragma unroll
        for (int nf = 0; nf < 4; nf++)
            #pragma unroll
            for (int i = 0; i < 4; i++) acc[mf][nf][i] = 0.f;

    auto load_stage = [&](int s) {
        char* base = dynsm + (s % GSTAGES) * STAGE_BYTES;
        __half* As = (__half*)base;
        __half* Bs = (__half*)(base + ABYTES);
        const __half* Ag = A + (size_t)bm * K + s * GBK;
        const __half* Wg = W + (size_t)(s * GBK) * Nw + bnw;
        #pragma unroll
        for (int i = 0; i < 4; i++) {
            int idx = tid + i * 256;
            int r = idx >> 3, c = idx & 7;
            cp_async16(sm_u32(As + r * APITCH + c * 8), Ag + (size_t)r * K + c * 8);
        }
        #pragma unroll
        for (int i = 0; i < 4; i++) {
            int idx = tid + i * 256;
            int r = idx >> 4, c = idx & 15;
            cp_async16(sm_u32(Bs + r * BPITCH + c * 8), Wg + (size_t)r * Nw + c * 8);
        }
    };

    load_stage(0); cp_commit();
    load_stage(1); cp_commit();

    int nst = K / GBK;
    for (int s = 0; s < nst; s++) {
        cp_wait<1>();
        __syncthreads();
        if (s + 2 < nst) load_stage(s + 2);
        cp_commit();

        char* base = dynsm + (s % GSTAGES) * STAGE_BYTES;
        uint32_t as_u32 = sm_u32(base);
        uint32_t bs_u32 = sm_u32(base + ABYTES);

        #pragma unroll
        for (int ks = 0; ks < 4; ks++) {
            int k0 = ks * 16;
            uint32_t af[4][4], bf[4][2];
            #pragma unroll
            for (int mf = 0; mf < 4; mf++)
                ldsm_x4(af[mf], as_u32 + a_lane_off[mf] + (uint32_t)(k0 * 2));
            #pragma unroll
            for (int nb = 0; nb < 2; nb++) {
                uint32_t r[4];
                ldsm_x4t(r, bs_u32 + b_lane_off +
                            (uint32_t)((k0 * BPITCH + wn + nb * 16) * 2));
                bf[2*nb][0]   = r[0]; bf[2*nb][1]   = r[1];
                bf[2*nb+1][0] = r[2]; bf[2*nb+1][1] = r[3];
            }
            #pragma unroll
            for (int mf = 0; mf < 4; mf++)
                #pragma unroll
                for (int nf = 0; nf < 4; nf++)
                    mma_f16(acc[mf][nf], af[mf], bf[nf]);
        }
    }

    float alpha = (MODE == 2) ? *alpha_p : 1.0f;
    #pragma unroll
    for (int mf = 0; mf < 4; mf++) {
        int r0 = bm + wm + mf * 16 + gid;
        #pragma unroll
        for (int nf = 0; nf < 4; nf++) {
            int loc = wn + nf * 8 + 2 * tg;
            int col = bn + loc;
            float2 bv = *(const float2*)&bias[bnw + loc];
            float v0 = acc[mf][nf][0] + bv.x;
            float v1 = acc[mf][nf][1] + bv.y;
            float v2 = acc[mf][nf][2] + bv.x;
            float v3 = acc[mf][nf][3] + bv.y;
            if (MODE == 1) {
                v0 = gelu_exact(v0); v1 = gelu_exact(v1);
                v2 = gelu_exact(v2); v3 = gelu_exact(v3);
            }
            if (MODE == 2) {
                float* C = (float*)Cv;
                float2 ra = *(const float2*)&res[(size_t)r0 * N + col];
                float2 rb = *(const float2*)&res[(size_t)(r0 + 8) * N + col];
                *(float2*)&C[(size_t)r0 * N + col] =
                    make_float2(ra.x + alpha * v0, ra.y + alpha * v1);
                *(float2*)&C[(size_t)(r0 + 8) * N + col] =
                    make_float2(rb.x + alpha * v2, rb.y + alpha * v3);
            } else {
                __half* C = (__half*)Cv;
                *(half2*)&C[(size_t)r0 * N + col]       = __floats2half2_rn(v0, v1);
                *(half2*)&C[(size_t)(r0 + 8) * N + col] = __floats2half2_rn(v2, v3);
            }
        }
    }
}

// ---------------- fp16 mma flash attention (3-buffer, split mask paths) ------
// 8 warps (16 q-rows each), BQ=128, BK=64 keys per tile. Register P.
#define ATP 72                               // halves per row (144B)
#define AT_TILE (64 * ATP)                   // halves per K or V tile
#define AT_NBUF 3
#define AT_SMEM (AT_NBUF * 2 * AT_TILE * 2)  // 55296 B

__global__ __launch_bounds__(256) void attn_mma(
    const __half* __restrict__ QKV, __half* __restrict__ O)
{
    extern __shared__ __half ash[];
    uint32_t ash_u32 = sm_u32(ash);

    int qt = gridDim.x - 1 - blockIdx.x;     // long blocks first
    int bh = blockIdx.y;
    int b  = bh >> 4, h = bh & 15;
    int tid = threadIdx.x, wid = tid >> 5, lid = tid & 31;
    int gid = lid >> 2, tg = lid & 3;
    int wm = wid * 16;
    int qb = qt * 128;
    const float qs = 0.125f * 1.44269504089f;   // scale * log2(e), folded into Q

    int l7 = lid & 7, t8 = lid >> 3;
    uint32_t k_lane_off = (uint32_t)((((lid >> 4) * 8 + l7) * ATP + ((t8 & 1) * 8)) * 2);
    uint32_t v_lane_off = (uint32_t)((((t8 & 1) * 8 + l7) * ATP + (lid >> 4) * 8) * 2);

    auto load_tile = [&](int kt) {
        __half* kb = ash + (kt % AT_NBUF) * 2 * AT_TILE;
        __half* vb = kb + AT_TILE;
        #pragma unroll
        for (int i = 0; i < 2; i++) {
            int idx = tid + i * 256;
            int r = idx >> 3, c = idx & 7;
            const __half* src = &QKV[(size_t)(b * SEQ + kt * 64 + r) * QKV_LD
                                     + h * HDIM + c * 8];
            cp_async16(sm_u32(kb + r * ATP + c * 8), src + EMB);
            cp_async16(sm_u32(vb + r * ATP + c * 8), src + 2 * EMB);
        }
    };

    // Q fragments, prescaled by qs in fp32 then packed to half
    uint32_t qf[4][4];
    {
        const __half* q0 = &QKV[(size_t)(b * SEQ + qb + wm + gid) * QKV_LD + h * HDIM];
        const __half* q8 = q0 + 8 * QKV_LD;
        #pragma unroll
        for (int ks = 0; ks < 4; ks++) {
            const __half* p[4] = { q0 + ks * 16 + 2 * tg, q8 + ks * 16 + 2 * tg,
                                   q0 + ks * 16 + 8 + 2 * tg, q8 + ks * 16 + 8 + 2 * tg };
            #pragma unroll
            for (int r = 0; r < 4; r++) {
                float2 f = __half22float2(*(const half2*)p[r]);
                qf[ks][r] = packh2(f.x * qs, f.y * qs);
            }
        }
    }

    float oacc[8][4];
    #pragma unroll
    for (int nf = 0; nf < 8; nf++)
        #pragma unroll
        for (int i = 0; i < 4; i++) oacc[nf][i] = 0.f;
    float om0 = -INFINITY, om1 = -INFINITY, ol0 = 0.f, ol1 = 0.f;

    int r0 = qb + wm + gid, r1 = r0 + 8;
    int nkt = 2 * qt + 2;

    load_tile(0); cp_commit();

    for (int kt = 0; kt < nkt; kt++) {
        if (kt + 1 < nkt) load_tile(kt + 1);
        cp_commit();
        cp_wait<1>();
        __syncthreads();                     // single barrier per tile (3 buffers)

        uint32_t ksh_u32 = ash_u32 + (uint32_t)((kt % AT_NBUF) * 2 * AT_TILE) * 2u;
        uint32_t vsh_u32 = ksh_u32 + (uint32_t)AT_TILE * 2u;

        // ---- S = (Q*qs) @ K^T  (log2-domain scores) ----
        float sacc[8][4];
        #pragma unroll
        for (int nf = 0; nf < 8; nf++)
            #pragma unroll
            for (int i = 0; i < 4; i++) sacc[nf][i] = 0.f;
        #pragma unroll
        for (int ks = 0; ks < 4; ks++) {
            uint32_t bf[8][2];
            #pragma unroll
            for (int np = 0; np < 4; np++) {
                uint32_t r[4];
                ldsm_x4(r, ksh_u32 + k_lane_off +
                           (uint32_t)((np * 16 * ATP + ks * 16) * 2));
                bf[2*np][0]   = r[0]; bf[2*np][1]   = r[1];
                bf[2*np+1][0] = r[2]; bf[2*np+1][1] = r[3];
            }
            #pragma unroll
            for (int nf = 0; nf < 8; nf++)
                mma_f16(sacc[nf], qf[ks], bf[nf]);
        }

        // ---- row max: predicate-free fast path off the diagonal ----
        float tmax0 = -INFINITY, tmax1 = -INFINITY;
        if (kt >= 2 * qt) {                  // diagonal region: apply causal mask
            int cb = kt * 64 + 2 * tg;
            #pragma unroll
            for (int nf = 0; nf < 8; nf++) {
                int c0 = cb + nf * 8;
                #pragma unroll
                for (int c = 0; c < 2; c++) {
                    float s0 = sacc[nf][c];
                    float s1 = sacc[nf][2 + c];
                    if (c0 + c > r0) s0 = -INFINITY;
                    if (c0 + c > r1) s1 = -INFINITY;
                    sacc[nf][c] = s0; sacc[nf][2 + c] = s1;
                    tmax0 = fmaxf(tmax0, s0);
                    tmax1 = fmaxf(tmax1, s1);
                }
            }
        } else {                             // interior: no masking needed
            #pragma unroll
            for (int nf = 0; nf < 8; nf++) {
                tmax0 = fmaxf(tmax0, fmaxf(sacc[nf][0], sacc[nf][1]));
                tmax1 = fmaxf(tmax1, fmaxf(sacc[nf][2], sacc[nf][3]));
            }
        }
        tmax0 = fmaxf(tmax0, __shfl_xor_sync(0xffffffffu, tmax0, 1));
        tmax0 = fmaxf(tmax0, __shfl_xor_sync(0xffffffffu, tmax0, 2));
        tmax1 = fmaxf(tmax1, __shfl_xor_sync(0xffffffffu, tmax1, 1));
        tmax1 = fmaxf(tmax1, __shfl_xor_sync(0xffffffffu, tmax1, 2));

        float mn0 = fmaxf(om0, tmax0), mn1 = fmaxf(om1, tmax1);
        float corr0 = exp2f(om0 - mn0), corr1 = exp2f(om1 - mn1);
        om0 = mn0; om1 = mn1;

        float ps0 = 0.f, ps1 = 0.f;
        #pragma unroll
        for (int nf = 0; nf < 8; nf++) {
            #pragma unroll
            for (int c = 0; c < 2; c++) {
                float e0 = exp2f(sacc[nf][c] - mn0);
                float e1 = exp2f(sacc[nf][2 + c] - mn1);
                sacc[nf][c] = e0; sacc[nf][2 + c] = e1;
                ps0 += e0; ps1 += e1;
            }
        }
        ps0 += __shfl_xor_sync(0xffffffffu, ps0, 1);
        ps0 += __shfl_xor_sync(0xffffffffu, ps0, 2);
        ps1 += __shfl_xor_sync(0xffffffffu, ps1, 1);
        ps1 += __shfl_xor_sync(0xffffffffu, ps1, 2);
        ol0 = ol0 * corr0 + ps0;
        ol1 = ol1 * corr1 + ps1;

        #pragma unroll
        for (int nf = 0; nf < 8; nf++) {
            oacc[nf][0] *= corr0; oacc[nf][1] *= corr0;
            oacc[nf][2] *= corr1; oacc[nf][3] *= corr1;
        }

        // ---- O += P @ V  (P straight from registers: C-frag == A-frag) ----
        #pragma unroll
        for (int ks = 0; ks < 4; ks++) {
            uint32_t af[4];
            af[0] = packh2(sacc[2*ks][0],   sacc[2*ks][1]);
            af[1] = packh2(sacc[2*ks][2],   sacc[2*ks][3]);
            af[2] = packh2(sacc[2*ks+1][0], sacc[2*ks+1][1]);
            af[3] = packh2(sacc[2*ks+1][2], sacc[2*ks+1][3]);
            uint32_t bf[8][2];
            #pragma unroll
            for (int nv = 0; nv < 4; nv++) {
                uint32_t r[4];
                ldsm_x4t(r, vsh_u32 + v_lane_off +
                            (uint32_t)((ks * 16 * ATP + nv * 16) * 2));
                bf[2*nv][0]   = r[0]; bf[2*nv][1]   = r[1];
                bf[2*nv+1][0] = r[2]; bf[2*nv+1][1] = r[3];
            }
            #pragma unroll
            for (int nf = 0; nf < 8; nf++)
                mma_f16(oacc[nf], af, bf[nf]);
        }
        // no trailing barrier: 3-buffer rotation makes next load safe
    }

    // ---- epilogue (half output) ----
    float inv0 = 1.0f / ol0, inv1 = 1.0f / ol1;
    __half* o0 = &O[(size_t)(b * SEQ + r0) * EMB + h * HDIM];
    __half* o8 = o0 + 8 * EMB;
    #pragma unroll
    for (int nf = 0; nf < 8; nf++) {
        int d = nf * 8 + 2 * tg;
        *(half2*)&o0[d] = __floats2half2_rn(oacc[nf][0] * inv0, oacc[nf][1] * inv0);
        *(half2*)&o8[d] = __floats2half2_rn(oacc[nf][2] * inv1, oacc[nf][3] * inv1);
    }
}

// ---------------- launch ----------------------------------------------------
extern "C" void kernel_launch(void* const* d_in, const int* in_sizes, int n_in,
                              void* d_out, int out_size)
{
    (void)in_sizes; (void)n_in; (void)out_size;
    const float* x     = (const float*)d_in[0];
    const float* wq    = (const float*)d_in[1];
    const float* bq    = (const float*)d_in[2];
    const float* wk    = (const float*)d_in[3];
    const float* bk    = (const float*)d_in[4];
    const float* wv    = (const float*)d_in[5];
    const float* bv    = (const float*)d_in[6];
    const float* wo    = (const float*)d_in[7];
    const float* bo    = (const float*)d_in[8];
    const float* w1    = (const float*)d_in[9];
    const float* b1    = (const float*)d_in[10];
    const float* w2    = (const float*)d_in[11];
    const float* b2    = (const float*)d_in[12];
    const float* ln1g  = (const float*)d_in[13];
    const float* ln1b  = (const float*)d_in[14];
    const float* ln2g  = (const float*)d_in[15];
    const float* ln2b  = (const float*)d_in[16];
    const float* a_att = (const float*)d_in[17];
    const float* a_ff  = (const float*)d_in[18];
    float* out = (float*)d_out;

    __half *xln, *qkv, *attn, *xln2, *ff;
    __half *wqh, *wkh, *wvh, *woh, *w1h, *w2h;
    float  *x1;
    cudaGetSymbolAddress((void**)&xln,  g_xln);
    cudaGetSymbolAddress((void**)&qkv,  g_qkv);
    cudaGetSymbolAddress((void**)&attn, g_attn);
    cudaGetSymbolAddress((void**)&x1,   g_x1);
    cudaGetSymbolAddress((void**)&xln2, g_xln2);
    cudaGetSymbolAddress((void**)&ff,   g_ff);
    cudaGetSymbolAddress((void**)&wqh,  g_wqh);
    cudaGetSymbolAddress((void**)&wkh,  g_wkh);
    cudaGetSymbolAddress((void**)&wvh,  g_wvh);
    cudaGetSymbolAddress((void**)&woh,  g_woh);
    cudaGetSymbolAddress((void**)&w1h,  g_w1h);
    cudaGetSymbolAddress((void**)&w2h,  g_w2h);

    cudaFuncSetAttribute(gemm_mma<0,3>, cudaFuncAttributeMaxDynamicSharedMemorySize, GSMEM_DYN);
    cudaFuncSetAttribute(gemm_mma<1,1>, cudaFuncAttributeMaxDynamicSharedMemorySize, GSMEM_DYN);
    cudaFuncSetAttribute(gemm_mma<2,1>, cudaFuncAttributeMaxDynamicSharedMemorySize, GSMEM_DYN);
    cudaFuncSetAttribute(attn_mma,      cudaFuncAttributeMaxDynamicSharedMemorySize, AT_SMEM);

    // 0) all weight conversions in ONE launch
    f2h_all<<<12 * WSEG / 1024, 256>>>(wq, wk, wv, wo, w1, w2,
                                       wqh, wkh, wvh, woh, w1h, w2h);

    // 1) LN1 (fp32 -> fp16)
    ln_kernel<<<NTOK, 256>>>(x, ln1g, ln1b, xln);
    // 2) fused QKV GEMM (fp16 mma, GBK=64)
    gemm_mma<0,3><<<dim3(QKV_LD / GBN, NTOK / GBM), 256, GSMEM_DYN>>>(
        xln, wqh, wkh, wvh, bq, bk, bv, nullptr, nullptr, qkv,
        NTOK, QKV_LD, EMB, EMB);
    // 3) causal attention (fp16 mma flash, register P, 3-buffer)
    attn_mma<<<dim3(SEQ / 128, BATCH * NHEAD), 256, AT_SMEM>>>(qkv, attn);
    // 4) O proj + residual (fp32 out)
    gemm_mma<2,1><<<dim3(EMB / GBN, NTOK / GBM), 256, GSMEM_DYN>>>(
        attn, woh, nullptr, nullptr, bo, nullptr, nullptr, x, a_att, x1,
        NTOK, EMB, EMB, EMB);
    // 5) LN2
    ln_kernel<<<NTOK, 256>>>(x1, ln2g, ln2b, xln2);
    // 6) FF1 + GELU (fp16 out)
    gemm_mma<1,1><<<dim3(FFD / GBN, NTOK / GBM), 256, GSMEM_DYN>>>(
        xln2, w1h, nullptr, nullptr, b1, nullptr, nullptr, nullptr, nullptr, ff,
        NTOK, FFD, EMB, FFD);
    // 7) FF2 + residual -> out (fp32)
    gemm_mma<2,1><<<dim3(EMB / GBN, NTOK / GBM), 256, GSMEM_DYN>>>(
        ff, w2h, nullptr, nullptr, b2, nullptr, nullptr, x1, a_ff, out,
        NTOK, EMB, FFD, EMB);
}